// round 1
// baseline (speedup 1.0000x reference)
#include <cuda_runtime.h>
#include <cstdint>

#define D_DIM 768
#define H_DIM 3072
#define E_NUM 8
#define MAX_T 4096
#define BM 128
#define BN 128
#define BK 8

// Per-expert routing lists + hidden scratch (slot = 2*token + k, k in {0,1})
__device__ int   g_counts[E_NUM];
__device__ int   g_tok [E_NUM * MAX_T];
__device__ int   g_slot[E_NUM * MAX_T];
__device__ float g_prob[E_NUM * MAX_T];
__device__ float g_hid[(size_t)2 * MAX_T * H_DIM];   // 8192 x 3072 fp32 = 100.7 MB

__global__ void zero_counts_kernel() {
    if (threadIdx.x < E_NUM) g_counts[threadIdx.x] = 0;
}

// One block (256 threads) per token: 16 dot products of length 768, then
// noisy-top2 gating done by thread 0.
__global__ void __launch_bounds__(256) route_kernel(
    const float* __restrict__ x, const float* __restrict__ noise,
    const float* __restrict__ Wg, const float* __restrict__ bg,
    const float* __restrict__ Wn, const float* __restrict__ bn)
{
    int t   = blockIdx.x;
    int tid = threadIdx.x;

    float pg[E_NUM], pn[E_NUM];
#pragma unroll
    for (int e = 0; e < E_NUM; e++) { pg[e] = 0.f; pn[e] = 0.f; }

    const float* xr = x + (size_t)t * D_DIM;
    for (int d = tid; d < D_DIM; d += 256) {
        float xv = xr[d];
#pragma unroll
        for (int e = 0; e < E_NUM; e++) {
            pg[e] = fmaf(xv, Wg[d * E_NUM + e], pg[e]);
            pn[e] = fmaf(xv, Wn[d * E_NUM + e], pn[e]);
        }
    }
#pragma unroll
    for (int e = 0; e < E_NUM; e++) {
#pragma unroll
        for (int o = 16; o > 0; o >>= 1) {
            pg[e] += __shfl_down_sync(0xffffffffu, pg[e], o);
            pn[e] += __shfl_down_sync(0xffffffffu, pn[e], o);
        }
    }
    __shared__ float sg[8][E_NUM], sn[8][E_NUM];
    int w = tid >> 5, l = tid & 31;
    if (l == 0) {
#pragma unroll
        for (int e = 0; e < E_NUM; e++) { sg[w][e] = pg[e]; sn[w][e] = pn[e]; }
    }
    __syncthreads();

    if (tid == 0) {
        float h[E_NUM];
#pragma unroll
        for (int e = 0; e < E_NUM; e++) {
            float a = bg[e], b = bn[e];
#pragma unroll
            for (int ww = 0; ww < 8; ww++) { a += sg[ww][e]; b += sn[ww][e]; }
            // softplus(b) = max(b,0) + log1p(exp(-|b|))
            float sp = fmaxf(b, 0.f) + log1pf(expf(-fabsf(b)));
            h[e] = a + noise[(size_t)t * E_NUM + e] * sp;
        }
        // top-2 (ties -> lowest index, matches jax.lax.top_k)
        int i0 = 0;
#pragma unroll
        for (int e = 1; e < E_NUM; e++) if (h[e] > h[i0]) i0 = e;
        int i1 = (i0 == 0) ? 1 : 0;
#pragma unroll
        for (int e = 0; e < E_NUM; e++) if (e != i0 && h[e] > h[i1]) i1 = e;

        float p0 = 1.f / (1.f + expf(h[i1] - h[i0]));
        float p1 = 1.f - p0;

        int s0 = atomicAdd(&g_counts[i0], 1);
        g_tok [i0 * MAX_T + s0] = t;
        g_slot[i0 * MAX_T + s0] = 2 * t;
        g_prob[i0 * MAX_T + s0] = p0;
        int s1 = atomicAdd(&g_counts[i1], 1);
        g_tok [i1 * MAX_T + s1] = t;
        g_slot[i1 * MAX_T + s1] = 2 * t + 1;
        g_prob[i1 * MAX_T + s1] = p1;
    }
}

// Grouped GEMM1: hid[slot] = relu(gather(x) @ W1[e] + b1[e])
__global__ void __launch_bounds__(256) gemm1_kernel(
    const float* __restrict__ x, const float* __restrict__ W1,
    const float* __restrict__ b1)
{
    int e   = blockIdx.z;
    int cnt = g_counts[e];
    int m0  = blockIdx.y * BM;
    if (m0 >= cnt) return;
    int n0  = blockIdx.x * BN;

    __shared__ float As[BK][BM];
    __shared__ float Bs[BK][BN];

    int tid = threadIdx.x;
    int ar = tid >> 1, ak = (tid & 1) * 4;     // A: 128 rows x 8 k, float4
    int br = tid >> 5, bcol = (tid & 31) * 4;  // B: 8 rows x 128 n, float4

    const float* arow_ptr = nullptr;
    {
        int arow = m0 + ar;
        if (arow < cnt)
            arow_ptr = x + (size_t)g_tok[e * MAX_T + arow] * D_DIM + ak;
    }
    const float* Wb = W1 + (size_t)e * D_DIM * H_DIM + (size_t)br * H_DIM + n0 + bcol;

    int tx = tid & 15, ty = tid >> 4;
    float acc[8][8];
#pragma unroll
    for (int i = 0; i < 8; i++)
#pragma unroll
        for (int j = 0; j < 8; j++) acc[i][j] = 0.f;

    for (int k0 = 0; k0 < D_DIM; k0 += BK) {
        float4 av = make_float4(0.f, 0.f, 0.f, 0.f);
        if (arow_ptr) av = *(const float4*)(arow_ptr + k0);
        float4 bv = *(const float4*)(Wb + (size_t)k0 * H_DIM);
        As[ak + 0][ar] = av.x; As[ak + 1][ar] = av.y;
        As[ak + 2][ar] = av.z; As[ak + 3][ar] = av.w;
        *(float4*)&Bs[br][bcol] = bv;
        __syncthreads();
#pragma unroll
        for (int k = 0; k < BK; k++) {
            float a[8], b[8];
            *(float4*)&a[0] = *(const float4*)&As[k][ty * 8];
            *(float4*)&a[4] = *(const float4*)&As[k][ty * 8 + 4];
            *(float4*)&b[0] = *(const float4*)&Bs[k][tx * 8];
            *(float4*)&b[4] = *(const float4*)&Bs[k][tx * 8 + 4];
#pragma unroll
            for (int i = 0; i < 8; i++)
#pragma unroll
                for (int j = 0; j < 8; j++)
                    acc[i][j] = fmaf(a[i], b[j], acc[i][j]);
        }
        __syncthreads();
    }

    const float* brow = b1 + (size_t)e * H_DIM + n0 + tx * 8;
#pragma unroll
    for (int i = 0; i < 8; i++) {
        int r = m0 + ty * 8 + i;
        if (r >= cnt) continue;
        int slot = g_slot[e * MAX_T + r];
        float* orow = g_hid + (size_t)slot * H_DIM + n0 + tx * 8;
        float4 c0, c1;
        c0.x = fmaxf(acc[i][0] + brow[0], 0.f);
        c0.y = fmaxf(acc[i][1] + brow[1], 0.f);
        c0.z = fmaxf(acc[i][2] + brow[2], 0.f);
        c0.w = fmaxf(acc[i][3] + brow[3], 0.f);
        c1.x = fmaxf(acc[i][4] + brow[4], 0.f);
        c1.y = fmaxf(acc[i][5] + brow[5], 0.f);
        c1.z = fmaxf(acc[i][6] + brow[6], 0.f);
        c1.w = fmaxf(acc[i][7] + brow[7], 0.f);
        *(float4*)orow = c0;
        *(float4*)(orow + 4) = c1;
    }
}

// Grouped GEMM2: out[tok] += p * (hid[slot] @ W2[e] + b2[e])
__global__ void __launch_bounds__(256) gemm2_kernel(
    const float* __restrict__ W2, const float* __restrict__ b2,
    float* __restrict__ out)
{
    int e   = blockIdx.z;
    int cnt = g_counts[e];
    int m0  = blockIdx.y * BM;
    if (m0 >= cnt) return;
    int n0  = blockIdx.x * BN;

    __shared__ float As[BK][BM];
    __shared__ float Bs[BK][BN];

    int tid = threadIdx.x;
    int ar = tid >> 1, ak = (tid & 1) * 4;
    int br = tid >> 5, bcol = (tid & 31) * 4;

    const float* arow_ptr = nullptr;
    {
        int arow = m0 + ar;
        if (arow < cnt)
            arow_ptr = g_hid + (size_t)g_slot[e * MAX_T + arow] * H_DIM + ak;
    }
    const float* Wb = W2 + (size_t)e * H_DIM * D_DIM + (size_t)br * D_DIM + n0 + bcol;

    int tx = tid & 15, ty = tid >> 4;
    float acc[8][8];
#pragma unroll
    for (int i = 0; i < 8; i++)
#pragma unroll
        for (int j = 0; j < 8; j++) acc[i][j] = 0.f;

    for (int k0 = 0; k0 < H_DIM; k0 += BK) {
        float4 av = make_float4(0.f, 0.f, 0.f, 0.f);
        if (arow_ptr) av = *(const float4*)(arow_ptr + k0);
        float4 bv = *(const float4*)(Wb + (size_t)k0 * D_DIM);
        As[ak + 0][ar] = av.x; As[ak + 1][ar] = av.y;
        As[ak + 2][ar] = av.z; As[ak + 3][ar] = av.w;
        *(float4*)&Bs[br][bcol] = bv;
        __syncthreads();
#pragma unroll
        for (int k = 0; k < BK; k++) {
            float a[8], b[8];
            *(float4*)&a[0] = *(const float4*)&As[k][ty * 8];
            *(float4*)&a[4] = *(const float4*)&As[k][ty * 8 + 4];
            *(float4*)&b[0] = *(const float4*)&Bs[k][tx * 8];
            *(float4*)&b[4] = *(const float4*)&Bs[k][tx * 8 + 4];
#pragma unroll
            for (int i = 0; i < 8; i++)
#pragma unroll
                for (int j = 0; j < 8; j++)
                    acc[i][j] = fmaf(a[i], b[j], acc[i][j]);
        }
        __syncthreads();
    }

    const float* brow = b2 + (size_t)e * D_DIM + n0 + tx * 8;
#pragma unroll
    for (int i = 0; i < 8; i++) {
        int r = m0 + ty * 8 + i;
        if (r >= cnt) continue;
        int tok = g_tok[e * MAX_T + r];
        float p = g_prob[e * MAX_T + r];
        float* orow = out + (size_t)tok * D_DIM + n0 + tx * 8;
#pragma unroll
        for (int j = 0; j < 8; j++)
            atomicAdd(&orow[j], p * (acc[i][j] + brow[j]));
    }
}

extern "C" void kernel_launch(void* const* d_in, const int* in_sizes, int n_in,
                              void* d_out, int out_size)
{
    const float* x     = (const float*)d_in[0];
    const float* noise = (const float*)d_in[1];
    const float* Wg    = (const float*)d_in[2];
    const float* bg    = (const float*)d_in[3];
    const float* Wn    = (const float*)d_in[4];
    const float* bn    = (const float*)d_in[5];
    const float* W1    = (const float*)d_in[6];
    const float* b1    = (const float*)d_in[7];
    const float* W2    = (const float*)d_in[8];
    const float* b2    = (const float*)d_in[9];
    float* out = (float*)d_out;

    int T = in_sizes[0] / D_DIM;   // 4096 for the bench shapes
    if (T > MAX_T) T = MAX_T;

    cudaMemsetAsync(d_out, 0, (size_t)out_size * sizeof(float));
    zero_counts_kernel<<<1, 32>>>();
    route_kernel<<<T, 256>>>(x, noise, Wg, bg, Wn, bn);

    int mt = (T + BM - 1) / BM;
    gemm1_kernel<<<dim3(H_DIM / BN, mt, E_NUM), 256>>>(x, W1, b1);
    gemm2_kernel<<<dim3(D_DIM / BN, mt, E_NUM), 256>>>(W2, b2, out);
}

// round 3
// speedup vs baseline: 3.5767x; 3.5767x over previous
#include <cuda_runtime.h>
#include <cstdint>

#define D_DIM 768
#define H_DIM 3072
#define E_NUM 8
#define MAX_T 4096

// ---------------- device scratch ----------------
__device__ int   g_counts[E_NUM];
__device__ int   g_tok [E_NUM * MAX_T];
__device__ int   g_slot[E_NUM * MAX_T];
__device__ float g_pslot[2 * MAX_T];
__device__ float g_hid[(size_t)2 * MAX_T * H_DIM];   // 100.7 MB
__device__ float g_y  [(size_t)2 * MAX_T * D_DIM];   // 25.2 MB

__device__ __forceinline__ float to_tf32(float x) {
    float r;
    asm("cvt.rna.tf32.f32 %0, %1;" : "=f"(r) : "f"(x));
    return r;
}
__device__ __forceinline__ void mma_tf32(float* d, const uint4& a, const uint2& b) {
    asm volatile(
        "mma.sync.aligned.m16n8k8.row.col.f32.tf32.tf32.f32 "
        "{%0,%1,%2,%3}, {%4,%5,%6,%7}, {%8,%9}, {%0,%1,%2,%3};"
        : "+f"(d[0]), "+f"(d[1]), "+f"(d[2]), "+f"(d[3])
        : "r"(a.x), "r"(a.y), "r"(a.z), "r"(a.w), "r"(b.x), "r"(b.y));
}

// ---------------- routing ----------------
__global__ void zero_counts_kernel() {
    if (threadIdx.x < E_NUM) g_counts[threadIdx.x] = 0;
}

__global__ void __launch_bounds__(256) route_kernel(
    const float* __restrict__ x, const float* __restrict__ noise,
    const float* __restrict__ Wg, const float* __restrict__ bg,
    const float* __restrict__ Wn, const float* __restrict__ bn)
{
    int t = blockIdx.x, tid = threadIdx.x;
    float pg[E_NUM], pn[E_NUM];
#pragma unroll
    for (int e = 0; e < E_NUM; e++) { pg[e] = 0.f; pn[e] = 0.f; }
    const float* xr = x + (size_t)t * D_DIM;
    for (int d = tid; d < D_DIM; d += 256) {
        float xv = xr[d];
#pragma unroll
        for (int e = 0; e < E_NUM; e++) {
            pg[e] = fmaf(xv, Wg[d * E_NUM + e], pg[e]);
            pn[e] = fmaf(xv, Wn[d * E_NUM + e], pn[e]);
        }
    }
#pragma unroll
    for (int e = 0; e < E_NUM; e++)
#pragma unroll
        for (int o = 16; o > 0; o >>= 1) {
            pg[e] += __shfl_down_sync(0xffffffffu, pg[e], o);
            pn[e] += __shfl_down_sync(0xffffffffu, pn[e], o);
        }
    __shared__ float sg[8][E_NUM], sn[8][E_NUM];
    int w = tid >> 5, l = tid & 31;
    if (l == 0)
#pragma unroll
        for (int e = 0; e < E_NUM; e++) { sg[w][e] = pg[e]; sn[w][e] = pn[e]; }
    __syncthreads();

    if (tid == 0) {
        float h[E_NUM];
#pragma unroll
        for (int e = 0; e < E_NUM; e++) {
            float a = bg[e], b = bn[e];
#pragma unroll
            for (int ww = 0; ww < 8; ww++) { a += sg[ww][e]; b += sn[ww][e]; }
            float sp = fmaxf(b, 0.f) + log1pf(expf(-fabsf(b)));
            h[e] = a + noise[(size_t)t * E_NUM + e] * sp;
        }
        int i0 = 0;
#pragma unroll
        for (int e = 1; e < E_NUM; e++) if (h[e] > h[i0]) i0 = e;
        int i1 = (i0 == 0) ? 1 : 0;
#pragma unroll
        for (int e = 0; e < E_NUM; e++) if (e != i0 && h[e] > h[i1]) i1 = e;

        float p0 = 1.f / (1.f + expf(h[i1] - h[i0]));
        float p1 = 1.f - p0;
        g_pslot[2 * t]     = p0;
        g_pslot[2 * t + 1] = p1;

        int s0 = atomicAdd(&g_counts[i0], 1);
        g_tok [i0 * MAX_T + s0] = t;
        g_slot[i0 * MAX_T + s0] = 2 * t;
        int s1 = atomicAdd(&g_counts[i1], 1);
        g_tok [i1 * MAX_T + s1] = t;
        g_slot[i1 * MAX_T + s1] = 2 * t + 1;
    }
}

// ---------------- grouped tf32 mma.sync GEMM ----------------
// BM=128, BN=256, BK=32. 8 warps (2x4), warp tile 64x64 = 4 mfrag x 8 nfrag
// of m16n8k8. SMEM holds fragment-major tiles:
//   A: offset = ((mf*4+ks)*32 + (lane^ks))*4 + ireg            (4096 floats)
//   B: offset = ((nf*4+ks)*32 + (lane^(nf&7)))*2 + ireg        (8192 floats)
#define SM_FLOATS 12288

template <bool G1>
__global__ void __launch_bounds__(256) moe_gemm(
    const float* __restrict__ Abase, const float* __restrict__ W,
    const float* __restrict__ bias, float* __restrict__ Out)
{
    constexpr int KTOT = G1 ? D_DIM : H_DIM;
    constexpr int NG   = G1 ? H_DIM : D_DIM;
    constexpr int NC   = KTOT / 32;

    int e   = blockIdx.z;
    int cnt = g_counts[e];
    int m0  = blockIdx.y * 128;
    if (m0 >= cnt) return;
    int n0  = blockIdx.x * 256;

    extern __shared__ float sm[];
    float* smA = sm;           // 4096 floats
    float* smB = sm + 4096;    // 8192 floats

    int tid = threadIdx.x, wid = tid >> 5, lane = tid & 31;
    int wm = wid >> 2, wn = wid & 3;
    const int* idxarr = G1 ? g_tok : g_slot;

    // A gather pointers: unit u = tid+256*i -> row=u>>3, c4=u&7 (float4 along K)
    const float* ap[4];
#pragma unroll
    for (int i = 0; i < 4; i++) {
        int u = tid + 256 * i, row = u >> 3, c4 = u & 7;
        int grow = m0 + row;
        ap[i] = (grow < cnt)
              ? Abase + (size_t)idxarr[e * MAX_T + grow] * KTOT + c4 * 4
              : nullptr;
    }
    // B pointers: u = tid+256*i -> krow=u>>6, c4=u&63 (float4 along N)
    const float* bp[8];
#pragma unroll
    for (int i = 0; i < 8; i++) {
        int u = tid + 256 * i, krow = u >> 6, c4 = u & 63;
        bp[i] = W + (size_t)e * KTOT * NG + (size_t)krow * NG + n0 + c4 * 4;
    }

    float4 av[4], bv[8];
#pragma unroll
    for (int i = 0; i < 4; i++)
        av[i] = ap[i] ? *(const float4*)ap[i] : make_float4(0.f, 0.f, 0.f, 0.f);
#pragma unroll
    for (int i = 0; i < 8; i++) bv[i] = *(const float4*)bp[i];

    float acc[4][8][4];
#pragma unroll
    for (int a = 0; a < 4; a++)
#pragma unroll
        for (int b = 0; b < 8; b++)
#pragma unroll
            for (int k = 0; k < 4; k++) acc[a][b][k] = 0.f;

#pragma unroll 1
    for (int c = 0; c < NC; c++) {
        // scatter A into fragment-major smem
#pragma unroll
        for (int i = 0; i < 4; i++) {
            int u = tid + 256 * i, row = u >> 3, c4 = u & 7;
            int mf = row >> 4, r = row & 15, g = r & 7, hi = r >> 3;
            int ks = c4 >> 1, chalf = c4 & 1, ireg = hi + 2 * chalf;
            int base = (mf * 4 + ks) * 32;
            float4 v = av[i];
            smA[(base + ((g * 4 + 0) ^ ks)) * 4 + ireg] = to_tf32(v.x);
            smA[(base + ((g * 4 + 1) ^ ks)) * 4 + ireg] = to_tf32(v.y);
            smA[(base + ((g * 4 + 2) ^ ks)) * 4 + ireg] = to_tf32(v.z);
            smA[(base + ((g * 4 + 3) ^ ks)) * 4 + ireg] = to_tf32(v.w);
        }
        // scatter B
#pragma unroll
        for (int i = 0; i < 8; i++) {
            int u = tid + 256 * i, krow = u >> 6, c4 = u & 63;
            int ks = krow >> 3, kk = krow & 7, ireg = kk >> 2, t = kk & 3;
            int nf = c4 >> 1, g0 = (c4 & 1) * 4;
            int base = (nf * 4 + ks) * 32, sw = nf & 7;
            float4 v = bv[i];
            smB[(base + (((g0 + 0) * 4 + t) ^ sw)) * 2 + ireg] = to_tf32(v.x);
            smB[(base + (((g0 + 1) * 4 + t) ^ sw)) * 2 + ireg] = to_tf32(v.y);
            smB[(base + (((g0 + 2) * 4 + t) ^ sw)) * 2 + ireg] = to_tf32(v.z);
            smB[(base + (((g0 + 3) * 4 + t) ^ sw)) * 2 + ireg] = to_tf32(v.w);
        }
        __syncthreads();

        if (c + 1 < NC) {   // prefetch next chunk while computing this one
#pragma unroll
            for (int i = 0; i < 4; i++)
                av[i] = ap[i] ? *(const float4*)(ap[i] + (size_t)(c + 1) * 32)
                              : make_float4(0.f, 0.f, 0.f, 0.f);
#pragma unroll
            for (int i = 0; i < 8; i++)
                bv[i] = *(const float4*)(bp[i] + (size_t)(c + 1) * 32 * NG);
        }

#pragma unroll
        for (int ks = 0; ks < 4; ks++) {
            uint4 af[4]; uint2 bf[8];
#pragma unroll
            for (int mf = 0; mf < 4; mf++)
                af[mf] = *(const uint4*)&smA[(((wm * 4 + mf) * 4 + ks) * 32 +
                                              (lane ^ ks)) * 4];
#pragma unroll
            for (int nf = 0; nf < 8; nf++) {
                int nfg = wn * 8 + nf;
                bf[nf] = *(const uint2*)&smB[(((nfg * 4 + ks) * 32 +
                                               (lane ^ (nfg & 7))) * 2)];
            }
#pragma unroll
            for (int mf = 0; mf < 4; mf++)
#pragma unroll
                for (int nf = 0; nf < 8; nf++)
                    mma_tf32(acc[mf][nf], af[mf], bf[nf]);
        }
        __syncthreads();
    }

    // epilogue: acc[mf][nf] -> rows r0=g, r1=g+8 ; cols 2t, 2t+1
#pragma unroll
    for (int mf = 0; mf < 4; mf++) {
        int r0 = m0 + wm * 64 + mf * 16 + (lane >> 2);
        int r1 = r0 + 8;
        bool v0 = r0 < cnt, v1 = r1 < cnt;
        int s0 = v0 ? g_slot[e * MAX_T + r0] : 0;
        int s1 = v1 ? g_slot[e * MAX_T + r1] : 0;
        float* o0 = Out + (size_t)s0 * NG;
        float* o1 = Out + (size_t)s1 * NG;
#pragma unroll
        for (int nf = 0; nf < 8; nf++) {
            int col = n0 + wn * 64 + nf * 8 + (lane & 3) * 2;
            float2 bb = *(const float2*)&bias[(size_t)e * NG + col];
            float x0 = acc[mf][nf][0] + bb.x, x1 = acc[mf][nf][1] + bb.y;
            float x2 = acc[mf][nf][2] + bb.x, x3 = acc[mf][nf][3] + bb.y;
            if (G1) {
                x0 = fmaxf(x0, 0.f); x1 = fmaxf(x1, 0.f);
                x2 = fmaxf(x2, 0.f); x3 = fmaxf(x3, 0.f);
            }
            if (v0) { float2 tmp; tmp.x = x0; tmp.y = x1; *(float2*)&o0[col] = tmp; }
            if (v1) { float2 tmp; tmp.x = x2; tmp.y = x3; *(float2*)&o1[col] = tmp; }
        }
    }
}

// out[t] = p0*y[2t] + p1*y[2t+1]
__global__ void __launch_bounds__(256) combine_kernel(float* __restrict__ out, int T)
{
    int idx = blockIdx.x * 256 + threadIdx.x;
    int total = T * (D_DIM / 4);
    if (idx >= total) return;
    int t  = idx / (D_DIM / 4);
    int c4 = idx % (D_DIM / 4);
    float4 a = ((const float4*)(g_y + (size_t)(2 * t) * D_DIM))[c4];
    float4 b = ((const float4*)(g_y + (size_t)(2 * t + 1) * D_DIM))[c4];
    float p0 = g_pslot[2 * t], p1 = g_pslot[2 * t + 1];
    float4 o;
    o.x = p0 * a.x + p1 * b.x;
    o.y = p0 * a.y + p1 * b.y;
    o.z = p0 * a.z + p1 * b.z;
    o.w = p0 * a.w + p1 * b.w;
    ((float4*)out)[idx] = o;
}

extern "C" void kernel_launch(void* const* d_in, const int* in_sizes, int n_in,
                              void* d_out, int out_size)
{
    const float* x     = (const float*)d_in[0];
    const float* noise = (const float*)d_in[1];
    const float* Wg    = (const float*)d_in[2];
    const float* bg    = (const float*)d_in[3];
    const float* Wn    = (const float*)d_in[4];
    const float* bn    = (const float*)d_in[5];
    const float* W1    = (const float*)d_in[6];
    const float* b1    = (const float*)d_in[7];
    const float* W2    = (const float*)d_in[8];
    const float* b2    = (const float*)d_in[9];
    float* out = (float*)d_out;

    int T = in_sizes[0] / D_DIM;
    if (T > MAX_T) T = MAX_T;

    size_t smb = SM_FLOATS * sizeof(float);   // 48 KB
    cudaFuncSetAttribute(moe_gemm<true>,
                         cudaFuncAttributeMaxDynamicSharedMemorySize, (int)smb);
    cudaFuncSetAttribute(moe_gemm<false>,
                         cudaFuncAttributeMaxDynamicSharedMemorySize, (int)smb);

    float* hid = nullptr; float* yv = nullptr;
    cudaGetSymbolAddress((void**)&hid, g_hid);
    cudaGetSymbolAddress((void**)&yv,  g_y);

    zero_counts_kernel<<<1, 32>>>();
    route_kernel<<<T, 256>>>(x, noise, Wg, bg, Wn, bn);

    int mt = (T + 127) / 128;   // per-expert cnt <= T
    moe_gemm<true ><<<dim3(H_DIM / 256, mt, E_NUM), 256, smb>>>(x,   W1, b1, hid);
    moe_gemm<false><<<dim3(D_DIM / 256, mt, E_NUM), 256, smb>>>(hid, W2, b2, yv);

    combine_kernel<<<(T * (D_DIM / 4) + 255) / 256, 256>>>(out, T);
}

// round 4
// speedup vs baseline: 3.6629x; 1.0241x over previous
#include <cuda_runtime.h>
#include <cstdint>

#define D_DIM 768
#define H_DIM 3072
#define E_NUM 8
#define MAX_T 4096

// ---------------- device scratch ----------------
__device__ int   g_counts[E_NUM];
__device__ int   g_tok [E_NUM * MAX_T];
__device__ int   g_slot[E_NUM * MAX_T];
__device__ float g_pslot[2 * MAX_T];
__device__ float g_hid[(size_t)2 * MAX_T * H_DIM];   // 100.7 MB
__device__ float g_y  [(size_t)2 * MAX_T * D_DIM];   // 25.2 MB

__device__ __forceinline__ float to_tf32(float x) {
    float r;
    asm("cvt.rna.tf32.f32 %0, %1;" : "=f"(r) : "f"(x));
    return r;
}
__device__ __forceinline__ void mma_tf32(float* d, const uint4& a, const uint2& b) {
    asm volatile(
        "mma.sync.aligned.m16n8k8.row.col.f32.tf32.tf32.f32 "
        "{%0,%1,%2,%3}, {%4,%5,%6,%7}, {%8,%9}, {%0,%1,%2,%3};"
        : "+f"(d[0]), "+f"(d[1]), "+f"(d[2]), "+f"(d[3])
        : "r"(a.x), "r"(a.y), "r"(a.z), "r"(a.w), "r"(b.x), "r"(b.y));
}

// ---------------- routing ----------------
__global__ void zero_counts_kernel() {
    if (threadIdx.x < E_NUM) g_counts[threadIdx.x] = 0;
}

__global__ void __launch_bounds__(256) route_kernel(
    const float* __restrict__ x, const float* __restrict__ noise,
    const float* __restrict__ Wg, const float* __restrict__ bg,
    const float* __restrict__ Wn, const float* __restrict__ bn)
{
    int t = blockIdx.x, tid = threadIdx.x;
    float pg[E_NUM], pn[E_NUM];
#pragma unroll
    for (int e = 0; e < E_NUM; e++) { pg[e] = 0.f; pn[e] = 0.f; }
    const float* xr = x + (size_t)t * D_DIM;
    for (int d = tid; d < D_DIM; d += 256) {
        float xv = xr[d];
#pragma unroll
        for (int e = 0; e < E_NUM; e++) {
            pg[e] = fmaf(xv, Wg[d * E_NUM + e], pg[e]);
            pn[e] = fmaf(xv, Wn[d * E_NUM + e], pn[e]);
        }
    }
#pragma unroll
    for (int e = 0; e < E_NUM; e++)
#pragma unroll
        for (int o = 16; o > 0; o >>= 1) {
            pg[e] += __shfl_down_sync(0xffffffffu, pg[e], o);
            pn[e] += __shfl_down_sync(0xffffffffu, pn[e], o);
        }
    __shared__ float sg[8][E_NUM], sn[8][E_NUM];
    int w = tid >> 5, l = tid & 31;
    if (l == 0)
#pragma unroll
        for (int e = 0; e < E_NUM; e++) { sg[w][e] = pg[e]; sn[w][e] = pn[e]; }
    __syncthreads();

    if (tid == 0) {
        float h[E_NUM];
#pragma unroll
        for (int e = 0; e < E_NUM; e++) {
            float a = bg[e], b = bn[e];
#pragma unroll
            for (int ww = 0; ww < 8; ww++) { a += sg[ww][e]; b += sn[ww][e]; }
            float sp = fmaxf(b, 0.f) + log1pf(expf(-fabsf(b)));
            h[e] = a + noise[(size_t)t * E_NUM + e] * sp;
        }
        int i0 = 0;
#pragma unroll
        for (int e = 1; e < E_NUM; e++) if (h[e] > h[i0]) i0 = e;
        int i1 = (i0 == 0) ? 1 : 0;
#pragma unroll
        for (int e = 0; e < E_NUM; e++) if (e != i0 && h[e] > h[i1]) i1 = e;

        float p0 = 1.f / (1.f + expf(h[i1] - h[i0]));
        float p1 = 1.f - p0;
        g_pslot[2 * t]     = p0;
        g_pslot[2 * t + 1] = p1;

        int s0 = atomicAdd(&g_counts[i0], 1);
        g_tok [i0 * MAX_T + s0] = t;
        g_slot[i0 * MAX_T + s0] = 2 * t;
        int s1 = atomicAdd(&g_counts[i1], 1);
        g_tok [i1 * MAX_T + s1] = t;
        g_slot[i1 * MAX_T + s1] = 2 * t + 1;
    }
}

// ---------------- grouped tf32 mma.sync GEMM ----------------
// BM=128, BN=256, BK=32, double-buffered SMEM (one __syncthreads per chunk).
// 8 warps (2x4), warp tile 64x64 = 4 mfrag x 8 nfrag of m16n8k8.
// Fragment-major SMEM:
//   A: [(mf*4+ks)*32 + (lane^ks)]*4 + ireg                      (4096 floats)
//   B: paired nf: [(nfp*4+ks)*32 + (lane^(nfp&7))]*4 + h*2+ireg (8192 floats)
#define BUF_FLOATS 12288
#define SM_BYTES (2 * BUF_FLOATS * 4)

template <bool G1>
__global__ void __launch_bounds__(256) moe_gemm(
    const float* __restrict__ Abase, const float* __restrict__ W,
    const float* __restrict__ bias, float* __restrict__ Out)
{
    constexpr int KTOT = G1 ? D_DIM : H_DIM;
    constexpr int NG   = G1 ? H_DIM : D_DIM;
    constexpr int NC   = KTOT / 32;

    int e   = blockIdx.z;
    int cnt = g_counts[e];
    int m0  = blockIdx.y * 128;
    if (m0 >= cnt) return;
    int n0  = blockIdx.x * 256;

    extern __shared__ float sm[];

    int tid = threadIdx.x, wid = tid >> 5, lane = tid & 31;
    int wm = wid >> 2, wn = wid & 3;
    const int* idxarr = G1 ? g_tok : g_slot;

    // A gather pointers: unit u = tid+256*i -> row=u>>3, c4=u&7 (float4 along K)
    const float* ap[4];
#pragma unroll
    for (int i = 0; i < 4; i++) {
        int u = tid + 256 * i, row = u >> 3, c4 = u & 7;
        int grow = m0 + row;
        ap[i] = (grow < cnt)
              ? Abase + (size_t)idxarr[e * MAX_T + grow] * KTOT + c4 * 4
              : nullptr;
    }
    // B pointers: u = tid+256*i -> krow=u>>6, c4=u&63 (float4 along N)
    const float* bp[8];
#pragma unroll
    for (int i = 0; i < 8; i++) {
        int u = tid + 256 * i, krow = u >> 6, c4 = u & 63;
        bp[i] = W + (size_t)e * KTOT * NG + (size_t)krow * NG + n0 + c4 * 4;
    }

    float4 av[4], bv[8];
    auto ldg_chunk = [&](int c) {
#pragma unroll
        for (int i = 0; i < 4; i++)
            av[i] = ap[i] ? *(const float4*)(ap[i] + (size_t)c * 32)
                          : make_float4(0.f, 0.f, 0.f, 0.f);
#pragma unroll
        for (int i = 0; i < 8; i++)
            bv[i] = *(const float4*)(bp[i] + (size_t)c * 32 * NG);
    };
    auto store_chunk = [&](int buf) {
        float* smA = sm + buf * BUF_FLOATS;
        float* smB = smA + 4096;
#pragma unroll
        for (int i = 0; i < 4; i++) {
            int u = tid + 256 * i, row = u >> 3, c4 = u & 7;
            int mf = row >> 4, r = row & 15, g = r & 7, hi = r >> 3;
            int ks = c4 >> 1, chalf = c4 & 1, ireg = hi + 2 * chalf;
            int base = (mf * 4 + ks) * 32;
            float4 v = av[i];
            smA[(base + ((g * 4 + 0) ^ ks)) * 4 + ireg] = to_tf32(v.x);
            smA[(base + ((g * 4 + 1) ^ ks)) * 4 + ireg] = to_tf32(v.y);
            smA[(base + ((g * 4 + 2) ^ ks)) * 4 + ireg] = to_tf32(v.z);
            smA[(base + ((g * 4 + 3) ^ ks)) * 4 + ireg] = to_tf32(v.w);
        }
#pragma unroll
        for (int i = 0; i < 8; i++) {
            int u = tid + 256 * i, krow = u >> 6, c4 = u & 63;
            int ks = krow >> 3, kk = krow & 7, ireg = kk >> 2, t = kk & 3;
            int nfp = c4 >> 2, h = (c4 >> 1) & 1, sw = nfp & 7;
            int q = h * 2 + ireg;
            int base = (nfp * 4 + ks) * 32;
            int nl0 = (c4 & 1) * 4;
            float4 v = bv[i];
            smB[(base + (((nl0 + 0) * 4 + t) ^ sw)) * 4 + q] = to_tf32(v.x);
            smB[(base + (((nl0 + 1) * 4 + t) ^ sw)) * 4 + q] = to_tf32(v.y);
            smB[(base + (((nl0 + 2) * 4 + t) ^ sw)) * 4 + q] = to_tf32(v.z);
            smB[(base + (((nl0 + 3) * 4 + t) ^ sw)) * 4 + q] = to_tf32(v.w);
        }
    };

    float acc[4][8][4];
#pragma unroll
    for (int a = 0; a < 4; a++)
#pragma unroll
        for (int b = 0; b < 8; b++)
#pragma unroll
            for (int k = 0; k < 4; k++) acc[a][b][k] = 0.f;

    // prologue: chunk 0 into buf 0
    ldg_chunk(0);
    store_chunk(0);
    __syncthreads();

#pragma unroll 1
    for (int c = 0; c < NC; c++) {
        int buf = c & 1;
        if (c + 1 < NC) ldg_chunk(c + 1);

        const float* smA = sm + buf * BUF_FLOATS;
        const float* smB = smA + 4096;
#pragma unroll
        for (int ks = 0; ks < 4; ks++) {
            uint4 af[4]; uint2 bf[8];
#pragma unroll
            for (int mf = 0; mf < 4; mf++)
                af[mf] = *(const uint4*)&smA[(((wm * 4 + mf) * 4 + ks) * 32 +
                                              (lane ^ ks)) * 4];
#pragma unroll
            for (int nfp = 0; nfp < 4; nfp++) {
                int nfg = wn * 4 + nfp;
                uint4 bb = *(const uint4*)&smB[((nfg * 4 + ks) * 32 +
                                                (lane ^ (nfg & 7))) * 4];
                bf[2 * nfp].x     = bb.x; bf[2 * nfp].y     = bb.y;
                bf[2 * nfp + 1].x = bb.z; bf[2 * nfp + 1].y = bb.w;
            }
#pragma unroll
            for (int mf = 0; mf < 4; mf++)
#pragma unroll
                for (int nf = 0; nf < 8; nf++)
                    mma_tf32(acc[mf][nf], af[mf], bf[nf]);
        }

        if (c + 1 < NC) store_chunk(buf ^ 1);
        __syncthreads();
    }

    // epilogue: acc[mf][nf] -> rows r0=g, r1=g+8 ; cols 2t, 2t+1
#pragma unroll
    for (int mf = 0; mf < 4; mf++) {
        int r0 = m0 + wm * 64 + mf * 16 + (lane >> 2);
        int r1 = r0 + 8;
        bool v0 = r0 < cnt, v1 = r1 < cnt;
        int s0 = v0 ? g_slot[e * MAX_T + r0] : 0;
        int s1 = v1 ? g_slot[e * MAX_T + r1] : 0;
        float* o0 = Out + (size_t)s0 * NG;
        float* o1 = Out + (size_t)s1 * NG;
#pragma unroll
        for (int nf = 0; nf < 8; nf++) {
            int col = n0 + wn * 64 + nf * 8 + (lane & 3) * 2;
            float2 bb = *(const float2*)&bias[(size_t)e * NG + col];
            float x0 = acc[mf][nf][0] + bb.x, x1 = acc[mf][nf][1] + bb.y;
            float x2 = acc[mf][nf][2] + bb.x, x3 = acc[mf][nf][3] + bb.y;
            if (G1) {
                x0 = fmaxf(x0, 0.f); x1 = fmaxf(x1, 0.f);
                x2 = fmaxf(x2, 0.f); x3 = fmaxf(x3, 0.f);
            }
            if (v0) { float2 tmp; tmp.x = x0; tmp.y = x1; *(float2*)&o0[col] = tmp; }
            if (v1) { float2 tmp; tmp.x = x2; tmp.y = x3; *(float2*)&o1[col] = tmp; }
        }
    }
}

// out[t] = p0*y[2t] + p1*y[2t+1]
__global__ void __launch_bounds__(256) combine_kernel(float* __restrict__ out, int T)
{
    int idx = blockIdx.x * 256 + threadIdx.x;
    int total = T * (D_DIM / 4);
    if (idx >= total) return;
    int t  = idx / (D_DIM / 4);
    int c4 = idx % (D_DIM / 4);
    float4 a = ((const float4*)(g_y + (size_t)(2 * t) * D_DIM))[c4];
    float4 b = ((const float4*)(g_y + (size_t)(2 * t + 1) * D_DIM))[c4];
    float p0 = g_pslot[2 * t], p1 = g_pslot[2 * t + 1];
    float4 o;
    o.x = p0 * a.x + p1 * b.x;
    o.y = p0 * a.y + p1 * b.y;
    o.z = p0 * a.z + p1 * b.z;
    o.w = p0 * a.w + p1 * b.w;
    ((float4*)out)[idx] = o;
}

extern "C" void kernel_launch(void* const* d_in, const int* in_sizes, int n_in,
                              void* d_out, int out_size)
{
    const float* x     = (const float*)d_in[0];
    const float* noise = (const float*)d_in[1];
    const float* Wg    = (const float*)d_in[2];
    const float* bg    = (const float*)d_in[3];
    const float* Wn    = (const float*)d_in[4];
    const float* bn    = (const float*)d_in[5];
    const float* W1    = (const float*)d_in[6];
    const float* b1    = (const float*)d_in[7];
    const float* W2    = (const float*)d_in[8];
    const float* b2    = (const float*)d_in[9];
    float* out = (float*)d_out;

    int T = in_sizes[0] / D_DIM;
    if (T > MAX_T) T = MAX_T;

    cudaFuncSetAttribute(moe_gemm<true>,
                         cudaFuncAttributeMaxDynamicSharedMemorySize, SM_BYTES);
    cudaFuncSetAttribute(moe_gemm<false>,
                         cudaFuncAttributeMaxDynamicSharedMemorySize, SM_BYTES);

    float* hid = nullptr; float* yv = nullptr;
    cudaGetSymbolAddress((void**)&hid, g_hid);
    cudaGetSymbolAddress((void**)&yv,  g_y);

    zero_counts_kernel<<<1, 32>>>();
    route_kernel<<<T, 256>>>(x, noise, Wg, bg, Wn, bn);

    int mt = (T + 127) / 128;   // per-expert cnt <= T
    moe_gemm<true ><<<dim3(H_DIM / 256, mt, E_NUM), 256, SM_BYTES>>>(x,   W1, b1, hid);
    moe_gemm<false><<<dim3(D_DIM / 256, mt, E_NUM), 256, SM_BYTES>>>(hid, W2, b2, yv);

    combine_kernel<<<(T * (D_DIM / 4) + 255) / 256, 256>>>(out, T);
}

// round 6
// speedup vs baseline: 4.9614x; 1.3545x over previous
#include <cuda_runtime.h>
#include <cuda_fp16.h>
#include <cstdint>

#define D_DIM 768
#define H_DIM 3072
#define E_NUM 8
#define MAX_T 4096

// ---------------- device scratch ----------------
__device__ int    g_counts[E_NUM];
__device__ int    g_tok [E_NUM * MAX_T];
__device__ int    g_slot[E_NUM * MAX_T];
__device__ float  g_pslot[2 * MAX_T];
__device__ __half g_xh [(size_t)MAX_T * D_DIM];          // 6.3 MB
__device__ __half g_hid[(size_t)2 * MAX_T * H_DIM];      // 50.3 MB (fp16)
__device__ float  g_y  [(size_t)2 * MAX_T * D_DIM];      // 25.2 MB
__device__ __half g_w1p[(size_t)E_NUM * D_DIM * H_DIM];  // 37.7 MB (k-pair interleaved)
__device__ __half g_w2p[(size_t)E_NUM * H_DIM * D_DIM];  // 37.7 MB

__device__ __forceinline__ void mma_f16(float* d, const uint4& a, const uint2& b) {
    asm volatile(
        "mma.sync.aligned.m16n8k16.row.col.f32.f16.f16.f32 "
        "{%0,%1,%2,%3}, {%4,%5,%6,%7}, {%8,%9}, {%0,%1,%2,%3};"
        : "+f"(d[0]), "+f"(d[1]), "+f"(d[2]), "+f"(d[3])
        : "r"(a.x), "r"(a.y), "r"(a.z), "r"(a.w), "r"(b.x), "r"(b.y));
}

// ---------------- converts ----------------
// x (fp32 row-major) -> fp16 row-major (k-contiguous = A-fragment ready)
__global__ void __launch_bounds__(256) convert_x_kernel(
    const float* __restrict__ x, int n8)
{
    int i = blockIdx.x * 256 + threadIdx.x;
    if (i >= n8) return;
    const float4* src = (const float4*)x + 2 * (size_t)i;
    float4 a = src[0], b = src[1];
    __half2 h0 = __floats2half2_rn(a.x, a.y);
    __half2 h1 = __floats2half2_rn(a.z, a.w);
    __half2 h2 = __floats2half2_rn(b.x, b.y);
    __half2 h3 = __floats2half2_rn(b.z, b.w);
    uint4 o;
    o.x = *(uint32_t*)&h0; o.y = *(uint32_t*)&h1;
    o.z = *(uint32_t*)&h2; o.w = *(uint32_t*)&h3;
    ((uint4*)g_xh)[i] = o;
}

// W (fp32 [e][K][N]) -> fp16 k-pair interleaved: b32 unit (kp, n) = {W[2kp][n], W[2kp+1][n]}
__global__ void __launch_bounds__(256) convert_w_kernel(
    const float* __restrict__ W, __half* __restrict__ Wp, int K, int N, int total)
{
    int i = blockIdx.x * 256 + threadIdx.x;   // one uint4 (4 b32 = kp x 4n)
    if (i >= total) return;
    int n4 = i % (N / 4);
    int ek = i / (N / 4);           // e*(K/2) + kp
    int kp = ek % (K / 2), e = ek / (K / 2);
    const float* r0 = W + ((size_t)e * K + 2 * kp) * N + n4 * 4;
    float4 a = *(const float4*)r0;
    float4 b = *(const float4*)(r0 + N);
    __half2 h0 = __floats2half2_rn(a.x, b.x);
    __half2 h1 = __floats2half2_rn(a.y, b.y);
    __half2 h2 = __floats2half2_rn(a.z, b.z);
    __half2 h3 = __floats2half2_rn(a.w, b.w);
    uint4 o;
    o.x = *(uint32_t*)&h0; o.y = *(uint32_t*)&h1;
    o.z = *(uint32_t*)&h2; o.w = *(uint32_t*)&h3;
    ((uint4*)Wp)[(size_t)ek * (N / 4) + n4] = o;
}

// ---------------- routing ----------------
__global__ void zero_counts_kernel() {
    if (threadIdx.x < E_NUM) g_counts[threadIdx.x] = 0;
}

__global__ void __launch_bounds__(256) route_kernel(
    const float* __restrict__ x, const float* __restrict__ noise,
    const float* __restrict__ Wg, const float* __restrict__ bg,
    const float* __restrict__ Wn, const float* __restrict__ bn)
{
    int t = blockIdx.x, tid = threadIdx.x;
    float pg[E_NUM], pn[E_NUM];
#pragma unroll
    for (int e = 0; e < E_NUM; e++) { pg[e] = 0.f; pn[e] = 0.f; }
    const float* xr = x + (size_t)t * D_DIM;
    for (int d = tid; d < D_DIM; d += 256) {
        float xv = xr[d];
#pragma unroll
        for (int e = 0; e < E_NUM; e++) {
            pg[e] = fmaf(xv, Wg[d * E_NUM + e], pg[e]);
            pn[e] = fmaf(xv, Wn[d * E_NUM + e], pn[e]);
        }
    }
#pragma unroll
    for (int e = 0; e < E_NUM; e++)
#pragma unroll
        for (int o = 16; o > 0; o >>= 1) {
            pg[e] += __shfl_down_sync(0xffffffffu, pg[e], o);
            pn[e] += __shfl_down_sync(0xffffffffu, pn[e], o);
        }
    __shared__ float sg[8][E_NUM], sn[8][E_NUM];
    int w = tid >> 5, l = tid & 31;
    if (l == 0)
#pragma unroll
        for (int e = 0; e < E_NUM; e++) { sg[w][e] = pg[e]; sn[w][e] = pn[e]; }
    __syncthreads();

    if (tid == 0) {
        float h[E_NUM];
#pragma unroll
        for (int e = 0; e < E_NUM; e++) {
            float a = bg[e], b = bn[e];
#pragma unroll
            for (int ww = 0; ww < 8; ww++) { a += sg[ww][e]; b += sn[ww][e]; }
            float sp = fmaxf(b, 0.f) + log1pf(expf(-fabsf(b)));
            h[e] = a + noise[(size_t)t * E_NUM + e] * sp;
        }
        int i0 = 0;
#pragma unroll
        for (int e = 1; e < E_NUM; e++) if (h[e] > h[i0]) i0 = e;
        int i1 = (i0 == 0) ? 1 : 0;
#pragma unroll
        for (int e = 0; e < E_NUM; e++) if (e != i0 && h[e] > h[i1]) i1 = e;

        float p0 = 1.f / (1.f + expf(h[i1] - h[i0]));
        float p1 = 1.f - p0;
        g_pslot[2 * t]     = p0;
        g_pslot[2 * t + 1] = p1;

        int s0 = atomicAdd(&g_counts[i0], 1);
        g_tok [i0 * MAX_T + s0] = t;
        g_slot[i0 * MAX_T + s0] = 2 * t;
        int s1 = atomicAdd(&g_counts[i1], 1);
        g_tok [i1 * MAX_T + s1] = t;
        g_slot[i1 * MAX_T + s1] = 2 * t + 1;
    }
}

// ---------------- grouped fp16 mma.sync GEMM ----------------
// BM=128, BN=256, BK=32 (2 ks-steps of k16), double-buffered.
// 8 warps (2x4), warp tile 64x64 = 4 mf x 8 nf of m16n8k16.
// SMEM b32 units:
//   A: [(mfg*2+ks)*32 + ((g*4+t)^ks)]*4 + (rh + 2*ch)       2048 u32
//   B: [(nfp*2+ks)*32 + (lane^(nfp&7))]*4 + h*2 + breg      4096 u32
#define BUF_U32 6144
#define SM_BYTES (2 * BUF_U32 * 4)

template <bool G1>
__global__ void __launch_bounds__(256) moe_gemm(
    const __half* __restrict__ Ah, const __half* __restrict__ Wp,
    const float* __restrict__ bias, void* __restrict__ OutV)
{
    constexpr int KTOT = G1 ? D_DIM : H_DIM;
    constexpr int NG   = G1 ? H_DIM : D_DIM;
    constexpr int NC   = KTOT / 32;

    int e   = blockIdx.z;
    int cnt = g_counts[e];
    int m0  = blockIdx.y * 128;
    if (m0 >= cnt) return;
    int n0  = blockIdx.x * 256;

    extern __shared__ uint32_t smu[];

    int tid = threadIdx.x, wid = tid >> 5, lane = tid & 31;
    int wm = wid >> 2, wn = wid & 3;
    const int* idxarr = G1 ? g_tok : g_slot;

    // ---- A plan: thread -> row r = tid>>1, k16-half ksl = tid&1 ----
    int r = tid >> 1, ksl = tid & 1;
    int mfg = r >> 4, g = r & 7, rh = (r >> 3) & 1;
    const __half* aptr = nullptr;
    {
        int grow = m0 + r;
        if (grow < cnt)
            aptr = Ah + (size_t)idxarr[e * MAX_T + grow] * KTOT + ksl * 16;
    }
    // ---- B plan: quads jj<4: u = tid+256*jj -> kpair p = u>>6, n4 = u&63 ----
    const uint32_t* wb32 = (const uint32_t*)Wp +
                           ((size_t)e * (KTOT / 2)) * NG + n0;

    uint4 av[2], bv[4];
    auto ldg_chunk = [&](int c) {
        if (aptr) {
            const uint4* p = (const uint4*)(aptr + (size_t)c * 32);
            av[0] = p[0]; av[1] = p[1];
        } else {
            av[0] = make_uint4(0, 0, 0, 0); av[1] = make_uint4(0, 0, 0, 0);
        }
#pragma unroll
        for (int jj = 0; jj < 4; jj++) {
            int u = tid + 256 * jj, p = u >> 6, n4 = u & 63;
            bv[jj] = *(const uint4*)(wb32 + ((size_t)c * 16 + p) * NG + n4 * 4);
        }
    };
    auto store_chunk = [&](int buf) {
        uint32_t* smA = smu + buf * BUF_U32;
        uint32_t* smB = smA + 2048;
        int ablk = (mfg * 2 + ksl) * 32;
#pragma unroll
        for (int j = 0; j < 2; j++) {
            int q = rh + 2 * j;
            const uint32_t* w = (const uint32_t*)&av[j];
#pragma unroll
            for (int t = 0; t < 4; t++)
                smA[(ablk + ((g * 4 + t) ^ ksl)) * 4 + q] = w[t];
        }
#pragma unroll
        for (int jj = 0; jj < 4; jj++) {
            int u = tid + 256 * jj, p = u >> 6, n4 = u & 63;
            int ks = p >> 3, pp = p & 7, breg = pp >> 2, t = pp & 3;
            int nfp = n4 >> 2, h = (n4 >> 1) & 1, sw = nfp & 7;
            int nl0 = (n4 & 1) * 4;
            int base = (nfp * 2 + ks) * 32, q = h * 2 + breg;
            const uint32_t* w = (const uint32_t*)&bv[jj];
#pragma unroll
            for (int ii = 0; ii < 4; ii++)
                smB[(base + (((nl0 + ii) * 4 + t) ^ sw)) * 4 + q] = w[ii];
        }
    };

    float acc[4][8][4];
#pragma unroll
    for (int a = 0; a < 4; a++)
#pragma unroll
        for (int b = 0; b < 8; b++)
#pragma unroll
            for (int k = 0; k < 4; k++) acc[a][b][k] = 0.f;

    ldg_chunk(0);
    store_chunk(0);
    __syncthreads();

#pragma unroll 1
    for (int c = 0; c < NC; c++) {
        int buf = c & 1;
        if (c + 1 < NC) ldg_chunk(c + 1);

        const uint4* smA4 = (const uint4*)(smu + buf * BUF_U32);
        const uint4* smB4 = (const uint4*)(smu + buf * BUF_U32 + 2048);
#pragma unroll
        for (int ks = 0; ks < 2; ks++) {
            uint4 af[4]; uint2 bf[8];
#pragma unroll
            for (int mf = 0; mf < 4; mf++)
                af[mf] = smA4[((wm * 4 + mf) * 2 + ks) * 32 + (lane ^ ks)];
#pragma unroll
            for (int nfp = 0; nfp < 4; nfp++) {
                int nfg = wn * 4 + nfp;
                uint4 bb = smB4[(nfg * 2 + ks) * 32 + (lane ^ (nfg & 7))];
                bf[2 * nfp].x     = bb.x; bf[2 * nfp].y     = bb.y;
                bf[2 * nfp + 1].x = bb.z; bf[2 * nfp + 1].y = bb.w;
            }
#pragma unroll
            for (int mf = 0; mf < 4; mf++)
#pragma unroll
                for (int nf = 0; nf < 8; nf++)
                    mma_f16(acc[mf][nf], af[mf], bf[nf]);
        }

        if (c + 1 < NC) store_chunk(buf ^ 1);
        __syncthreads();
    }

    // ---- epilogue ----
#pragma unroll
    for (int mf = 0; mf < 4; mf++) {
        int r0 = m0 + wm * 64 + mf * 16 + (lane >> 2);
        int r1 = r0 + 8;
        bool v0 = r0 < cnt, v1 = r1 < cnt;
        int s0 = v0 ? g_slot[e * MAX_T + r0] : 0;
        int s1 = v1 ? g_slot[e * MAX_T + r1] : 0;
#pragma unroll
        for (int nf = 0; nf < 8; nf++) {
            int col = n0 + wn * 64 + nf * 8 + (lane & 3) * 2;
            float2 bb = *(const float2*)&bias[(size_t)e * NG + col];
            float x0 = acc[mf][nf][0] + bb.x, x1 = acc[mf][nf][1] + bb.y;
            float x2 = acc[mf][nf][2] + bb.x, x3 = acc[mf][nf][3] + bb.y;
            if (G1) {
                x0 = fmaxf(x0, 0.f); x1 = fmaxf(x1, 0.f);
                x2 = fmaxf(x2, 0.f); x3 = fmaxf(x3, 0.f);
                __half* Out = (__half*)OutV;
                if (v0) {
                    __half2 hv = __floats2half2_rn(x0, x1);
                    *(__half2*)(Out + (size_t)s0 * NG + col) = hv;
                }
                if (v1) {
                    __half2 hv = __floats2half2_rn(x2, x3);
                    *(__half2*)(Out + (size_t)s1 * NG + col) = hv;
                }
            } else {
                float* Out = (float*)OutV;
                if (v0) { float2 o; o.x = x0; o.y = x1;
                          *(float2*)(Out + (size_t)s0 * NG + col) = o; }
                if (v1) { float2 o; o.x = x2; o.y = x3;
                          *(float2*)(Out + (size_t)s1 * NG + col) = o; }
            }
        }
    }
}

// out[t] = p0*y[2t] + p1*y[2t+1]
__global__ void __launch_bounds__(256) combine_kernel(float* __restrict__ out, int T)
{
    int idx = blockIdx.x * 256 + threadIdx.x;
    int total = T * (D_DIM / 4);
    if (idx >= total) return;
    int t  = idx / (D_DIM / 4);
    int c4 = idx % (D_DIM / 4);
    float4 a = ((const float4*)(g_y + (size_t)(2 * t) * D_DIM))[c4];
    float4 b = ((const float4*)(g_y + (size_t)(2 * t + 1) * D_DIM))[c4];
    float p0 = g_pslot[2 * t], p1 = g_pslot[2 * t + 1];
    float4 o;
    o.x = p0 * a.x + p1 * b.x;
    o.y = p0 * a.y + p1 * b.y;
    o.z = p0 * a.z + p1 * b.z;
    o.w = p0 * a.w + p1 * b.w;
    ((float4*)out)[idx] = o;
}

extern "C" void kernel_launch(void* const* d_in, const int* in_sizes, int n_in,
                              void* d_out, int out_size)
{
    const float* x     = (const float*)d_in[0];
    const float* noise = (const float*)d_in[1];
    const float* Wg    = (const float*)d_in[2];
    const float* bg    = (const float*)d_in[3];
    const float* Wn    = (const float*)d_in[4];
    const float* bn    = (const float*)d_in[5];
    const float* W1    = (const float*)d_in[6];
    const float* b1    = (const float*)d_in[7];
    const float* W2    = (const float*)d_in[8];
    const float* b2    = (const float*)d_in[9];
    float* out = (float*)d_out;

    int T = in_sizes[0] / D_DIM;
    if (T > MAX_T) T = MAX_T;

    cudaFuncSetAttribute(moe_gemm<true>,
                         cudaFuncAttributeMaxDynamicSharedMemorySize, SM_BYTES);
    cudaFuncSetAttribute(moe_gemm<false>,
                         cudaFuncAttributeMaxDynamicSharedMemorySize, SM_BYTES);

    __half *xh = nullptr, *hid = nullptr, *w1p = nullptr, *w2p = nullptr;
    float* yv = nullptr;
    cudaGetSymbolAddress((void**)&xh,  g_xh);
    cudaGetSymbolAddress((void**)&hid, g_hid);
    cudaGetSymbolAddress((void**)&w1p, g_w1p);
    cudaGetSymbolAddress((void**)&w2p, g_w2p);
    cudaGetSymbolAddress((void**)&yv,  g_y);

    zero_counts_kernel<<<1, 32>>>();

    int n8 = T * D_DIM / 8;
    convert_x_kernel<<<(n8 + 255) / 256, 256>>>(x, n8);
    int tw1 = E_NUM * (D_DIM / 2) * (H_DIM / 4);
    convert_w_kernel<<<(tw1 + 255) / 256, 256>>>(W1, w1p, D_DIM, H_DIM, tw1);
    int tw2 = E_NUM * (H_DIM / 2) * (D_DIM / 4);
    convert_w_kernel<<<(tw2 + 255) / 256, 256>>>(W2, w2p, H_DIM, D_DIM, tw2);

    route_kernel<<<T, 256>>>(x, noise, Wg, bg, Wn, bn);

    int mt = (T + 127) / 128;
    moe_gemm<true ><<<dim3(H_DIM / 256, mt, E_NUM), 256, SM_BYTES>>>(xh,  w1p, b1, hid);
    moe_gemm<false><<<dim3(D_DIM / 256, mt, E_NUM), 256, SM_BYTES>>>(hid, w2p, b2, yv);

    combine_kernel<<<(T * (D_DIM / 4) + 255) / 256, 256>>>(out, T);
}

// round 7
// speedup vs baseline: 5.8116x; 1.1714x over previous
#include <cuda_runtime.h>
#include <cuda_fp16.h>
#include <cstdint>

#define D_DIM 768
#define H_DIM 3072
#define E_NUM 8
#define MAX_T 4096

// ---------------- device scratch ----------------
__device__ int    g_counts[E_NUM];
__device__ int    g_tok [E_NUM * MAX_T];
__device__ int    g_slot[E_NUM * MAX_T];
__device__ float  g_pslot[2 * MAX_T];
__device__ __half g_xh [(size_t)MAX_T * D_DIM];          // 6.3 MB
__device__ __half g_hid[(size_t)2 * MAX_T * H_DIM];      // 50.3 MB (fp16)
__device__ float  g_y  [(size_t)2 * MAX_T * D_DIM];      // 25.2 MB
__device__ __half g_w1h[(size_t)E_NUM * D_DIM * H_DIM];  // 37.7 MB fp16 row-major
__device__ __half g_w2h[(size_t)E_NUM * H_DIM * D_DIM];  // 37.7 MB

// ---------------- PTX helpers ----------------
__device__ __forceinline__ uint32_t smem_u32(const void* p) {
    uint32_t r;
    asm("{ .reg .u64 t; cvta.to.shared.u64 t, %1; cvt.u32.u64 %0, t; }"
        : "=r"(r) : "l"(p));
    return r;
}
__device__ __forceinline__ void mma_f16(float* d, const uint4& a, const uint2& b) {
    asm volatile(
        "mma.sync.aligned.m16n8k16.row.col.f32.f16.f16.f32 "
        "{%0,%1,%2,%3}, {%4,%5,%6,%7}, {%8,%9}, {%0,%1,%2,%3};"
        : "+f"(d[0]), "+f"(d[1]), "+f"(d[2]), "+f"(d[3])
        : "r"(a.x), "r"(a.y), "r"(a.z), "r"(a.w), "r"(b.x), "r"(b.y));
}
__device__ __forceinline__ void ldsm_x4(uint4& r, uint32_t addr) {
    asm volatile("ldmatrix.sync.aligned.m8n8.x4.shared.b16 {%0,%1,%2,%3}, [%4];"
                 : "=r"(r.x), "=r"(r.y), "=r"(r.z), "=r"(r.w) : "r"(addr));
}
__device__ __forceinline__ void ldsm_x4t(uint4& r, uint32_t addr) {
    asm volatile("ldmatrix.sync.aligned.m8n8.x4.trans.shared.b16 {%0,%1,%2,%3}, [%4];"
                 : "=r"(r.x), "=r"(r.y), "=r"(r.z), "=r"(r.w) : "r"(addr));
}
__device__ __forceinline__ void cp16(uint32_t dst, const void* src, uint32_t sz) {
    asm volatile("cp.async.cg.shared.global [%0], [%1], 16, %2;"
                 :: "r"(dst), "l"(src), "r"(sz) : "memory");
}
__device__ __forceinline__ void cp_commit() {
    asm volatile("cp.async.commit_group;" ::: "memory");
}
__device__ __forceinline__ void cp_wait2() {
    asm volatile("cp.async.wait_group 2;" ::: "memory");
}

// ---------------- generic fp32 -> fp16 convert (x, W1, W2) ----------------
__global__ void __launch_bounds__(256) convert_f2h(
    const float* __restrict__ src, __half* __restrict__ dst, int n8)
{
    int i = blockIdx.x * 256 + threadIdx.x;
    if (i >= n8) return;
    const float4* s = (const float4*)src + 2 * (size_t)i;
    float4 a = s[0], b = s[1];
    __half2 h0 = __floats2half2_rn(a.x, a.y);
    __half2 h1 = __floats2half2_rn(a.z, a.w);
    __half2 h2 = __floats2half2_rn(b.x, b.y);
    __half2 h3 = __floats2half2_rn(b.z, b.w);
    uint4 o;
    o.x = *(uint32_t*)&h0; o.y = *(uint32_t*)&h1;
    o.z = *(uint32_t*)&h2; o.w = *(uint32_t*)&h3;
    ((uint4*)dst)[i] = o;
}

// ---------------- routing ----------------
__global__ void zero_counts_kernel() {
    if (threadIdx.x < E_NUM) g_counts[threadIdx.x] = 0;
}

__global__ void __launch_bounds__(256) route_kernel(
    const float* __restrict__ x, const float* __restrict__ noise,
    const float* __restrict__ Wg, const float* __restrict__ bg,
    const float* __restrict__ Wn, const float* __restrict__ bn)
{
    int t = blockIdx.x, tid = threadIdx.x;
    float pg[E_NUM], pn[E_NUM];
#pragma unroll
    for (int e = 0; e < E_NUM; e++) { pg[e] = 0.f; pn[e] = 0.f; }
    const float* xr = x + (size_t)t * D_DIM;
    for (int d = tid; d < D_DIM; d += 256) {
        float xv = xr[d];
#pragma unroll
        for (int e = 0; e < E_NUM; e++) {
            pg[e] = fmaf(xv, Wg[d * E_NUM + e], pg[e]);
            pn[e] = fmaf(xv, Wn[d * E_NUM + e], pn[e]);
        }
    }
#pragma unroll
    for (int e = 0; e < E_NUM; e++)
#pragma unroll
        for (int o = 16; o > 0; o >>= 1) {
            pg[e] += __shfl_down_sync(0xffffffffu, pg[e], o);
            pn[e] += __shfl_down_sync(0xffffffffu, pn[e], o);
        }
    __shared__ float sg[8][E_NUM], sn[8][E_NUM];
    int w = tid >> 5, l = tid & 31;
    if (l == 0)
#pragma unroll
        for (int e = 0; e < E_NUM; e++) { sg[w][e] = pg[e]; sn[w][e] = pn[e]; }
    __syncthreads();

    if (tid == 0) {
        float h[E_NUM];
#pragma unroll
        for (int e = 0; e < E_NUM; e++) {
            float a = bg[e], b = bn[e];
#pragma unroll
            for (int ww = 0; ww < 8; ww++) { a += sg[ww][e]; b += sn[ww][e]; }
            float sp = fmaxf(b, 0.f) + log1pf(expf(-fabsf(b)));
            h[e] = a + noise[(size_t)t * E_NUM + e] * sp;
        }
        int i0 = 0;
#pragma unroll
        for (int e = 1; e < E_NUM; e++) if (h[e] > h[i0]) i0 = e;
        int i1 = (i0 == 0) ? 1 : 0;
#pragma unroll
        for (int e = 0; e < E_NUM; e++) if (e != i0 && h[e] > h[i1]) i1 = e;

        float p0 = 1.f / (1.f + expf(h[i1] - h[i0]));
        float p1 = 1.f - p0;
        g_pslot[2 * t]     = p0;
        g_pslot[2 * t + 1] = p1;

        int s0 = atomicAdd(&g_counts[i0], 1);
        g_tok [i0 * MAX_T + s0] = t;
        g_slot[i0 * MAX_T + s0] = 2 * t;
        int s1 = atomicAdd(&g_counts[i1], 1);
        g_tok [i1 * MAX_T + s1] = t;
        g_slot[i1 * MAX_T + s1] = 2 * t + 1;
    }
}

// ---------------- grouped fp16 GEMM: cp.async + ldmatrix + mma ----------------
// BM=128, BN=256, BK=32, 4-stage cp.async ring. 8 warps 2x4, warp tile 64x64.
// Per-stage SMEM: A 128x32 half (8KB, unit = row*4 + (kq ^ ((row>>1)&3))),
//                 B  32x256 half (16KB, unit = k*32 + (nq ^ (k&7))).
#define STAGE_BYTES 24576
#define SM_BYTES (4 * STAGE_BYTES)   // 98304

template <bool G1>
__global__ void __launch_bounds__(256) moe_gemm(
    const __half* __restrict__ Ah, const __half* __restrict__ Wh,
    const float* __restrict__ bias, void* __restrict__ OutV)
{
    constexpr int KTOT = G1 ? D_DIM : H_DIM;
    constexpr int NG   = G1 ? H_DIM : D_DIM;
    constexpr int NC   = KTOT / 32;

    int e   = blockIdx.z;
    int cnt = g_counts[e];
    int m0  = blockIdx.y * 128;
    if (m0 >= cnt) return;
    int n0  = blockIdx.x * 256;

    extern __shared__ char smem[];
    uint32_t sbase = smem_u32(smem);

    int tid = threadIdx.x, wid = tid >> 5, lane = tid & 31;
    int wm = wid >> 2, wn = wid & 3;
    const int* idxarr = G1 ? g_tok : g_slot;

    // ---- cp.async plans ----
    int arow0 = tid >> 2, akq = tid & 3;
    int arow1 = arow0 + 64;
    uint32_t a_dst0 = (uint32_t)(arow0 * 4 + (akq ^ ((arow0 >> 1) & 3))) * 16;
    uint32_t a_dst1 = (uint32_t)(arow1 * 4 + (akq ^ ((arow1 >> 1) & 3))) * 16;
    const __half* a_src0 = Ah; uint32_t a_sz0 = 0;
    const __half* a_src1 = Ah; uint32_t a_sz1 = 0;
    {
        int gr = m0 + arow0;
        if (gr < cnt) {
            a_src0 = Ah + (size_t)idxarr[e * MAX_T + gr] * KTOT + akq * 8;
            a_sz0 = 16;
        }
        gr = m0 + arow1;
        if (gr < cnt) {
            a_src1 = Ah + (size_t)idxarr[e * MAX_T + gr] * KTOT + akq * 8;
            a_sz1 = 16;
        }
    }
    int bnq = tid & 31, bk0 = tid >> 5;
    const __half* b_src = Wh + (size_t)e * KTOT * NG + n0 + bnq * 8;
    uint32_t b_dst[4];
#pragma unroll
    for (int j = 0; j < 4; j++) {
        int k = bk0 + 8 * j;
        b_dst[j] = 8192u + (uint32_t)(k * 32 + (bnq ^ (k & 7))) * 16;
    }

    auto issue = [&](int c) {
        if (c < NC) {
            uint32_t sa = sbase + (uint32_t)(c & 3) * STAGE_BYTES;
            cp16(sa + a_dst0, a_src0 + (size_t)c * 32, a_sz0);
            cp16(sa + a_dst1, a_src1 + (size_t)c * 32, a_sz1);
            const __half* bs = b_src + (size_t)c * 32 * NG;
#pragma unroll
            for (int j = 0; j < 4; j++)
                cp16(sa + b_dst[j], bs + (size_t)(bk0 + 8 * j) * NG, 16);
        }
        cp_commit();
    };

    issue(0); issue(1); issue(2);

    // lane constants for ldmatrix addressing
    int lrow = (lane & 7) + 8 * ((lane >> 3) & 1);   // 0..15
    int lsel = lane >> 4;                            // 0/1

    float acc[4][8][4];
#pragma unroll
    for (int a = 0; a < 4; a++)
#pragma unroll
        for (int b = 0; b < 8; b++)
#pragma unroll
            for (int k = 0; k < 4; k++) acc[a][b][k] = 0.f;

#pragma unroll 1
    for (int c = 0; c < NC; c++) {
        cp_wait2();
        __syncthreads();
        issue(c + 3);

        uint32_t sa = sbase + (uint32_t)(c & 3) * STAGE_BYTES;
        uint32_t sb = sa + 8192u;
#pragma unroll
        for (int ks = 0; ks < 2; ks++) {
            uint4 af[4]; uint2 bf[8];
            int kq = ks * 2 + lsel;
#pragma unroll
            for (int mf = 0; mf < 4; mf++) {
                int row = wm * 64 + mf * 16 + lrow;
                ldsm_x4(af[mf],
                        sa + (uint32_t)(row * 4 + (kq ^ ((row >> 1) & 3))) * 16);
            }
            int kb = ks * 16 + lrow;
#pragma unroll
            for (int np = 0; np < 4; np++) {
                int nq = (wn * 4 + np) * 2 + lsel;
                uint4 bb;
                ldsm_x4t(bb, sb + (uint32_t)(kb * 32 + (nq ^ (kb & 7))) * 16);
                bf[2 * np].x     = bb.x; bf[2 * np].y     = bb.y;
                bf[2 * np + 1].x = bb.z; bf[2 * np + 1].y = bb.w;
            }
#pragma unroll
            for (int mf = 0; mf < 4; mf++)
#pragma unroll
                for (int nf = 0; nf < 8; nf++)
                    mma_f16(acc[mf][nf], af[mf], bf[nf]);
        }
    }

    // ---- epilogue ----
#pragma unroll
    for (int mf = 0; mf < 4; mf++) {
        int r0 = m0 + wm * 64 + mf * 16 + (lane >> 2);
        int r1 = r0 + 8;
        bool v0 = r0 < cnt, v1 = r1 < cnt;
        int s0 = v0 ? g_slot[e * MAX_T + r0] : 0;
        int s1 = v1 ? g_slot[e * MAX_T + r1] : 0;
#pragma unroll
        for (int nf = 0; nf < 8; nf++) {
            int col = n0 + wn * 64 + nf * 8 + (lane & 3) * 2;
            float2 bb = *(const float2*)&bias[(size_t)e * NG + col];
            float x0 = acc[mf][nf][0] + bb.x, x1 = acc[mf][nf][1] + bb.y;
            float x2 = acc[mf][nf][2] + bb.x, x3 = acc[mf][nf][3] + bb.y;
            if (G1) {
                x0 = fmaxf(x0, 0.f); x1 = fmaxf(x1, 0.f);
                x2 = fmaxf(x2, 0.f); x3 = fmaxf(x3, 0.f);
                __half* Out = (__half*)OutV;
                if (v0) {
                    __half2 hv = __floats2half2_rn(x0, x1);
                    *(__half2*)(Out + (size_t)s0 * NG + col) = hv;
                }
                if (v1) {
                    __half2 hv = __floats2half2_rn(x2, x3);
                    *(__half2*)(Out + (size_t)s1 * NG + col) = hv;
                }
            } else {
                float* Out = (float*)OutV;
                if (v0) { float2 o; o.x = x0; o.y = x1;
                          *(float2*)(Out + (size_t)s0 * NG + col) = o; }
                if (v1) { float2 o; o.x = x2; o.y = x3;
                          *(float2*)(Out + (size_t)s1 * NG + col) = o; }
            }
        }
    }
}

// out[t] = p0*y[2t] + p1*y[2t+1]
__global__ void __launch_bounds__(256) combine_kernel(float* __restrict__ out, int T)
{
    int idx = blockIdx.x * 256 + threadIdx.x;
    int total = T * (D_DIM / 4);
    if (idx >= total) return;
    int t  = idx / (D_DIM / 4);
    int c4 = idx % (D_DIM / 4);
    float4 a = ((const float4*)(g_y + (size_t)(2 * t) * D_DIM))[c4];
    float4 b = ((const float4*)(g_y + (size_t)(2 * t + 1) * D_DIM))[c4];
    float p0 = g_pslot[2 * t], p1 = g_pslot[2 * t + 1];
    float4 o;
    o.x = p0 * a.x + p1 * b.x;
    o.y = p0 * a.y + p1 * b.y;
    o.z = p0 * a.z + p1 * b.z;
    o.w = p0 * a.w + p1 * b.w;
    ((float4*)out)[idx] = o;
}

extern "C" void kernel_launch(void* const* d_in, const int* in_sizes, int n_in,
                              void* d_out, int out_size)
{
    const float* x     = (const float*)d_in[0];
    const float* noise = (const float*)d_in[1];
    const float* Wg    = (const float*)d_in[2];
    const float* bg    = (const float*)d_in[3];
    const float* Wn    = (const float*)d_in[4];
    const float* bn    = (const float*)d_in[5];
    const float* W1    = (const float*)d_in[6];
    const float* b1    = (const float*)d_in[7];
    const float* W2    = (const float*)d_in[8];
    const float* b2    = (const float*)d_in[9];
    float* out = (float*)d_out;

    int T = in_sizes[0] / D_DIM;
    if (T > MAX_T) T = MAX_T;

    cudaFuncSetAttribute(moe_gemm<true>,
                         cudaFuncAttributeMaxDynamicSharedMemorySize, SM_BYTES);
    cudaFuncSetAttribute(moe_gemm<false>,
                         cudaFuncAttributeMaxDynamicSharedMemorySize, SM_BYTES);

    __half *xh = nullptr, *hid = nullptr, *w1h = nullptr, *w2h = nullptr;
    float* yv = nullptr;
    cudaGetSymbolAddress((void**)&xh,  g_xh);
    cudaGetSymbolAddress((void**)&hid, g_hid);
    cudaGetSymbolAddress((void**)&w1h, g_w1h);
    cudaGetSymbolAddress((void**)&w2h, g_w2h);
    cudaGetSymbolAddress((void**)&yv,  g_y);

    zero_counts_kernel<<<1, 32>>>();

    int nx = T * D_DIM / 8;
    convert_f2h<<<(nx + 255) / 256, 256>>>(x, xh, nx);
    int nw = E_NUM * D_DIM * H_DIM / 8;
    convert_f2h<<<(nw + 255) / 256, 256>>>(W1, w1h, nw);
    convert_f2h<<<(nw + 255) / 256, 256>>>(W2, w2h, nw);

    route_kernel<<<T, 256>>>(x, noise, Wg, bg, Wn, bn);

    int mt = (T + 127) / 128;
    moe_gemm<true ><<<dim3(H_DIM / 256, mt, E_NUM), 256, SM_BYTES>>>(xh,  w1h, b1, hid);
    moe_gemm<false><<<dim3(D_DIM / 256, mt, E_NUM), 256, SM_BYTES>>>(hid, w2h, b2, yv);

    combine_kernel<<<(T * (D_DIM / 4) + 255) / 256, 256>>>(out, T);
}

// round 8
// speedup vs baseline: 7.5916x; 1.3063x over previous
#include <cuda_runtime.h>
#include <cuda_fp16.h>
#include <cstdint>

#define D_DIM 768
#define H_DIM 3072
#define E_NUM 8
#define MAX_T 4096

// ---------------- device scratch ----------------
__device__ int    g_counts[E_NUM];
__device__ int    g_tok [E_NUM * MAX_T];
__device__ int    g_slot[E_NUM * MAX_T];
__device__ float  g_pslot[2 * MAX_T];
__device__ __half g_xh [(size_t)MAX_T * D_DIM];
__device__ __half g_hid[(size_t)2 * MAX_T * H_DIM];
__device__ float  g_y  [(size_t)2 * MAX_T * D_DIM];
__device__ __half g_w1h[(size_t)E_NUM * D_DIM * H_DIM];
__device__ __half g_w2h[(size_t)E_NUM * H_DIM * D_DIM];

// ---------------- PTX helpers ----------------
__device__ __forceinline__ uint32_t smem_u32(const void* p) {
    uint32_t r;
    asm("{ .reg .u64 t; cvta.to.shared.u64 t, %1; cvt.u32.u64 %0, t; }"
        : "=r"(r) : "l"(p));
    return r;
}
__device__ __forceinline__ void mma_f16(float* d, const uint4& a, const uint2& b) {
    asm volatile(
        "mma.sync.aligned.m16n8k16.row.col.f32.f16.f16.f32 "
        "{%0,%1,%2,%3}, {%4,%5,%6,%7}, {%8,%9}, {%0,%1,%2,%3};"
        : "+f"(d[0]), "+f"(d[1]), "+f"(d[2]), "+f"(d[3])
        : "r"(a.x), "r"(a.y), "r"(a.z), "r"(a.w), "r"(b.x), "r"(b.y));
}
__device__ __forceinline__ void ldsm_x4(uint4& r, uint32_t addr) {
    asm volatile("ldmatrix.sync.aligned.m8n8.x4.shared.b16 {%0,%1,%2,%3}, [%4];"
                 : "=r"(r.x), "=r"(r.y), "=r"(r.z), "=r"(r.w) : "r"(addr));
}
__device__ __forceinline__ void ldsm_x4t(uint4& r, uint32_t addr) {
    asm volatile("ldmatrix.sync.aligned.m8n8.x4.trans.shared.b16 {%0,%1,%2,%3}, [%4];"
                 : "=r"(r.x), "=r"(r.y), "=r"(r.z), "=r"(r.w) : "r"(addr));
}
__device__ __forceinline__ void cp16(uint32_t dst, const void* src, uint32_t sz) {
    asm volatile("cp.async.cg.shared.global [%0], [%1], 16, %2;"
                 :: "r"(dst), "l"(src), "r"(sz) : "memory");
}
__device__ __forceinline__ void cp_commit() {
    asm volatile("cp.async.commit_group;" ::: "memory");
}
__device__ __forceinline__ void cp_wait1() {
    asm volatile("cp.async.wait_group 1;" ::: "memory");
}

// ---------------- fp32 -> fp16 convert ----------------
__global__ void __launch_bounds__(256) convert_f2h(
    const float* __restrict__ src, __half* __restrict__ dst, int n8)
{
    int i = blockIdx.x * 256 + threadIdx.x;
    if (i >= n8) return;
    const float4* s = (const float4*)src + 2 * (size_t)i;
    float4 a = s[0], b = s[1];
    __half2 h0 = __floats2half2_rn(a.x, a.y);
    __half2 h1 = __floats2half2_rn(a.z, a.w);
    __half2 h2 = __floats2half2_rn(b.x, b.y);
    __half2 h3 = __floats2half2_rn(b.z, b.w);
    uint4 o;
    o.x = *(uint32_t*)&h0; o.y = *(uint32_t*)&h1;
    o.z = *(uint32_t*)&h2; o.w = *(uint32_t*)&h3;
    ((uint4*)dst)[i] = o;
}

// ---------------- routing ----------------
__global__ void zero_counts_kernel() {
    if (threadIdx.x < E_NUM) g_counts[threadIdx.x] = 0;
}

__global__ void __launch_bounds__(256) route_kernel(
    const float* __restrict__ x, const float* __restrict__ noise,
    const float* __restrict__ Wg, const float* __restrict__ bg,
    const float* __restrict__ Wn, const float* __restrict__ bn)
{
    int t = blockIdx.x, tid = threadIdx.x;
    float pg[E_NUM], pn[E_NUM];
#pragma unroll
    for (int e = 0; e < E_NUM; e++) { pg[e] = 0.f; pn[e] = 0.f; }
    const float* xr = x + (size_t)t * D_DIM;
    for (int d = tid; d < D_DIM; d += 256) {
        float xv = xr[d];
#pragma unroll
        for (int e = 0; e < E_NUM; e++) {
            pg[e] = fmaf(xv, Wg[d * E_NUM + e], pg[e]);
            pn[e] = fmaf(xv, Wn[d * E_NUM + e], pn[e]);
        }
    }
#pragma unroll
    for (int e = 0; e < E_NUM; e++)
#pragma unroll
        for (int o = 16; o > 0; o >>= 1) {
            pg[e] += __shfl_down_sync(0xffffffffu, pg[e], o);
            pn[e] += __shfl_down_sync(0xffffffffu, pn[e], o);
        }
    __shared__ float sg[8][E_NUM], sn[8][E_NUM];
    int w = tid >> 5, l = tid & 31;
    if (l == 0)
#pragma unroll
        for (int e = 0; e < E_NUM; e++) { sg[w][e] = pg[e]; sn[w][e] = pn[e]; }
    __syncthreads();

    if (tid == 0) {
        float h[E_NUM];
#pragma unroll
        for (int e = 0; e < E_NUM; e++) {
            float a = bg[e], b = bn[e];
#pragma unroll
            for (int ww = 0; ww < 8; ww++) { a += sg[ww][e]; b += sn[ww][e]; }
            float sp = fmaxf(b, 0.f) + log1pf(expf(-fabsf(b)));
            h[e] = a + noise[(size_t)t * E_NUM + e] * sp;
        }
        int i0 = 0;
#pragma unroll
        for (int e = 1; e < E_NUM; e++) if (h[e] > h[i0]) i0 = e;
        int i1 = (i0 == 0) ? 1 : 0;
#pragma unroll
        for (int e = 0; e < E_NUM; e++) if (e != i0 && h[e] > h[i1]) i1 = e;

        float p0 = 1.f / (1.f + expf(h[i1] - h[i0]));
        float p1 = 1.f - p0;
        g_pslot[2 * t]     = p0;
        g_pslot[2 * t + 1] = p1;

        int s0 = atomicAdd(&g_counts[i0], 1);
        g_tok [i0 * MAX_T + s0] = t;
        g_slot[i0 * MAX_T + s0] = 2 * t;
        int s1 = atomicAdd(&g_counts[i1], 1);
        g_tok [i1 * MAX_T + s1] = t;
        g_slot[i1 * MAX_T + s1] = 2 * t + 1;
    }
}

// ---------------- grouped fp16 GEMM ----------------
// 128 threads (4 warps 2x2), BM=128, BN=128, BK=64, 3-stage cp.async ring.
// Warp tile 64x64 (4 mf x 8 nf of m16n8k16). 2 CTAs/SM (96KB smem each).
// Per-stage SMEM: A 128x64 half (16KB, unit = row*8 + (kq ^ (row&7))),
//                 B  64x128 half (16KB, unit = k*16 + (nq ^ (k&7))).
#define STAGE_BYTES 32768
#define SM_BYTES (3 * STAGE_BYTES)   // 98304 per CTA

template <bool G1>
__global__ void __launch_bounds__(128) moe_gemm(
    const __half* __restrict__ Ah, const __half* __restrict__ Wh,
    const float* __restrict__ bias, void* __restrict__ OutV)
{
    constexpr int KTOT = G1 ? D_DIM : H_DIM;
    constexpr int NG   = G1 ? H_DIM : D_DIM;
    constexpr int NC   = KTOT / 64;

    int e   = blockIdx.z;
    int cnt = g_counts[e];
    int m0  = blockIdx.y * 128;
    if (m0 >= cnt) return;
    int n0  = blockIdx.x * 128;

    extern __shared__ char smem[];
    uint32_t sbase = smem_u32(smem);

    int tid = threadIdx.x, wid = tid >> 5, lane = tid & 31;
    int wm = wid >> 1, wn = wid & 1;
    const int* idxarr = G1 ? g_tok : g_slot;

    // ---- cp.async plans ----
    // A: iter i<8: row = (tid>>3) + 16*i, kq = tid&7  (quad of 8 halfs along K)
    int ar0 = tid >> 3, akq = tid & 7;
    uint32_t a_dst0 = (uint32_t)(ar0 * 8 + (akq ^ (ar0 & 7))) * 16;
    const __half* a_src[8]; uint32_t a_sz[8];
#pragma unroll
    for (int i = 0; i < 8; i++) {
        int gr = m0 + ar0 + 16 * i;
        if (gr < cnt) {
            a_src[i] = Ah + (size_t)idxarr[e * MAX_T + gr] * KTOT + akq * 8;
            a_sz[i] = 16;
        } else { a_src[i] = Ah; a_sz[i] = 0; }
    }
    // B: iter j<8: k = (tid>>4) + 8*j, nq = tid&15
    int bk0 = tid >> 4, bnq = tid & 15;
    const __half* b_src = Wh + (size_t)e * KTOT * NG + (size_t)bk0 * NG + n0 + bnq * 8;
    uint32_t b_dst0 = 16384u + (uint32_t)(bk0 * 16 + (bnq ^ (bk0 & 7))) * 16;

    auto issue = [&](int c) {
        if (c < NC) {
            uint32_t sa = sbase + (uint32_t)(c % 3) * STAGE_BYTES;
#pragma unroll
            for (int i = 0; i < 8; i++)
                cp16(sa + a_dst0 + (uint32_t)i * 2048,
                     a_src[i] + (size_t)c * 64, a_sz[i]);
            const __half* bs = b_src + (size_t)c * 64 * NG;
#pragma unroll
            for (int j = 0; j < 8; j++)
                cp16(sa + b_dst0 + (uint32_t)j * 2048,
                     bs + (size_t)(8 * j) * NG, 16);
        }
        cp_commit();
    };

    issue(0); issue(1);

    int lrow = (lane & 7) + 8 * ((lane >> 3) & 1);   // 0..15
    int lsel = lane >> 4;                            // 0/1

    float acc[4][8][4];
#pragma unroll
    for (int a = 0; a < 4; a++)
#pragma unroll
        for (int b = 0; b < 8; b++)
#pragma unroll
            for (int k = 0; k < 4; k++) acc[a][b][k] = 0.f;

#pragma unroll 1
    for (int c = 0; c < NC; c++) {
        cp_wait1();
        __syncthreads();
        issue(c + 2);

        uint32_t sa = sbase + (uint32_t)(c % 3) * STAGE_BYTES;
        uint32_t sb = sa + 16384u;
#pragma unroll
        for (int ks = 0; ks < 4; ks++) {
            uint4 af[4]; uint2 bf[8];
            int kq = ks * 2 + lsel;
#pragma unroll
            for (int mf = 0; mf < 4; mf++) {
                int row = wm * 64 + mf * 16 + lrow;
                ldsm_x4(af[mf], sa + (uint32_t)(row * 8 + (kq ^ (row & 7))) * 16);
            }
            int kb = ks * 16 + lrow;
#pragma unroll
            for (int np = 0; np < 4; np++) {
                int nq = (wn * 4 + np) * 2 + lsel;
                uint4 bb;
                ldsm_x4t(bb, sb + (uint32_t)(kb * 16 + (nq ^ (kb & 7))) * 16);
                bf[2 * np].x     = bb.x; bf[2 * np].y     = bb.y;
                bf[2 * np + 1].x = bb.z; bf[2 * np + 1].y = bb.w;
            }
#pragma unroll
            for (int mf = 0; mf < 4; mf++)
#pragma unroll
                for (int nf = 0; nf < 8; nf++)
                    mma_f16(acc[mf][nf], af[mf], bf[nf]);
        }
        __syncthreads();
    }

    // ---- epilogue ----
#pragma unroll
    for (int mf = 0; mf < 4; mf++) {
        int r0 = m0 + wm * 64 + mf * 16 + (lane >> 2);
        int r1 = r0 + 8;
        bool v0 = r0 < cnt, v1 = r1 < cnt;
        int s0 = v0 ? g_slot[e * MAX_T + r0] : 0;
        int s1 = v1 ? g_slot[e * MAX_T + r1] : 0;
#pragma unroll
        for (int nf = 0; nf < 8; nf++) {
            int col = n0 + wn * 64 + nf * 8 + (lane & 3) * 2;
            float2 bb = *(const float2*)&bias[(size_t)e * NG + col];
            float x0 = acc[mf][nf][0] + bb.x, x1 = acc[mf][nf][1] + bb.y;
            float x2 = acc[mf][nf][2] + bb.x, x3 = acc[mf][nf][3] + bb.y;
            if (G1) {
                x0 = fmaxf(x0, 0.f); x1 = fmaxf(x1, 0.f);
                x2 = fmaxf(x2, 0.f); x3 = fmaxf(x3, 0.f);
                __half* Out = (__half*)OutV;
                if (v0) {
                    __half2 hv = __floats2half2_rn(x0, x1);
                    *(__half2*)(Out + (size_t)s0 * NG + col) = hv;
                }
                if (v1) {
                    __half2 hv = __floats2half2_rn(x2, x3);
                    *(__half2*)(Out + (size_t)s1 * NG + col) = hv;
                }
            } else {
                float* Out = (float*)OutV;
                if (v0) { float2 o; o.x = x0; o.y = x1;
                          *(float2*)(Out + (size_t)s0 * NG + col) = o; }
                if (v1) { float2 o; o.x = x2; o.y = x3;
                          *(float2*)(Out + (size_t)s1 * NG + col) = o; }
            }
        }
    }
}

// out[t] = p0*y[2t] + p1*y[2t+1]
__global__ void __launch_bounds__(256) combine_kernel(float* __restrict__ out, int T)
{
    int idx = blockIdx.x * 256 + threadIdx.x;
    int total = T * (D_DIM / 4);
    if (idx >= total) return;
    int t  = idx / (D_DIM / 4);
    int c4 = idx % (D_DIM / 4);
    float4 a = ((const float4*)(g_y + (size_t)(2 * t) * D_DIM))[c4];
    float4 b = ((const float4*)(g_y + (size_t)(2 * t + 1) * D_DIM))[c4];
    float p0 = g_pslot[2 * t], p1 = g_pslot[2 * t + 1];
    float4 o;
    o.x = p0 * a.x + p1 * b.x;
    o.y = p0 * a.y + p1 * b.y;
    o.z = p0 * a.z + p1 * b.z;
    o.w = p0 * a.w + p1 * b.w;
    ((float4*)out)[idx] = o;
}

extern "C" void kernel_launch(void* const* d_in, const int* in_sizes, int n_in,
                              void* d_out, int out_size)
{
    const float* x     = (const float*)d_in[0];
    const float* noise = (const float*)d_in[1];
    const float* Wg    = (const float*)d_in[2];
    const float* bg    = (const float*)d_in[3];
    const float* Wn    = (const float*)d_in[4];
    const float* bn    = (const float*)d_in[5];
    const float* W1    = (const float*)d_in[6];
    const float* b1    = (const float*)d_in[7];
    const float* W2    = (const float*)d_in[8];
    const float* b2    = (const float*)d_in[9];
    float* out = (float*)d_out;

    int T = in_sizes[0] / D_DIM;
    if (T > MAX_T) T = MAX_T;

    cudaFuncSetAttribute(moe_gemm<true>,
                         cudaFuncAttributeMaxDynamicSharedMemorySize, SM_BYTES);
    cudaFuncSetAttribute(moe_gemm<false>,
                         cudaFuncAttributeMaxDynamicSharedMemorySize, SM_BYTES);

    __half *xh = nullptr, *hid = nullptr, *w1h = nullptr, *w2h = nullptr;
    float* yv = nullptr;
    cudaGetSymbolAddress((void**)&xh,  g_xh);
    cudaGetSymbolAddress((void**)&hid, g_hid);
    cudaGetSymbolAddress((void**)&w1h, g_w1h);
    cudaGetSymbolAddress((void**)&w2h, g_w2h);
    cudaGetSymbolAddress((void**)&yv,  g_y);

    zero_counts_kernel<<<1, 32>>>();

    int nx = T * D_DIM / 8;
    convert_f2h<<<(nx + 255) / 256, 256>>>(x, xh, nx);
    int nw = E_NUM * D_DIM * H_DIM / 8;
    convert_f2h<<<(nw + 255) / 256, 256>>>(W1, w1h, nw);
    convert_f2h<<<(nw + 255) / 256, 256>>>(W2, w2h, nw);

    route_kernel<<<T, 256>>>(x, noise, Wg, bg, Wn, bn);

    int mt = (T + 127) / 128;
    moe_gemm<true ><<<dim3(H_DIM / 128, mt, E_NUM), 128, SM_BYTES>>>(xh,  w1h, b1, hid);
    moe_gemm<false><<<dim3(D_DIM / 128, mt, E_NUM), 128, SM_BYTES>>>(hid, w2h, b2, yv);

    combine_kernel<<<(T * (D_DIM / 4) + 255) / 256, 256>>>(out, T);
}

// round 9
// speedup vs baseline: 7.5977x; 1.0008x over previous
#include <cuda_runtime.h>
#include <cuda_fp16.h>
#include <cstdint>

#define D_DIM 768
#define H_DIM 3072
#define E_NUM 8
#define MAX_T 4096

// ---------------- device scratch ----------------
__device__ int    g_counts[E_NUM];
__device__ int    g_tok [E_NUM * MAX_T];
__device__ int    g_slot[E_NUM * MAX_T];
__device__ float  g_pslot[2 * MAX_T];
__device__ __half g_xh [(size_t)MAX_T * D_DIM];
__device__ __half g_hid[(size_t)2 * MAX_T * H_DIM];
__device__ float  g_y  [(size_t)2 * MAX_T * D_DIM];   // split-K half 0 (+bias)
__device__ float  g_y2 [(size_t)2 * MAX_T * D_DIM];   // split-K half 1
__device__ __half g_w1h[(size_t)E_NUM * D_DIM * H_DIM];
__device__ __half g_w2h[(size_t)E_NUM * H_DIM * D_DIM];

// ---------------- PTX helpers ----------------
__device__ __forceinline__ uint32_t smem_u32(const void* p) {
    uint32_t r;
    asm("{ .reg .u64 t; cvta.to.shared.u64 t, %1; cvt.u32.u64 %0, t; }"
        : "=r"(r) : "l"(p));
    return r;
}
__device__ __forceinline__ void mma_f16(float* d, const uint4& a, const uint2& b) {
    asm volatile(
        "mma.sync.aligned.m16n8k16.row.col.f32.f16.f16.f32 "
        "{%0,%1,%2,%3}, {%4,%5,%6,%7}, {%8,%9}, {%0,%1,%2,%3};"
        : "+f"(d[0]), "+f"(d[1]), "+f"(d[2]), "+f"(d[3])
        : "r"(a.x), "r"(a.y), "r"(a.z), "r"(a.w), "r"(b.x), "r"(b.y));
}
__device__ __forceinline__ void ldsm_x4(uint4& r, uint32_t addr) {
    asm volatile("ldmatrix.sync.aligned.m8n8.x4.shared.b16 {%0,%1,%2,%3}, [%4];"
                 : "=r"(r.x), "=r"(r.y), "=r"(r.z), "=r"(r.w) : "r"(addr));
}
__device__ __forceinline__ void ldsm_x4t(uint4& r, uint32_t addr) {
    asm volatile("ldmatrix.sync.aligned.m8n8.x4.trans.shared.b16 {%0,%1,%2,%3}, [%4];"
                 : "=r"(r.x), "=r"(r.y), "=r"(r.z), "=r"(r.w) : "r"(addr));
}
__device__ __forceinline__ void cp16(uint32_t dst, const void* src, uint32_t sz) {
    asm volatile("cp.async.cg.shared.global [%0], [%1], 16, %2;"
                 :: "r"(dst), "l"(src), "r"(sz) : "memory");
}
__device__ __forceinline__ void cp_commit() {
    asm volatile("cp.async.commit_group;" ::: "memory");
}
__device__ __forceinline__ void cp_wait1() {
    asm volatile("cp.async.wait_group 1;" ::: "memory");
}

// ---------------- fp32 -> fp16 convert ----------------
__global__ void __launch_bounds__(256) convert_f2h(
    const float* __restrict__ src, __half* __restrict__ dst, int n8)
{
    int i = blockIdx.x * 256 + threadIdx.x;
    if (i >= n8) return;
    const float4* s = (const float4*)src + 2 * (size_t)i;
    float4 a = s[0], b = s[1];
    __half2 h0 = __floats2half2_rn(a.x, a.y);
    __half2 h1 = __floats2half2_rn(a.z, a.w);
    __half2 h2 = __floats2half2_rn(b.x, b.y);
    __half2 h3 = __floats2half2_rn(b.z, b.w);
    uint4 o;
    o.x = *(uint32_t*)&h0; o.y = *(uint32_t*)&h1;
    o.z = *(uint32_t*)&h2; o.w = *(uint32_t*)&h3;
    ((uint4*)dst)[i] = o;
}

// ---------------- routing ----------------
__global__ void zero_counts_kernel() {
    if (threadIdx.x < E_NUM) g_counts[threadIdx.x] = 0;
}

__global__ void __launch_bounds__(256) route_kernel(
    const float* __restrict__ x, const float* __restrict__ noise,
    const float* __restrict__ Wg, const float* __restrict__ bg,
    const float* __restrict__ Wn, const float* __restrict__ bn)
{
    int t = blockIdx.x, tid = threadIdx.x;
    float pg[E_NUM], pn[E_NUM];
#pragma unroll
    for (int e = 0; e < E_NUM; e++) { pg[e] = 0.f; pn[e] = 0.f; }
    const float* xr = x + (size_t)t * D_DIM;
    for (int d = tid; d < D_DIM; d += 256) {
        float xv = xr[d];
#pragma unroll
        for (int e = 0; e < E_NUM; e++) {
            pg[e] = fmaf(xv, Wg[d * E_NUM + e], pg[e]);
            pn[e] = fmaf(xv, Wn[d * E_NUM + e], pn[e]);
        }
    }
#pragma unroll
    for (int e = 0; e < E_NUM; e++)
#pragma unroll
        for (int o = 16; o > 0; o >>= 1) {
            pg[e] += __shfl_down_sync(0xffffffffu, pg[e], o);
            pn[e] += __shfl_down_sync(0xffffffffu, pn[e], o);
        }
    __shared__ float sg[8][E_NUM], sn[8][E_NUM];
    int w = tid >> 5, l = tid & 31;
    if (l == 0)
#pragma unroll
        for (int e = 0; e < E_NUM; e++) { sg[w][e] = pg[e]; sn[w][e] = pn[e]; }
    __syncthreads();

    if (tid == 0) {
        float h[E_NUM];
#pragma unroll
        for (int e = 0; e < E_NUM; e++) {
            float a = bg[e], b = bn[e];
#pragma unroll
            for (int ww = 0; ww < 8; ww++) { a += sg[ww][e]; b += sn[ww][e]; }
            float sp = fmaxf(b, 0.f) + log1pf(expf(-fabsf(b)));
            h[e] = a + noise[(size_t)t * E_NUM + e] * sp;
        }
        int i0 = 0;
#pragma unroll
        for (int e = 1; e < E_NUM; e++) if (h[e] > h[i0]) i0 = e;
        int i1 = (i0 == 0) ? 1 : 0;
#pragma unroll
        for (int e = 0; e < E_NUM; e++) if (e != i0 && h[e] > h[i1]) i1 = e;

        float p0 = 1.f / (1.f + expf(h[i1] - h[i0]));
        float p1 = 1.f - p0;
        g_pslot[2 * t]     = p0;
        g_pslot[2 * t + 1] = p1;

        int s0 = atomicAdd(&g_counts[i0], 1);
        g_tok [i0 * MAX_T + s0] = t;
        g_slot[i0 * MAX_T + s0] = 2 * t;
        int s1 = atomicAdd(&g_counts[i1], 1);
        g_tok [i1 * MAX_T + s1] = t;
        g_slot[i1 * MAX_T + s1] = 2 * t + 1;
    }
}

// ---------------- grouped fp16 GEMM ----------------
// 128 threads (4 warps 2x2), BM=128, BN=128, BK=64, 3-stage cp.async ring.
// 2 CTAs/SM. GEMM2 (!G1) is split-K=2: blockIdx.z = half*8 + e; half 0
// writes acc+bias to g_y, half 1 writes raw acc to g_y2.
#define STAGE_BYTES 32768
#define SM_BYTES (3 * STAGE_BYTES)   // 98304 per CTA

template <bool G1>
__global__ void __launch_bounds__(128) moe_gemm(
    const __half* __restrict__ Ah, const __half* __restrict__ Wh,
    const float* __restrict__ bias, void* __restrict__ OutV,
    float* __restrict__ Out2)
{
    constexpr int KTOT  = G1 ? D_DIM : H_DIM;
    constexpr int KSPAN = G1 ? D_DIM : (H_DIM / 2);
    constexpr int NG    = G1 ? H_DIM : D_DIM;
    constexpr int NC    = KSPAN / 64;

    int z    = blockIdx.z;
    int e    = G1 ? z : (z & 7);
    int half = G1 ? 0 : (z >> 3);
    int cnt  = g_counts[e];
    int m0   = blockIdx.y * 128;
    if (m0 >= cnt) return;
    int n0   = blockIdx.x * 128;
    size_t kbase = (size_t)half * KSPAN;

    extern __shared__ char smem[];
    uint32_t sbase = smem_u32(smem);

    int tid = threadIdx.x, wid = tid >> 5, lane = tid & 31;
    int wm = wid >> 1, wn = wid & 1;
    const int* idxarr = G1 ? g_tok : g_slot;

    // ---- cp.async plans ----
    int ar0 = tid >> 3, akq = tid & 7;
    uint32_t a_dst0 = (uint32_t)(ar0 * 8 + (akq ^ (ar0 & 7))) * 16;
    const __half* a_src[8]; uint32_t a_sz[8];
#pragma unroll
    for (int i = 0; i < 8; i++) {
        int gr = m0 + ar0 + 16 * i;
        if (gr < cnt) {
            a_src[i] = Ah + (size_t)idxarr[e * MAX_T + gr] * KTOT + kbase + akq * 8;
            a_sz[i] = 16;
        } else { a_src[i] = Ah; a_sz[i] = 0; }
    }
    int bk0 = tid >> 4, bnq = tid & 15;
    const __half* b_src = Wh + (size_t)e * KTOT * NG + (kbase + bk0) * NG
                        + n0 + bnq * 8;
    uint32_t b_dst0 = 16384u + (uint32_t)(bk0 * 16 + (bnq ^ (bk0 & 7))) * 16;

    auto issue = [&](int c) {
        if (c < NC) {
            uint32_t sa = sbase + (uint32_t)(c % 3) * STAGE_BYTES;
#pragma unroll
            for (int i = 0; i < 8; i++)
                cp16(sa + a_dst0 + (uint32_t)i * 2048,
                     a_src[i] + (size_t)c * 64, a_sz[i]);
            const __half* bs = b_src + (size_t)c * 64 * NG;
#pragma unroll
            for (int j = 0; j < 8; j++)
                cp16(sa + b_dst0 + (uint32_t)j * 2048,
                     bs + (size_t)(8 * j) * NG, 16);
        }
        cp_commit();
    };

    issue(0); issue(1);

    int lrow = (lane & 7) + 8 * ((lane >> 3) & 1);
    int lsel = lane >> 4;

    float acc[4][8][4];
#pragma unroll
    for (int a = 0; a < 4; a++)
#pragma unroll
        for (int b = 0; b < 8; b++)
#pragma unroll
            for (int k = 0; k < 4; k++) acc[a][b][k] = 0.f;

#pragma unroll 1
    for (int c = 0; c < NC; c++) {
        cp_wait1();
        __syncthreads();
        issue(c + 2);

        uint32_t sa = sbase + (uint32_t)(c % 3) * STAGE_BYTES;
        uint32_t sb = sa + 16384u;
#pragma unroll
        for (int ks = 0; ks < 4; ks++) {
            uint4 af[4]; uint2 bf[8];
            int kq = ks * 2 + lsel;
#pragma unroll
            for (int mf = 0; mf < 4; mf++) {
                int row = wm * 64 + mf * 16 + lrow;
                ldsm_x4(af[mf], sa + (uint32_t)(row * 8 + (kq ^ (row & 7))) * 16);
            }
            int kb = ks * 16 + lrow;
#pragma unroll
            for (int np = 0; np < 4; np++) {
                int nq = (wn * 4 + np) * 2 + lsel;
                uint4 bb;
                ldsm_x4t(bb, sb + (uint32_t)(kb * 16 + (nq ^ (kb & 7))) * 16);
                bf[2 * np].x     = bb.x; bf[2 * np].y     = bb.y;
                bf[2 * np + 1].x = bb.z; bf[2 * np + 1].y = bb.w;
            }
#pragma unroll
            for (int mf = 0; mf < 4; mf++)
#pragma unroll
                for (int nf = 0; nf < 8; nf++)
                    mma_f16(acc[mf][nf], af[mf], bf[nf]);
        }
        __syncthreads();
    }

    // ---- epilogue ----
#pragma unroll
    for (int mf = 0; mf < 4; mf++) {
        int r0 = m0 + wm * 64 + mf * 16 + (lane >> 2);
        int r1 = r0 + 8;
        bool v0 = r0 < cnt, v1 = r1 < cnt;
        int s0 = v0 ? g_slot[e * MAX_T + r0] : 0;
        int s1 = v1 ? g_slot[e * MAX_T + r1] : 0;
#pragma unroll
        for (int nf = 0; nf < 8; nf++) {
            int col = n0 + wn * 64 + nf * 8 + (lane & 3) * 2;
            float x0 = acc[mf][nf][0], x1 = acc[mf][nf][1];
            float x2 = acc[mf][nf][2], x3 = acc[mf][nf][3];
            if (G1 || half == 0) {
                float2 bb = *(const float2*)&bias[(size_t)e * NG + col];
                x0 += bb.x; x1 += bb.y; x2 += bb.x; x3 += bb.y;
            }
            if (G1) {
                x0 = fmaxf(x0, 0.f); x1 = fmaxf(x1, 0.f);
                x2 = fmaxf(x2, 0.f); x3 = fmaxf(x3, 0.f);
                __half* Out = (__half*)OutV;
                if (v0) {
                    __half2 hv = __floats2half2_rn(x0, x1);
                    *(__half2*)(Out + (size_t)s0 * NG + col) = hv;
                }
                if (v1) {
                    __half2 hv = __floats2half2_rn(x2, x3);
                    *(__half2*)(Out + (size_t)s1 * NG + col) = hv;
                }
            } else {
                float* Out = half ? Out2 : (float*)OutV;
                if (v0) { float2 o; o.x = x0; o.y = x1;
                          *(float2*)(Out + (size_t)s0 * NG + col) = o; }
                if (v1) { float2 o; o.x = x2; o.y = x3;
                          *(float2*)(Out + (size_t)s1 * NG + col) = o; }
            }
        }
    }
}

// out[t] = p0*(y[2t]+y2[2t]) + p1*(y[2t+1]+y2[2t+1])
__global__ void __launch_bounds__(256) combine_kernel(float* __restrict__ out, int T)
{
    int idx = blockIdx.x * 256 + threadIdx.x;
    int total = T * (D_DIM / 4);
    if (idx >= total) return;
    int t  = idx / (D_DIM / 4);
    int c4 = idx % (D_DIM / 4);
    float4 a0 = ((const float4*)(g_y  + (size_t)(2 * t) * D_DIM))[c4];
    float4 a1 = ((const float4*)(g_y2 + (size_t)(2 * t) * D_DIM))[c4];
    float4 b0 = ((const float4*)(g_y  + (size_t)(2 * t + 1) * D_DIM))[c4];
    float4 b1 = ((const float4*)(g_y2 + (size_t)(2 * t + 1) * D_DIM))[c4];
    float p0 = g_pslot[2 * t], p1 = g_pslot[2 * t + 1];
    float4 o;
    o.x = p0 * (a0.x + a1.x) + p1 * (b0.x + b1.x);
    o.y = p0 * (a0.y + a1.y) + p1 * (b0.y + b1.y);
    o.z = p0 * (a0.z + a1.z) + p1 * (b0.z + b1.z);
    o.w = p0 * (a0.w + a1.w) + p1 * (b0.w + b1.w);
    ((float4*)out)[idx] = o;
}

extern "C" void kernel_launch(void* const* d_in, const int* in_sizes, int n_in,
                              void* d_out, int out_size)
{
    const float* x     = (const float*)d_in[0];
    const float* noise = (const float*)d_in[1];
    const float* Wg    = (const float*)d_in[2];
    const float* bg    = (const float*)d_in[3];
    const float* Wn    = (const float*)d_in[4];
    const float* bn    = (const float*)d_in[5];
    const float* W1    = (const float*)d_in[6];
    const float* b1    = (const float*)d_in[7];
    const float* W2    = (const float*)d_in[8];
    const float* b2    = (const float*)d_in[9];
    float* out = (float*)d_out;

    int T = in_sizes[0] / D_DIM;
    if (T > MAX_T) T = MAX_T;

    cudaFuncSetAttribute(moe_gemm<true>,
                         cudaFuncAttributeMaxDynamicSharedMemorySize, SM_BYTES);
    cudaFuncSetAttribute(moe_gemm<false>,
                         cudaFuncAttributeMaxDynamicSharedMemorySize, SM_BYTES);

    __half *xh = nullptr, *hid = nullptr, *w1h = nullptr, *w2h = nullptr;
    float *yv = nullptr, *yv2 = nullptr;
    cudaGetSymbolAddress((void**)&xh,  g_xh);
    cudaGetSymbolAddress((void**)&hid, g_hid);
    cudaGetSymbolAddress((void**)&w1h, g_w1h);
    cudaGetSymbolAddress((void**)&w2h, g_w2h);
    cudaGetSymbolAddress((void**)&yv,  g_y);
    cudaGetSymbolAddress((void**)&yv2, g_y2);

    zero_counts_kernel<<<1, 32>>>();

    int nx = T * D_DIM / 8;
    convert_f2h<<<(nx + 255) / 256, 256>>>(x, xh, nx);
    int nw = E_NUM * D_DIM * H_DIM / 8;
    convert_f2h<<<(nw + 255) / 256, 256>>>(W1, w1h, nw);
    convert_f2h<<<(nw + 255) / 256, 256>>>(W2, w2h, nw);

    route_kernel<<<T, 256>>>(x, noise, Wg, bg, Wn, bn);

    int mt = (T + 127) / 128;
    moe_gemm<true ><<<dim3(H_DIM / 128, mt, E_NUM), 128, SM_BYTES>>>(
        xh, w1h, b1, hid, nullptr);
    moe_gemm<false><<<dim3(D_DIM / 128, mt, E_NUM * 2), 128, SM_BYTES>>>(
        hid, w2h, b2, yv, yv2);

    combine_kernel<<<(T * (D_DIM / 4) + 255) / 256, 256>>>(out, T);
}

// round 10
// speedup vs baseline: 7.8173x; 1.0289x over previous
#include <cuda_runtime.h>
#include <cuda_fp16.h>
#include <cstdint>

#define D_DIM 768
#define H_DIM 3072
#define E_NUM 8
#define MAX_T 4096

// ---------------- device scratch ----------------
__device__ int    g_counts[E_NUM];
__device__ int    g_tok [E_NUM * MAX_T];
__device__ int    g_slot[E_NUM * MAX_T];
__device__ float  g_pslot[2 * MAX_T];
__device__ __half g_xh [(size_t)MAX_T * D_DIM];
__device__ __half g_hid[(size_t)2 * MAX_T * H_DIM];
__device__ float  g_y  [(size_t)2 * MAX_T * D_DIM];   // split-K half 0 (+bias)
__device__ float  g_y2 [(size_t)2 * MAX_T * D_DIM];   // split-K half 1
__device__ __half g_w1h[(size_t)E_NUM * D_DIM * H_DIM];
__device__ __half g_w2h[(size_t)E_NUM * H_DIM * D_DIM];

// ---------------- PTX helpers ----------------
__device__ __forceinline__ uint32_t smem_u32(const void* p) {
    uint32_t r;
    asm("{ .reg .u64 t; cvta.to.shared.u64 t, %1; cvt.u32.u64 %0, t; }"
        : "=r"(r) : "l"(p));
    return r;
}
__device__ __forceinline__ void mma_f16(float* d, const uint4& a, const uint2& b) {
    asm volatile(
        "mma.sync.aligned.m16n8k16.row.col.f32.f16.f16.f32 "
        "{%0,%1,%2,%3}, {%4,%5,%6,%7}, {%8,%9}, {%0,%1,%2,%3};"
        : "+f"(d[0]), "+f"(d[1]), "+f"(d[2]), "+f"(d[3])
        : "r"(a.x), "r"(a.y), "r"(a.z), "r"(a.w), "r"(b.x), "r"(b.y));
}
__device__ __forceinline__ void ldsm_x4(uint4& r, uint32_t addr) {
    asm volatile("ldmatrix.sync.aligned.m8n8.x4.shared.b16 {%0,%1,%2,%3}, [%4];"
                 : "=r"(r.x), "=r"(r.y), "=r"(r.z), "=r"(r.w) : "r"(addr));
}
__device__ __forceinline__ void ldsm_x4t(uint4& r, uint32_t addr) {
    asm volatile("ldmatrix.sync.aligned.m8n8.x4.trans.shared.b16 {%0,%1,%2,%3}, [%4];"
                 : "=r"(r.x), "=r"(r.y), "=r"(r.z), "=r"(r.w) : "r"(addr));
}
__device__ __forceinline__ void cp16(uint32_t dst, const void* src, uint32_t sz) {
    asm volatile("cp.async.cg.shared.global [%0], [%1], 16, %2;"
                 :: "r"(dst), "l"(src), "r"(sz) : "memory");
}
__device__ __forceinline__ void cp_commit() {
    asm volatile("cp.async.commit_group;" ::: "memory");
}
__device__ __forceinline__ void cp_wait1() {
    asm volatile("cp.async.wait_group 1;" ::: "memory");
}

// ---------------- fp32 -> fp16 convert ----------------
__global__ void __launch_bounds__(256) convert_f2h(
    const float* __restrict__ src, __half* __restrict__ dst, int n8)
{
    int i = blockIdx.x * 256 + threadIdx.x;
    if (i >= n8) return;
    const float4* s = (const float4*)src + 2 * (size_t)i;
    float4 a = s[0], b = s[1];
    __half2 h0 = __floats2half2_rn(a.x, a.y);
    __half2 h1 = __floats2half2_rn(a.z, a.w);
    __half2 h2 = __floats2half2_rn(b.x, b.y);
    __half2 h3 = __floats2half2_rn(b.z, b.w);
    uint4 o;
    o.x = *(uint32_t*)&h0; o.y = *(uint32_t*)&h1;
    o.z = *(uint32_t*)&h2; o.w = *(uint32_t*)&h3;
    ((uint4*)dst)[i] = o;
}

// ---------------- routing (also emits x as fp16) ----------------
__global__ void zero_counts_kernel() {
    if (threadIdx.x < E_NUM) g_counts[threadIdx.x] = 0;
}

__global__ void __launch_bounds__(256) route_kernel(
    const float* __restrict__ x, const float* __restrict__ noise,
    const float* __restrict__ Wg, const float* __restrict__ bg,
    const float* __restrict__ Wn, const float* __restrict__ bn)
{
    int t = blockIdx.x, tid = threadIdx.x;
    float pg[E_NUM], pn[E_NUM];
#pragma unroll
    for (int e = 0; e < E_NUM; e++) { pg[e] = 0.f; pn[e] = 0.f; }
    const float* xr = x + (size_t)t * D_DIM;
    for (int d = tid; d < D_DIM; d += 256) {
        float xv = xr[d];
        g_xh[(size_t)t * D_DIM + d] = __float2half_rn(xv);
#pragma unroll
        for (int e = 0; e < E_NUM; e++) {
            pg[e] = fmaf(xv, Wg[d * E_NUM + e], pg[e]);
            pn[e] = fmaf(xv, Wn[d * E_NUM + e], pn[e]);
        }
    }
#pragma unroll
    for (int e = 0; e < E_NUM; e++)
#pragma unroll
        for (int o = 16; o > 0; o >>= 1) {
            pg[e] += __shfl_down_sync(0xffffffffu, pg[e], o);
            pn[e] += __shfl_down_sync(0xffffffffu, pn[e], o);
        }
    __shared__ float sg[8][E_NUM], sn[8][E_NUM];
    int w = tid >> 5, l = tid & 31;
    if (l == 0)
#pragma unroll
        for (int e = 0; e < E_NUM; e++) { sg[w][e] = pg[e]; sn[w][e] = pn[e]; }
    __syncthreads();

    if (tid == 0) {
        float h[E_NUM];
#pragma unroll
        for (int e = 0; e < E_NUM; e++) {
            float a = bg[e], b = bn[e];
#pragma unroll
            for (int ww = 0; ww < 8; ww++) { a += sg[ww][e]; b += sn[ww][e]; }
            float sp = fmaxf(b, 0.f) + log1pf(expf(-fabsf(b)));
            h[e] = a + noise[(size_t)t * E_NUM + e] * sp;
        }
        int i0 = 0;
#pragma unroll
        for (int e = 1; e < E_NUM; e++) if (h[e] > h[i0]) i0 = e;
        int i1 = (i0 == 0) ? 1 : 0;
#pragma unroll
        for (int e = 0; e < E_NUM; e++) if (e != i0 && h[e] > h[i1]) i1 = e;

        float p0 = 1.f / (1.f + expf(h[i1] - h[i0]));
        float p1 = 1.f - p0;
        g_pslot[2 * t]     = p0;
        g_pslot[2 * t + 1] = p1;

        int s0 = atomicAdd(&g_counts[i0], 1);
        g_tok [i0 * MAX_T + s0] = t;
        g_slot[i0 * MAX_T + s0] = 2 * t;
        int s1 = atomicAdd(&g_counts[i1], 1);
        g_tok [i1 * MAX_T + s1] = t;
        g_slot[i1 * MAX_T + s1] = 2 * t + 1;
    }
}

// ---------------- grouped fp16 GEMM ----------------
// 128 threads (4 warps 2x2), BM=128, BN=128, BK=64, 3-stage cp.async ring.
// 2 CTAs/SM. GEMM2 (!G1) is split-K=2: blockIdx.z = half*8 + e.
#define STAGE_BYTES 32768
#define SM_BYTES (3 * STAGE_BYTES)   // 98304 per CTA

template <bool G1>
__global__ void __launch_bounds__(128) moe_gemm(
    const __half* __restrict__ Ah, const __half* __restrict__ Wh,
    const float* __restrict__ bias, void* __restrict__ OutV,
    float* __restrict__ Out2)
{
    constexpr int KTOT  = G1 ? D_DIM : H_DIM;
    constexpr int KSPAN = G1 ? D_DIM : (H_DIM / 2);
    constexpr int NG    = G1 ? H_DIM : D_DIM;
    constexpr int NC    = KSPAN / 64;

    int z    = blockIdx.z;
    int e    = G1 ? z : (z & 7);
    int half = G1 ? 0 : (z >> 3);
    int cnt  = g_counts[e];
    int m0   = blockIdx.y * 128;
    if (m0 >= cnt) return;
    int n0   = blockIdx.x * 128;
    size_t kbase = (size_t)half * KSPAN;

    extern __shared__ char smem[];
    uint32_t sbase = smem_u32(smem);

    int tid = threadIdx.x, wid = tid >> 5, lane = tid & 31;
    int wm = wid >> 1, wn = wid & 1;
    const int* idxarr = G1 ? g_tok : g_slot;

    // ---- cp.async plans ----
    int ar0 = tid >> 3, akq = tid & 7;
    uint32_t a_dst0 = (uint32_t)(ar0 * 8 + (akq ^ (ar0 & 7))) * 16;
    const __half* a_src[8]; uint32_t a_sz[8];
#pragma unroll
    for (int i = 0; i < 8; i++) {
        int gr = m0 + ar0 + 16 * i;
        if (gr < cnt) {
            a_src[i] = Ah + (size_t)idxarr[e * MAX_T + gr] * KTOT + kbase + akq * 8;
            a_sz[i] = 16;
        } else { a_src[i] = Ah; a_sz[i] = 0; }
    }
    int bk0 = tid >> 4, bnq = tid & 15;
    const __half* b_src = Wh + (size_t)e * KTOT * NG + (kbase + bk0) * NG
                        + n0 + bnq * 8;
    uint32_t b_dst0 = 16384u + (uint32_t)(bk0 * 16 + (bnq ^ (bk0 & 7))) * 16;

    auto issue = [&](int c) {
        if (c < NC) {
            uint32_t sa = sbase + (uint32_t)(c % 3) * STAGE_BYTES;
#pragma unroll
            for (int i = 0; i < 8; i++)
                cp16(sa + a_dst0 + (uint32_t)i * 2048,
                     a_src[i] + (size_t)c * 64, a_sz[i]);
            const __half* bs = b_src + (size_t)c * 64 * NG;
#pragma unroll
            for (int j = 0; j < 8; j++)
                cp16(sa + b_dst0 + (uint32_t)j * 2048,
                     bs + (size_t)(8 * j) * NG, 16);
        }
        cp_commit();
    };

    issue(0); issue(1);

    int lrow = (lane & 7) + 8 * ((lane >> 3) & 1);
    int lsel = lane >> 4;

    float acc[4][8][4];
#pragma unroll
    for (int a = 0; a < 4; a++)
#pragma unroll
        for (int b = 0; b < 8; b++)
#pragma unroll
            for (int k = 0; k < 4; k++) acc[a][b][k] = 0.f;

#pragma unroll 1
    for (int c = 0; c < NC; c++) {
        cp_wait1();
        __syncthreads();
        issue(c + 2);

        uint32_t sa = sbase + (uint32_t)(c % 3) * STAGE_BYTES;
        uint32_t sb = sa + 16384u;
#pragma unroll
        for (int ks = 0; ks < 4; ks++) {
            uint4 af[4]; uint2 bf[8];
            int kq = ks * 2 + lsel;
#pragma unroll
            for (int mf = 0; mf < 4; mf++) {
                int row = wm * 64 + mf * 16 + lrow;
                ldsm_x4(af[mf], sa + (uint32_t)(row * 8 + (kq ^ (row & 7))) * 16);
            }
            int kb = ks * 16 + lrow;
#pragma unroll
            for (int np = 0; np < 4; np++) {
                int nq = (wn * 4 + np) * 2 + lsel;
                uint4 bb;
                ldsm_x4t(bb, sb + (uint32_t)(kb * 16 + (nq ^ (kb & 7))) * 16);
                bf[2 * np].x     = bb.x; bf[2 * np].y     = bb.y;
                bf[2 * np + 1].x = bb.z; bf[2 * np + 1].y = bb.w;
            }
#pragma unroll
            for (int mf = 0; mf < 4; mf++)
#pragma unroll
                for (int nf = 0; nf < 8; nf++)
                    mma_f16(acc[mf][nf], af[mf], bf[nf]);
        }
        __syncthreads();
    }

    // ---- epilogue ----
#pragma unroll
    for (int mf = 0; mf < 4; mf++) {
        int r0 = m0 + wm * 64 + mf * 16 + (lane >> 2);
        int r1 = r0 + 8;
        bool v0 = r0 < cnt, v1 = r1 < cnt;
        int s0 = v0 ? g_slot[e * MAX_T + r0] : 0;
        int s1 = v1 ? g_slot[e * MAX_T + r1] : 0;
#pragma unroll
        for (int nf = 0; nf < 8; nf++) {
            int col = n0 + wn * 64 + nf * 8 + (lane & 3) * 2;
            float x0 = acc[mf][nf][0], x1 = acc[mf][nf][1];
            float x2 = acc[mf][nf][2], x3 = acc[mf][nf][3];
            if (G1 || half == 0) {
                float2 bb = *(const float2*)&bias[(size_t)e * NG + col];
                x0 += bb.x; x1 += bb.y; x2 += bb.x; x3 += bb.y;
            }
            if (G1) {
                x0 = fmaxf(x0, 0.f); x1 = fmaxf(x1, 0.f);
                x2 = fmaxf(x2, 0.f); x3 = fmaxf(x3, 0.f);
                __half* Out = (__half*)OutV;
                if (v0) {
                    __half2 hv = __floats2half2_rn(x0, x1);
                    *(__half2*)(Out + (size_t)s0 * NG + col) = hv;
                }
                if (v1) {
                    __half2 hv = __floats2half2_rn(x2, x3);
                    *(__half2*)(Out + (size_t)s1 * NG + col) = hv;
                }
            } else {
                float* Out = half ? Out2 : (float*)OutV;
                if (v0) { float2 o; o.x = x0; o.y = x1;
                          *(float2*)(Out + (size_t)s0 * NG + col) = o; }
                if (v1) { float2 o; o.x = x2; o.y = x3;
                          *(float2*)(Out + (size_t)s1 * NG + col) = o; }
            }
        }
    }
}

// out[t] = p0*(y[2t]+y2[2t]) + p1*(y[2t+1]+y2[2t+1])
__global__ void __launch_bounds__(256) combine_kernel(float* __restrict__ out, int T)
{
    int idx = blockIdx.x * 256 + threadIdx.x;
    int total = T * (D_DIM / 4);
    if (idx >= total) return;
    int t  = idx / (D_DIM / 4);
    int c4 = idx % (D_DIM / 4);
    float4 a0 = ((const float4*)(g_y  + (size_t)(2 * t) * D_DIM))[c4];
    float4 a1 = ((const float4*)(g_y2 + (size_t)(2 * t) * D_DIM))[c4];
    float4 b0 = ((const float4*)(g_y  + (size_t)(2 * t + 1) * D_DIM))[c4];
    float4 b1 = ((const float4*)(g_y2 + (size_t)(2 * t + 1) * D_DIM))[c4];
    float p0 = g_pslot[2 * t], p1 = g_pslot[2 * t + 1];
    float4 o;
    o.x = p0 * (a0.x + a1.x) + p1 * (b0.x + b1.x);
    o.y = p0 * (a0.y + a1.y) + p1 * (b0.y + b1.y);
    o.z = p0 * (a0.z + a1.z) + p1 * (b0.z + b1.z);
    o.w = p0 * (a0.w + a1.w) + p1 * (b0.w + b1.w);
    ((float4*)out)[idx] = o;
}

extern "C" void kernel_launch(void* const* d_in, const int* in_sizes, int n_in,
                              void* d_out, int out_size)
{
    const float* x     = (const float*)d_in[0];
    const float* noise = (const float*)d_in[1];
    const float* Wg    = (const float*)d_in[2];
    const float* bg    = (const float*)d_in[3];
    const float* Wn    = (const float*)d_in[4];
    const float* bn    = (const float*)d_in[5];
    const float* W1    = (const float*)d_in[6];
    const float* b1    = (const float*)d_in[7];
    const float* W2    = (const float*)d_in[8];
    const float* b2    = (const float*)d_in[9];
    float* out = (float*)d_out;

    int T = in_sizes[0] / D_DIM;
    if (T > MAX_T) T = MAX_T;

    // one-time setup (first call is the uncaptured correctness run)
    static bool s_init = false;
    static cudaStream_t s1, s2;
    static cudaEvent_t ev0, ev1, ev2;
    if (!s_init) {
        cudaStreamCreateWithFlags(&s1, cudaStreamNonBlocking);
        cudaStreamCreateWithFlags(&s2, cudaStreamNonBlocking);
        cudaEventCreateWithFlags(&ev0, cudaEventDisableTiming);
        cudaEventCreateWithFlags(&ev1, cudaEventDisableTiming);
        cudaEventCreateWithFlags(&ev2, cudaEventDisableTiming);
        cudaFuncSetAttribute(moe_gemm<true>,
                             cudaFuncAttributeMaxDynamicSharedMemorySize, SM_BYTES);
        cudaFuncSetAttribute(moe_gemm<false>,
                             cudaFuncAttributeMaxDynamicSharedMemorySize, SM_BYTES);
        s_init = true;
    }

    __half *xh = nullptr, *hid = nullptr, *w1h = nullptr, *w2h = nullptr;
    float *yv = nullptr, *yv2 = nullptr;
    cudaGetSymbolAddress((void**)&xh,  g_xh);
    cudaGetSymbolAddress((void**)&hid, g_hid);
    cudaGetSymbolAddress((void**)&w1h, g_w1h);
    cudaGetSymbolAddress((void**)&w2h, g_w2h);
    cudaGetSymbolAddress((void**)&yv,  g_y);
    cudaGetSymbolAddress((void**)&yv2, g_y2);

    int nw = E_NUM * D_DIM * H_DIM / 8;

    // fork: weight converts on side streams, route on main stream
    zero_counts_kernel<<<1, 32>>>();
    cudaEventRecord(ev0, 0);
    cudaStreamWaitEvent(s1, ev0, 0);
    cudaStreamWaitEvent(s2, ev0, 0);
    convert_f2h<<<(nw + 255) / 256, 256, 0, s1>>>(W1, w1h, nw);
    cudaEventRecord(ev1, s1);
    convert_f2h<<<(nw + 255) / 256, 256, 0, s2>>>(W2, w2h, nw);
    cudaEventRecord(ev2, s2);

    route_kernel<<<T, 256>>>(x, noise, Wg, bg, Wn, bn);  // also writes g_xh

    int mt = (T + 127) / 128;
    cudaStreamWaitEvent(0, ev1, 0);   // join W1 convert
    moe_gemm<true ><<<dim3(H_DIM / 128, mt, E_NUM), 128, SM_BYTES>>>(
        xh, w1h, b1, hid, nullptr);
    cudaStreamWaitEvent(0, ev2, 0);   // join W2 convert
    moe_gemm<false><<<dim3(D_DIM / 128, mt, E_NUM * 2), 128, SM_BYTES>>>(
        hid, w2h, b2, yv, yv2);

    combine_kernel<<<(T * (D_DIM / 4) + 255) / 256, 256>>>(out, T);
}

// round 11
// speedup vs baseline: 8.6338x; 1.1044x over previous
#include <cuda_runtime.h>
#include <cuda_fp16.h>
#include <cstdint>

#define D_DIM 768
#define H_DIM 3072
#define E_NUM 8
#define MAX_T 4096
#define RT_TOK 16   // tokens per routing block

// ---------------- device scratch ----------------
__device__ int    g_counts[E_NUM];
__device__ int    g_tok [E_NUM * MAX_T];
__device__ int    g_slot[E_NUM * MAX_T];
__device__ float  g_pslot[2 * MAX_T];
__device__ __half g_xh [(size_t)MAX_T * D_DIM];
__device__ __half g_hid[(size_t)2 * MAX_T * H_DIM];
__device__ float  g_y  [(size_t)2 * MAX_T * D_DIM];   // split-K half 0 (+bias)
__device__ float  g_y2 [(size_t)2 * MAX_T * D_DIM];   // split-K half 1
__device__ __half g_w1h[(size_t)E_NUM * D_DIM * H_DIM];
__device__ __half g_w2h[(size_t)E_NUM * H_DIM * D_DIM];

// ---------------- PTX helpers ----------------
__device__ __forceinline__ uint32_t smem_u32(const void* p) {
    uint32_t r;
    asm("{ .reg .u64 t; cvta.to.shared.u64 t, %1; cvt.u32.u64 %0, t; }"
        : "=r"(r) : "l"(p));
    return r;
}
__device__ __forceinline__ void mma_f16(float* d, const uint4& a, const uint2& b) {
    asm volatile(
        "mma.sync.aligned.m16n8k16.row.col.f32.f16.f16.f32 "
        "{%0,%1,%2,%3}, {%4,%5,%6,%7}, {%8,%9}, {%0,%1,%2,%3};"
        : "+f"(d[0]), "+f"(d[1]), "+f"(d[2]), "+f"(d[3])
        : "r"(a.x), "r"(a.y), "r"(a.z), "r"(a.w), "r"(b.x), "r"(b.y));
}
__device__ __forceinline__ void ldsm_x4(uint4& r, uint32_t addr) {
    asm volatile("ldmatrix.sync.aligned.m8n8.x4.shared.b16 {%0,%1,%2,%3}, [%4];"
                 : "=r"(r.x), "=r"(r.y), "=r"(r.z), "=r"(r.w) : "r"(addr));
}
__device__ __forceinline__ void ldsm_x4t(uint4& r, uint32_t addr) {
    asm volatile("ldmatrix.sync.aligned.m8n8.x4.trans.shared.b16 {%0,%1,%2,%3}, [%4];"
                 : "=r"(r.x), "=r"(r.y), "=r"(r.z), "=r"(r.w) : "r"(addr));
}
__device__ __forceinline__ void cp16(uint32_t dst, const void* src, uint32_t sz) {
    asm volatile("cp.async.cg.shared.global [%0], [%1], 16, %2;"
                 :: "r"(dst), "l"(src), "r"(sz) : "memory");
}
__device__ __forceinline__ void cp_commit() {
    asm volatile("cp.async.commit_group;" ::: "memory");
}
__device__ __forceinline__ void cp_wait1() {
    asm volatile("cp.async.wait_group 1;" ::: "memory");
}

// ---------------- fp32 -> fp16 convert ----------------
__global__ void __launch_bounds__(256) convert_f2h(
    const float* __restrict__ src, __half* __restrict__ dst, int n8)
{
    int i = blockIdx.x * 256 + threadIdx.x;
    if (i >= n8) return;
    const float4* s = (const float4*)src + 2 * (size_t)i;
    float4 a = s[0], b = s[1];
    __half2 h0 = __floats2half2_rn(a.x, a.y);
    __half2 h1 = __floats2half2_rn(a.z, a.w);
    __half2 h2 = __floats2half2_rn(b.x, b.y);
    __half2 h3 = __floats2half2_rn(b.z, b.w);
    uint4 o;
    o.x = *(uint32_t*)&h0; o.y = *(uint32_t*)&h1;
    o.z = *(uint32_t*)&h2; o.w = *(uint32_t*)&h3;
    ((uint4*)dst)[i] = o;
}

// ---------------- routing ----------------
__global__ void zero_counts_kernel() {
    if (threadIdx.x < E_NUM) g_counts[threadIdx.x] = 0;
}

// 16 tokens per 256-thread block; gate weights cached in smem (pad stride 9).
// Each warp handles 2 tokens; lane l owns d = l + 32*i. Also emits x as fp16.
__global__ void __launch_bounds__(256) route_kernel(
    const float* __restrict__ x, const float* __restrict__ noise,
    const float* __restrict__ Wg, const float* __restrict__ bg,
    const float* __restrict__ Wn, const float* __restrict__ bn, int T)
{
    __shared__ float sWg[D_DIM * 9];
    __shared__ float sWn[D_DIM * 9];

    int tid = threadIdx.x, wid = tid >> 5, lane = tid & 31;

    for (int idx = tid; idx < D_DIM * E_NUM; idx += 256) {
        int d = idx >> 3, e = idx & 7;
        sWg[d * 9 + e] = Wg[idx];
        sWn[d * 9 + e] = Wn[idx];
    }
    __syncthreads();

    int tbase = blockIdx.x * RT_TOK + wid * 2;

#pragma unroll 1
    for (int tt = 0; tt < 2; tt++) {
        int t = tbase + tt;
        if (t >= T) break;

        float pg[E_NUM], pn[E_NUM];
#pragma unroll
        for (int e = 0; e < E_NUM; e++) { pg[e] = 0.f; pn[e] = 0.f; }

        const float* xr = x + (size_t)t * D_DIM;
        __half* xhr = g_xh + (size_t)t * D_DIM;
#pragma unroll 4
        for (int i = 0; i < D_DIM / 32; i++) {
            int d = lane + 32 * i;
            float xv = xr[d];
            xhr[d] = __float2half_rn(xv);
            const float* wg = &sWg[d * 9];
            const float* wn = &sWn[d * 9];
#pragma unroll
            for (int e = 0; e < E_NUM; e++) {
                pg[e] = fmaf(xv, wg[e], pg[e]);
                pn[e] = fmaf(xv, wn[e], pn[e]);
            }
        }
#pragma unroll
        for (int e = 0; e < E_NUM; e++)
#pragma unroll
            for (int o = 16; o > 0; o >>= 1) {
                pg[e] += __shfl_down_sync(0xffffffffu, pg[e], o);
                pn[e] += __shfl_down_sync(0xffffffffu, pn[e], o);
            }

        if (lane == 0) {
            float h[E_NUM];
#pragma unroll
            for (int e = 0; e < E_NUM; e++) {
                float a = pg[e] + bg[e];
                float b = pn[e] + bn[e];
                float sp = fmaxf(b, 0.f) + log1pf(expf(-fabsf(b)));
                h[e] = a + noise[(size_t)t * E_NUM + e] * sp;
            }
            int i0 = 0;
#pragma unroll
            for (int e = 1; e < E_NUM; e++) if (h[e] > h[i0]) i0 = e;
            int i1 = (i0 == 0) ? 1 : 0;
#pragma unroll
            for (int e = 0; e < E_NUM; e++) if (e != i0 && h[e] > h[i1]) i1 = e;

            float p0 = 1.f / (1.f + expf(h[i1] - h[i0]));
            float p1 = 1.f - p0;
            g_pslot[2 * t]     = p0;
            g_pslot[2 * t + 1] = p1;

            int s0 = atomicAdd(&g_counts[i0], 1);
            g_tok [i0 * MAX_T + s0] = t;
            g_slot[i0 * MAX_T + s0] = 2 * t;
            int s1 = atomicAdd(&g_counts[i1], 1);
            g_tok [i1 * MAX_T + s1] = t;
            g_slot[i1 * MAX_T + s1] = 2 * t + 1;
        }
    }
}

// ---------------- grouped fp16 GEMM ----------------
// 128 threads (4 warps 2x2), BM=128, BN=128, BK=64, 3-stage cp.async ring.
// 2 CTAs/SM. GEMM2 (!G1) is split-K=2: blockIdx.z = half*8 + e.
#define STAGE_BYTES 32768
#define SM_BYTES (3 * STAGE_BYTES)   // 98304 per CTA

template <bool G1>
__global__ void __launch_bounds__(128) moe_gemm(
    const __half* __restrict__ Ah, const __half* __restrict__ Wh,
    const float* __restrict__ bias, void* __restrict__ OutV,
    float* __restrict__ Out2)
{
    constexpr int KTOT  = G1 ? D_DIM : H_DIM;
    constexpr int KSPAN = G1 ? D_DIM : (H_DIM / 2);
    constexpr int NG    = G1 ? H_DIM : D_DIM;
    constexpr int NC    = KSPAN / 64;

    int z    = blockIdx.z;
    int e    = G1 ? z : (z & 7);
    int half = G1 ? 0 : (z >> 3);
    int cnt  = g_counts[e];
    int m0   = blockIdx.y * 128;
    if (m0 >= cnt) return;
    int n0   = blockIdx.x * 128;
    size_t kbase = (size_t)half * KSPAN;

    extern __shared__ char smem[];
    uint32_t sbase = smem_u32(smem);

    int tid = threadIdx.x, wid = tid >> 5, lane = tid & 31;
    int wm = wid >> 1, wn = wid & 1;
    const int* idxarr = G1 ? g_tok : g_slot;

    // ---- cp.async plans ----
    int ar0 = tid >> 3, akq = tid & 7;
    uint32_t a_dst0 = (uint32_t)(ar0 * 8 + (akq ^ (ar0 & 7))) * 16;
    const __half* a_src[8]; uint32_t a_sz[8];
#pragma unroll
    for (int i = 0; i < 8; i++) {
        int gr = m0 + ar0 + 16 * i;
        if (gr < cnt) {
            a_src[i] = Ah + (size_t)idxarr[e * MAX_T + gr] * KTOT + kbase + akq * 8;
            a_sz[i] = 16;
        } else { a_src[i] = Ah; a_sz[i] = 0; }
    }
    int bk0 = tid >> 4, bnq = tid & 15;
    const __half* b_src = Wh + (size_t)e * KTOT * NG + (kbase + bk0) * NG
                        + n0 + bnq * 8;
    uint32_t b_dst0 = 16384u + (uint32_t)(bk0 * 16 + (bnq ^ (bk0 & 7))) * 16;

    auto issue = [&](int c) {
        if (c < NC) {
            uint32_t sa = sbase + (uint32_t)(c % 3) * STAGE_BYTES;
#pragma unroll
            for (int i = 0; i < 8; i++)
                cp16(sa + a_dst0 + (uint32_t)i * 2048,
                     a_src[i] + (size_t)c * 64, a_sz[i]);
            const __half* bs = b_src + (size_t)c * 64 * NG;
#pragma unroll
            for (int j = 0; j < 8; j++)
                cp16(sa + b_dst0 + (uint32_t)j * 2048,
                     bs + (size_t)(8 * j) * NG, 16);
        }
        cp_commit();
    };

    issue(0); issue(1);

    int lrow = (lane & 7) + 8 * ((lane >> 3) & 1);
    int lsel = lane >> 4;

    float acc[4][8][4];
#pragma unroll
    for (int a = 0; a < 4; a++)
#pragma unroll
        for (int b = 0; b < 8; b++)
#pragma unroll
            for (int k = 0; k < 4; k++) acc[a][b][k] = 0.f;

#pragma unroll 1
    for (int c = 0; c < NC; c++) {
        cp_wait1();
        __syncthreads();
        issue(c + 2);

        uint32_t sa = sbase + (uint32_t)(c % 3) * STAGE_BYTES;
        uint32_t sb = sa + 16384u;
#pragma unroll
        for (int ks = 0; ks < 4; ks++) {
            uint4 af[4]; uint2 bf[8];
            int kq = ks * 2 + lsel;
#pragma unroll
            for (int mf = 0; mf < 4; mf++) {
                int row = wm * 64 + mf * 16 + lrow;
                ldsm_x4(af[mf], sa + (uint32_t)(row * 8 + (kq ^ (row & 7))) * 16);
            }
            int kb = ks * 16 + lrow;
#pragma unroll
            for (int np = 0; np < 4; np++) {
                int nq = (wn * 4 + np) * 2 + lsel;
                uint4 bb;
                ldsm_x4t(bb, sb + (uint32_t)(kb * 16 + (nq ^ (kb & 7))) * 16);
                bf[2 * np].x     = bb.x; bf[2 * np].y     = bb.y;
                bf[2 * np + 1].x = bb.z; bf[2 * np + 1].y = bb.w;
            }
#pragma unroll
            for (int mf = 0; mf < 4; mf++)
#pragma unroll
                for (int nf = 0; nf < 8; nf++)
                    mma_f16(acc[mf][nf], af[mf], bf[nf]);
        }
        __syncthreads();
    }

    // ---- epilogue ----
#pragma unroll
    for (int mf = 0; mf < 4; mf++) {
        int r0 = m0 + wm * 64 + mf * 16 + (lane >> 2);
        int r1 = r0 + 8;
        bool v0 = r0 < cnt, v1 = r1 < cnt;
        int s0 = v0 ? g_slot[e * MAX_T + r0] : 0;
        int s1 = v1 ? g_slot[e * MAX_T + r1] : 0;
#pragma unroll
        for (int nf = 0; nf < 8; nf++) {
            int col = n0 + wn * 64 + nf * 8 + (lane & 3) * 2;
            float x0 = acc[mf][nf][0], x1 = acc[mf][nf][1];
            float x2 = acc[mf][nf][2], x3 = acc[mf][nf][3];
            if (G1 || half == 0) {
                float2 bb = *(const float2*)&bias[(size_t)e * NG + col];
                x0 += bb.x; x1 += bb.y; x2 += bb.x; x3 += bb.y;
            }
            if (G1) {
                x0 = fmaxf(x0, 0.f); x1 = fmaxf(x1, 0.f);
                x2 = fmaxf(x2, 0.f); x3 = fmaxf(x3, 0.f);
                __half* Out = (__half*)OutV;
                if (v0) {
                    __half2 hv = __floats2half2_rn(x0, x1);
                    *(__half2*)(Out + (size_t)s0 * NG + col) = hv;
                }
                if (v1) {
                    __half2 hv = __floats2half2_rn(x2, x3);
                    *(__half2*)(Out + (size_t)s1 * NG + col) = hv;
                }
            } else {
                float* Out = half ? Out2 : (float*)OutV;
                if (v0) { float2 o; o.x = x0; o.y = x1;
                          *(float2*)(Out + (size_t)s0 * NG + col) = o; }
                if (v1) { float2 o; o.x = x2; o.y = x3;
                          *(float2*)(Out + (size_t)s1 * NG + col) = o; }
            }
        }
    }
}

// out[t] = p0*(y[2t]+y2[2t]) + p1*(y[2t+1]+y2[2t+1])
__global__ void __launch_bounds__(256) combine_kernel(float* __restrict__ out, int T)
{
    int idx = blockIdx.x * 256 + threadIdx.x;
    int total = T * (D_DIM / 4);
    if (idx >= total) return;
    int t  = idx / (D_DIM / 4);
    int c4 = idx % (D_DIM / 4);
    float4 a0 = ((const float4*)(g_y  + (size_t)(2 * t) * D_DIM))[c4];
    float4 a1 = ((const float4*)(g_y2 + (size_t)(2 * t) * D_DIM))[c4];
    float4 b0 = ((const float4*)(g_y  + (size_t)(2 * t + 1) * D_DIM))[c4];
    float4 b1 = ((const float4*)(g_y2 + (size_t)(2 * t + 1) * D_DIM))[c4];
    float p0 = g_pslot[2 * t], p1 = g_pslot[2 * t + 1];
    float4 o;
    o.x = p0 * (a0.x + a1.x) + p1 * (b0.x + b1.x);
    o.y = p0 * (a0.y + a1.y) + p1 * (b0.y + b1.y);
    o.z = p0 * (a0.z + a1.z) + p1 * (b0.z + b1.z);
    o.w = p0 * (a0.w + a1.w) + p1 * (b0.w + b1.w);
    ((float4*)out)[idx] = o;
}

extern "C" void kernel_launch(void* const* d_in, const int* in_sizes, int n_in,
                              void* d_out, int out_size)
{
    const float* x     = (const float*)d_in[0];
    const float* noise = (const float*)d_in[1];
    const float* Wg    = (const float*)d_in[2];
    const float* bg    = (const float*)d_in[3];
    const float* Wn    = (const float*)d_in[4];
    const float* bn    = (const float*)d_in[5];
    const float* W1    = (const float*)d_in[6];
    const float* b1    = (const float*)d_in[7];
    const float* W2    = (const float*)d_in[8];
    const float* b2    = (const float*)d_in[9];
    float* out = (float*)d_out;

    int T = in_sizes[0] / D_DIM;
    if (T > MAX_T) T = MAX_T;

    // one-time setup (first call is the uncaptured correctness run)
    static bool s_init = false;
    static cudaStream_t s1, s2;
    static cudaEvent_t ev0, ev1, ev2;
    if (!s_init) {
        cudaStreamCreateWithFlags(&s1, cudaStreamNonBlocking);
        cudaStreamCreateWithFlags(&s2, cudaStreamNonBlocking);
        cudaEventCreateWithFlags(&ev0, cudaEventDisableTiming);
        cudaEventCreateWithFlags(&ev1, cudaEventDisableTiming);
        cudaEventCreateWithFlags(&ev2, cudaEventDisableTiming);
        cudaFuncSetAttribute(moe_gemm<true>,
                             cudaFuncAttributeMaxDynamicSharedMemorySize, SM_BYTES);
        cudaFuncSetAttribute(moe_gemm<false>,
                             cudaFuncAttributeMaxDynamicSharedMemorySize, SM_BYTES);
        s_init = true;
    }

    __half *xh = nullptr, *hid = nullptr, *w1h = nullptr, *w2h = nullptr;
    float *yv = nullptr, *yv2 = nullptr;
    cudaGetSymbolAddress((void**)&xh,  g_xh);
    cudaGetSymbolAddress((void**)&hid, g_hid);
    cudaGetSymbolAddress((void**)&w1h, g_w1h);
    cudaGetSymbolAddress((void**)&w2h, g_w2h);
    cudaGetSymbolAddress((void**)&yv,  g_y);
    cudaGetSymbolAddress((void**)&yv2, g_y2);

    int nw = E_NUM * D_DIM * H_DIM / 8;

    // fork: weight converts on side streams, route on main stream
    zero_counts_kernel<<<1, 32>>>();
    cudaEventRecord(ev0, 0);
    cudaStreamWaitEvent(s1, ev0, 0);
    cudaStreamWaitEvent(s2, ev0, 0);
    convert_f2h<<<(nw + 255) / 256, 256, 0, s1>>>(W1, w1h, nw);
    cudaEventRecord(ev1, s1);
    convert_f2h<<<(nw + 255) / 256, 256, 0, s2>>>(W2, w2h, nw);
    cudaEventRecord(ev2, s2);

    route_kernel<<<(T + RT_TOK - 1) / RT_TOK, 256>>>(x, noise, Wg, bg, Wn, bn, T);

    int mt = (T + 127) / 128;
    cudaStreamWaitEvent(0, ev1, 0);   // join W1 convert
    moe_gemm<true ><<<dim3(H_DIM / 128, mt, E_NUM), 128, SM_BYTES>>>(
        xh, w1h, b1, hid, nullptr);
    cudaStreamWaitEvent(0, ev2, 0);   // join W2 convert
    moe_gemm<false><<<dim3(D_DIM / 128, mt, E_NUM * 2), 128, SM_BYTES>>>(
        hid, w2h, b2, yv, yv2);

    combine_kernel<<<(T * (D_DIM / 4) + 255) / 256, 256>>>(out, T);
}

// round 12
// speedup vs baseline: 8.8894x; 1.0296x over previous
#include <cuda_runtime.h>
#include <cuda_fp16.h>
#include <cstdint>

#define D_DIM 768
#define H_DIM 3072
#define E_NUM 8
#define MAX_T 4096
#define RT_TOK 16   // tokens per routing block

// ---------------- device scratch ----------------
__device__ int    g_counts[E_NUM];
__device__ int    g_ntiles;
__device__ int    g_tmap[256];              // (e<<16)|mtile
__device__ int    g_tok [E_NUM * MAX_T];
__device__ int    g_slot[E_NUM * MAX_T];
__device__ float  g_pslot[2 * MAX_T];
__device__ __half g_xh [(size_t)MAX_T * D_DIM];
__device__ __half g_hid[(size_t)2 * MAX_T * H_DIM];
__device__ float  g_y  [(size_t)2 * MAX_T * D_DIM];   // split-K half 0 (+bias)
__device__ float  g_y2 [(size_t)2 * MAX_T * D_DIM];   // split-K half 1
__device__ __half g_w1h[(size_t)E_NUM * D_DIM * H_DIM];
__device__ __half g_w2h[(size_t)E_NUM * H_DIM * D_DIM];

// ---------------- PTX helpers ----------------
__device__ __forceinline__ uint32_t smem_u32(const void* p) {
    uint32_t r;
    asm("{ .reg .u64 t; cvta.to.shared.u64 t, %1; cvt.u32.u64 %0, t; }"
        : "=r"(r) : "l"(p));
    return r;
}
__device__ __forceinline__ void mma_f16(float* d, const uint4& a, const uint2& b) {
    asm volatile(
        "mma.sync.aligned.m16n8k16.row.col.f32.f16.f16.f32 "
        "{%0,%1,%2,%3}, {%4,%5,%6,%7}, {%8,%9}, {%0,%1,%2,%3};"
        : "+f"(d[0]), "+f"(d[1]), "+f"(d[2]), "+f"(d[3])
        : "r"(a.x), "r"(a.y), "r"(a.z), "r"(a.w), "r"(b.x), "r"(b.y));
}
__device__ __forceinline__ void ldsm_x4(uint4& r, uint32_t addr) {
    asm volatile("ldmatrix.sync.aligned.m8n8.x4.shared.b16 {%0,%1,%2,%3}, [%4];"
                 : "=r"(r.x), "=r"(r.y), "=r"(r.z), "=r"(r.w) : "r"(addr));
}
__device__ __forceinline__ void ldsm_x4t(uint4& r, uint32_t addr) {
    asm volatile("ldmatrix.sync.aligned.m8n8.x4.trans.shared.b16 {%0,%1,%2,%3}, [%4];"
                 : "=r"(r.x), "=r"(r.y), "=r"(r.z), "=r"(r.w) : "r"(addr));
}
__device__ __forceinline__ void cp16(uint32_t dst, const void* src, uint32_t sz) {
    asm volatile("cp.async.cg.shared.global [%0], [%1], 16, %2;"
                 :: "r"(dst), "l"(src), "r"(sz) : "memory");
}
__device__ __forceinline__ void cp_commit() {
    asm volatile("cp.async.commit_group;" ::: "memory");
}
__device__ __forceinline__ void cp_wait1() {
    asm volatile("cp.async.wait_group 1;" ::: "memory");
}

// ---------------- fp32 -> fp16 convert ----------------
__global__ void __launch_bounds__(256) convert_f2h(
    const float* __restrict__ src, __half* __restrict__ dst, int n8)
{
    int i = blockIdx.x * 256 + threadIdx.x;
    if (i >= n8) return;
    const float4* s = (const float4*)src + 2 * (size_t)i;
    float4 a = s[0], b = s[1];
    __half2 h0 = __floats2half2_rn(a.x, a.y);
    __half2 h1 = __floats2half2_rn(a.z, a.w);
    __half2 h2 = __floats2half2_rn(b.x, b.y);
    __half2 h3 = __floats2half2_rn(b.z, b.w);
    uint4 o;
    o.x = *(uint32_t*)&h0; o.y = *(uint32_t*)&h1;
    o.z = *(uint32_t*)&h2; o.w = *(uint32_t*)&h3;
    ((uint4*)dst)[i] = o;
}

// ---------------- routing ----------------
__global__ void zero_counts_kernel() {
    if (threadIdx.x < E_NUM) g_counts[threadIdx.x] = 0;
}

// Builds the compacted (expert, m-tile) work list after routing.
__global__ void tiles_kernel() {
    if (threadIdx.x == 0) {
        int c = 0;
#pragma unroll
        for (int e = 0; e < E_NUM; e++) {
            int nt = (g_counts[e] + 127) >> 7;
            for (int m = 0; m < nt; m++) g_tmap[c++] = (e << 16) | m;
        }
        g_ntiles = c;
    }
}

// 16 tokens per 256-thread block; each warp processes 2 tokens SIMULTANEOUSLY
// (2 concurrent LDG streams -> 2x MLP). Weights cached in smem as float2
// {wg,wn} at word stride 18 (conflict-free LDS.64). Also emits x as fp16.
__global__ void __launch_bounds__(256) route_kernel(
    const float* __restrict__ x, const float* __restrict__ noise,
    const float* __restrict__ Wg, const float* __restrict__ bg,
    const float* __restrict__ Wn, const float* __restrict__ bn, int T)
{
    __shared__ float sW[D_DIM * 18];

    int tid = threadIdx.x, wid = tid >> 5, lane = tid & 31;

    for (int idx = tid; idx < D_DIM * E_NUM; idx += 256) {
        int d = idx >> 3, e = idx & 7;
        sW[d * 18 + 2 * e]     = Wg[idx];
        sW[d * 18 + 2 * e + 1] = Wn[idx];
    }
    __syncthreads();

    int t0 = blockIdx.x * RT_TOK + wid * 2;
    if (t0 >= T) return;
    int t1 = t0 + 1;
    bool v1 = t1 < T;
    int t1s = v1 ? t1 : t0;

    float pg0[E_NUM], pn0[E_NUM], pg1[E_NUM], pn1[E_NUM];
#pragma unroll
    for (int e = 0; e < E_NUM; e++) {
        pg0[e] = 0.f; pn0[e] = 0.f; pg1[e] = 0.f; pn1[e] = 0.f;
    }

    const float* xr0 = x + (size_t)t0 * D_DIM;
    const float* xr1 = x + (size_t)t1s * D_DIM;
    __half* xh0 = g_xh + (size_t)t0 * D_DIM;
    __half* xh1 = g_xh + (size_t)t1s * D_DIM;

#pragma unroll 4
    for (int i = 0; i < D_DIM / 32; i++) {
        int d = lane + 32 * i;
        float xv0 = xr0[d];
        float xv1 = xr1[d];
        xh0[d] = __float2half_rn(xv0);
        xh1[d] = __float2half_rn(xv1);
        const float2* w = (const float2*)(sW + d * 18);
#pragma unroll
        for (int e = 0; e < E_NUM; e++) {
            float2 wv = w[e];
            pg0[e] = fmaf(xv0, wv.x, pg0[e]);
            pn0[e] = fmaf(xv0, wv.y, pn0[e]);
            pg1[e] = fmaf(xv1, wv.x, pg1[e]);
            pn1[e] = fmaf(xv1, wv.y, pn1[e]);
        }
    }
#pragma unroll
    for (int e = 0; e < E_NUM; e++)
#pragma unroll
        for (int o = 16; o > 0; o >>= 1) {
            pg0[e] += __shfl_down_sync(0xffffffffu, pg0[e], o);
            pn0[e] += __shfl_down_sync(0xffffffffu, pn0[e], o);
            pg1[e] += __shfl_down_sync(0xffffffffu, pg1[e], o);
            pn1[e] += __shfl_down_sync(0xffffffffu, pn1[e], o);
        }

    if (lane == 0) {
#pragma unroll 1
        for (int tt = 0; tt < 2; tt++) {
            if (tt == 1 && !v1) break;
            int t = t0 + tt;
            float h[E_NUM];
#pragma unroll
            for (int e = 0; e < E_NUM; e++) {
                float a = (tt ? pg1[e] : pg0[e]) + bg[e];
                float b = (tt ? pn1[e] : pn0[e]) + bn[e];
                float sp = fmaxf(b, 0.f) + log1pf(expf(-fabsf(b)));
                h[e] = a + noise[(size_t)t * E_NUM + e] * sp;
            }
            int i0 = 0;
#pragma unroll
            for (int e = 1; e < E_NUM; e++) if (h[e] > h[i0]) i0 = e;
            int i1 = (i0 == 0) ? 1 : 0;
#pragma unroll
            for (int e = 0; e < E_NUM; e++) if (e != i0 && h[e] > h[i1]) i1 = e;

            float p0 = 1.f / (1.f + expf(h[i1] - h[i0]));
            float p1 = 1.f - p0;
            g_pslot[2 * t]     = p0;
            g_pslot[2 * t + 1] = p1;

            int s0 = atomicAdd(&g_counts[i0], 1);
            g_tok [i0 * MAX_T + s0] = t;
            g_slot[i0 * MAX_T + s0] = 2 * t;
            int s1 = atomicAdd(&g_counts[i1], 1);
            g_tok [i1 * MAX_T + s1] = t;
            g_slot[i1 * MAX_T + s1] = 2 * t + 1;
        }
    }
}

// ---------------- grouped fp16 GEMM ----------------
// 128 threads (4 warps 2x2), BM=128, BN=128, BK=64, 3-stage cp.async ring.
// 2 CTAs/SM. Compacted tile map: blockIdx.y indexes g_tmap (no dead m-tiles).
// GEMM2 (!G1) is split-K=2: blockIdx.z = half.
#define STAGE_BYTES 32768
#define SM_BYTES (3 * STAGE_BYTES)   // 98304 per CTA

template <bool G1>
__global__ void __launch_bounds__(128) moe_gemm(
    const __half* __restrict__ Ah, const __half* __restrict__ Wh,
    const float* __restrict__ bias, void* __restrict__ OutV,
    float* __restrict__ Out2)
{
    constexpr int KTOT  = G1 ? D_DIM : H_DIM;
    constexpr int KSPAN = G1 ? D_DIM : (H_DIM / 2);
    constexpr int NG    = G1 ? H_DIM : D_DIM;
    constexpr int NC    = KSPAN / 64;

    int ty = blockIdx.y;
    if (ty >= g_ntiles) return;
    int tm   = g_tmap[ty];
    int e    = tm >> 16;
    int m0   = (tm & 0xFFFF) * 128;
    int half = G1 ? 0 : blockIdx.z;
    int cnt  = g_counts[e];
    int n0   = blockIdx.x * 128;
    size_t kbase = (size_t)half * KSPAN;

    extern __shared__ char smem[];
    uint32_t sbase = smem_u32(smem);

    int tid = threadIdx.x, wid = tid >> 5, lane = tid & 31;
    int wm = wid >> 1, wn = wid & 1;
    const int* idxarr = G1 ? g_tok : g_slot;

    // ---- cp.async plans ----
    int ar0 = tid >> 3, akq = tid & 7;
    uint32_t a_dst0 = (uint32_t)(ar0 * 8 + (akq ^ (ar0 & 7))) * 16;
    const __half* a_src[8]; uint32_t a_sz[8];
#pragma unroll
    for (int i = 0; i < 8; i++) {
        int gr = m0 + ar0 + 16 * i;
        if (gr < cnt) {
            a_src[i] = Ah + (size_t)idxarr[e * MAX_T + gr] * KTOT + kbase + akq * 8;
            a_sz[i] = 16;
        } else { a_src[i] = Ah; a_sz[i] = 0; }
    }
    int bk0 = tid >> 4, bnq = tid & 15;
    const __half* b_src = Wh + (size_t)e * KTOT * NG + (kbase + bk0) * NG
                        + n0 + bnq * 8;
    uint32_t b_dst0 = 16384u + (uint32_t)(bk0 * 16 + (bnq ^ (bk0 & 7))) * 16;

    auto issue = [&](int c) {
        if (c < NC) {
            uint32_t sa = sbase + (uint32_t)(c % 3) * STAGE_BYTES;
#pragma unroll
            for (int i = 0; i < 8; i++)
                cp16(sa + a_dst0 + (uint32_t)i * 2048,
                     a_src[i] + (size_t)c * 64, a_sz[i]);
            const __half* bs = b_src + (size_t)c * 64 * NG;
#pragma unroll
            for (int j = 0; j < 8; j++)
                cp16(sa + b_dst0 + (uint32_t)j * 2048,
                     bs + (size_t)(8 * j) * NG, 16);
        }
        cp_commit();
    };

    issue(0); issue(1);

    int lrow = (lane & 7) + 8 * ((lane >> 3) & 1);
    int lsel = lane >> 4;

    float acc[4][8][4];
#pragma unroll
    for (int a = 0; a < 4; a++)
#pragma unroll
        for (int b = 0; b < 8; b++)
#pragma unroll
            for (int k = 0; k < 4; k++) acc[a][b][k] = 0.f;

#pragma unroll 1
    for (int c = 0; c < NC; c++) {
        cp_wait1();
        __syncthreads();
        issue(c + 2);

        uint32_t sa = sbase + (uint32_t)(c % 3) * STAGE_BYTES;
        uint32_t sb = sa + 16384u;
#pragma unroll
        for (int ks = 0; ks < 4; ks++) {
            uint4 af[4]; uint2 bf[8];
            int kq = ks * 2 + lsel;
#pragma unroll
            for (int mf = 0; mf < 4; mf++) {
                int row = wm * 64 + mf * 16 + lrow;
                ldsm_x4(af[mf], sa + (uint32_t)(row * 8 + (kq ^ (row & 7))) * 16);
            }
            int kb = ks * 16 + lrow;
#pragma unroll
            for (int np = 0; np < 4; np++) {
                int nq = (wn * 4 + np) * 2 + lsel;
                uint4 bb;
                ldsm_x4t(bb, sb + (uint32_t)(kb * 16 + (nq ^ (kb & 7))) * 16);
                bf[2 * np].x     = bb.x; bf[2 * np].y     = bb.y;
                bf[2 * np + 1].x = bb.z; bf[2 * np + 1].y = bb.w;
            }
#pragma unroll
            for (int mf = 0; mf < 4; mf++)
#pragma unroll
                for (int nf = 0; nf < 8; nf++)
                    mma_f16(acc[mf][nf], af[mf], bf[nf]);
        }
        __syncthreads();
    }

    // ---- epilogue ----
#pragma unroll
    for (int mf = 0; mf < 4; mf++) {
        int r0 = m0 + wm * 64 + mf * 16 + (lane >> 2);
        int r1 = r0 + 8;
        bool v0 = r0 < cnt, v1 = r1 < cnt;
        int s0 = v0 ? g_slot[e * MAX_T + r0] : 0;
        int s1 = v1 ? g_slot[e * MAX_T + r1] : 0;
#pragma unroll
        for (int nf = 0; nf < 8; nf++) {
            int col = n0 + wn * 64 + nf * 8 + (lane & 3) * 2;
            float x0 = acc[mf][nf][0], x1 = acc[mf][nf][1];
            float x2 = acc[mf][nf][2], x3 = acc[mf][nf][3];
            if (G1 || half == 0) {
                float2 bb = *(const float2*)&bias[(size_t)e * NG + col];
                x0 += bb.x; x1 += bb.y; x2 += bb.x; x3 += bb.y;
            }
            if (G1) {
                x0 = fmaxf(x0, 0.f); x1 = fmaxf(x1, 0.f);
                x2 = fmaxf(x2, 0.f); x3 = fmaxf(x3, 0.f);
                __half* Out = (__half*)OutV;
                if (v0) {
                    __half2 hv = __floats2half2_rn(x0, x1);
                    *(__half2*)(Out + (size_t)s0 * NG + col) = hv;
                }
                if (v1) {
                    __half2 hv = __floats2half2_rn(x2, x3);
                    *(__half2*)(Out + (size_t)s1 * NG + col) = hv;
                }
            } else {
                float* Out = half ? Out2 : (float*)OutV;
                if (v0) { float2 o; o.x = x0; o.y = x1;
                          *(float2*)(Out + (size_t)s0 * NG + col) = o; }
                if (v1) { float2 o; o.x = x2; o.y = x3;
                          *(float2*)(Out + (size_t)s1 * NG + col) = o; }
            }
        }
    }
}

// out[t] = p0*(y[2t]+y2[2t]) + p1*(y[2t+1]+y2[2t+1])
__global__ void __launch_bounds__(256) combine_kernel(float* __restrict__ out, int T)
{
    int idx = blockIdx.x * 256 + threadIdx.x;
    int total = T * (D_DIM / 4);
    if (idx >= total) return;
    int t  = idx / (D_DIM / 4);
    int c4 = idx % (D_DIM / 4);
    float4 a0 = ((const float4*)(g_y  + (size_t)(2 * t) * D_DIM))[c4];
    float4 a1 = ((const float4*)(g_y2 + (size_t)(2 * t) * D_DIM))[c4];
    float4 b0 = ((const float4*)(g_y  + (size_t)(2 * t + 1) * D_DIM))[c4];
    float4 b1 = ((const float4*)(g_y2 + (size_t)(2 * t + 1) * D_DIM))[c4];
    float p0 = g_pslot[2 * t], p1 = g_pslot[2 * t + 1];
    float4 o;
    o.x = p0 * (a0.x + a1.x) + p1 * (b0.x + b1.x);
    o.y = p0 * (a0.y + a1.y) + p1 * (b0.y + b1.y);
    o.z = p0 * (a0.z + a1.z) + p1 * (b0.z + b1.z);
    o.w = p0 * (a0.w + a1.w) + p1 * (b0.w + b1.w);
    ((float4*)out)[idx] = o;
}

extern "C" void kernel_launch(void* const* d_in, const int* in_sizes, int n_in,
                              void* d_out, int out_size)
{
    const float* x     = (const float*)d_in[0];
    const float* noise = (const float*)d_in[1];
    const float* Wg    = (const float*)d_in[2];
    const float* bg    = (const float*)d_in[3];
    const float* Wn    = (const float*)d_in[4];
    const float* bn    = (const float*)d_in[5];
    const float* W1    = (const float*)d_in[6];
    const float* b1    = (const float*)d_in[7];
    const float* W2    = (const float*)d_in[8];
    const float* b2    = (const float*)d_in[9];
    float* out = (float*)d_out;

    int T = in_sizes[0] / D_DIM;
    if (T > MAX_T) T = MAX_T;

    // one-time setup (first call is the uncaptured correctness run)
    static bool s_init = false;
    static cudaStream_t s1, s2;
    static cudaEvent_t ev0, ev1, ev2;
    if (!s_init) {
        cudaStreamCreateWithFlags(&s1, cudaStreamNonBlocking);
        cudaStreamCreateWithFlags(&s2, cudaStreamNonBlocking);
        cudaEventCreateWithFlags(&ev0, cudaEventDisableTiming);
        cudaEventCreateWithFlags(&ev1, cudaEventDisableTiming);
        cudaEventCreateWithFlags(&ev2, cudaEventDisableTiming);
        cudaFuncSetAttribute(moe_gemm<true>,
                             cudaFuncAttributeMaxDynamicSharedMemorySize, SM_BYTES);
        cudaFuncSetAttribute(moe_gemm<false>,
                             cudaFuncAttributeMaxDynamicSharedMemorySize, SM_BYTES);
        s_init = true;
    }

    __half *xh = nullptr, *hid = nullptr, *w1h = nullptr, *w2h = nullptr;
    float *yv = nullptr, *yv2 = nullptr;
    cudaGetSymbolAddress((void**)&xh,  g_xh);
    cudaGetSymbolAddress((void**)&hid, g_hid);
    cudaGetSymbolAddress((void**)&w1h, g_w1h);
    cudaGetSymbolAddress((void**)&w2h, g_w2h);
    cudaGetSymbolAddress((void**)&yv,  g_y);
    cudaGetSymbolAddress((void**)&yv2, g_y2);

    int nw = E_NUM * D_DIM * H_DIM / 8;

    // fork: weight converts on side streams, route on main stream
    zero_counts_kernel<<<1, 32>>>();
    cudaEventRecord(ev0, 0);
    cudaStreamWaitEvent(s1, ev0, 0);
    cudaStreamWaitEvent(s2, ev0, 0);
    convert_f2h<<<(nw + 255) / 256, 256, 0, s1>>>(W1, w1h, nw);
    cudaEventRecord(ev1, s1);
    convert_f2h<<<(nw + 255) / 256, 256, 0, s2>>>(W2, w2h, nw);
    cudaEventRecord(ev2, s2);

    route_kernel<<<(T + RT_TOK - 1) / RT_TOK, 256>>>(x, noise, Wg, bg, Wn, bn, T);
    tiles_kernel<<<1, 32>>>();

    int maxt = (2 * T + 127) / 128 + E_NUM;   // upper bound on active m-tiles
    cudaStreamWaitEvent(0, ev1, 0);   // join W1 convert
    moe_gemm<true ><<<dim3(H_DIM / 128, maxt, 1), 128, SM_BYTES>>>(
        xh, w1h, b1, hid, nullptr);
    cudaStreamWaitEvent(0, ev2, 0);   // join W2 convert
    moe_gemm<false><<<dim3(D_DIM / 128, maxt, 2), 128, SM_BYTES>>>(
        hid, w2h, b2, yv, yv2);

    combine_kernel<<<(T * (D_DIM / 4) + 255) / 256, 256>>>(out, T);
}

// round 13
// speedup vs baseline: 8.9883x; 1.0111x over previous
#include <cuda_runtime.h>
#include <cuda_fp16.h>
#include <cstdint>

#define D_DIM 768
#define H_DIM 3072
#define E_NUM 8
#define MAX_T 4096
#define RT_TOK 8    // tokens per routing block (1 per warp)

// ---------------- device scratch ----------------
__device__ int    g_counts[E_NUM];
__device__ int    g_done;
__device__ int    g_ntiles;
__device__ int    g_tmap[256];              // (e<<16)|mtile
__device__ int    g_tok [E_NUM * MAX_T];
__device__ int    g_slot[E_NUM * MAX_T];
__device__ float  g_pslot[2 * MAX_T];
__device__ __half g_xh [(size_t)MAX_T * D_DIM];
__device__ __half g_hid[(size_t)2 * MAX_T * H_DIM];
__device__ float  g_y  [(size_t)2 * MAX_T * D_DIM];   // split-K half 0 (+bias)
__device__ float  g_y2 [(size_t)2 * MAX_T * D_DIM];   // split-K half 1
__device__ __half g_w1h[(size_t)E_NUM * D_DIM * H_DIM];
__device__ __half g_w2h[(size_t)E_NUM * H_DIM * D_DIM];

// ---------------- PTX helpers ----------------
__device__ __forceinline__ uint32_t smem_u32(const void* p) {
    uint32_t r;
    asm("{ .reg .u64 t; cvta.to.shared.u64 t, %1; cvt.u32.u64 %0, t; }"
        : "=r"(r) : "l"(p));
    return r;
}
__device__ __forceinline__ void mma_f16(float* d, const uint4& a, const uint2& b) {
    asm volatile(
        "mma.sync.aligned.m16n8k16.row.col.f32.f16.f16.f32 "
        "{%0,%1,%2,%3}, {%4,%5,%6,%7}, {%8,%9}, {%0,%1,%2,%3};"
        : "+f"(d[0]), "+f"(d[1]), "+f"(d[2]), "+f"(d[3])
        : "r"(a.x), "r"(a.y), "r"(a.z), "r"(a.w), "r"(b.x), "r"(b.y));
}
__device__ __forceinline__ void ldsm_x4(uint4& r, uint32_t addr) {
    asm volatile("ldmatrix.sync.aligned.m8n8.x4.shared.b16 {%0,%1,%2,%3}, [%4];"
                 : "=r"(r.x), "=r"(r.y), "=r"(r.z), "=r"(r.w) : "r"(addr));
}
__device__ __forceinline__ void ldsm_x4t(uint4& r, uint32_t addr) {
    asm volatile("ldmatrix.sync.aligned.m8n8.x4.trans.shared.b16 {%0,%1,%2,%3}, [%4];"
                 : "=r"(r.x), "=r"(r.y), "=r"(r.z), "=r"(r.w) : "r"(addr));
}
__device__ __forceinline__ void cp16(uint32_t dst, const void* src, uint32_t sz) {
    asm volatile("cp.async.cg.shared.global [%0], [%1], 16, %2;"
                 :: "r"(dst), "l"(src), "r"(sz) : "memory");
}
__device__ __forceinline__ void cp_commit() {
    asm volatile("cp.async.commit_group;" ::: "memory");
}
__device__ __forceinline__ void cp_wait1() {
    asm volatile("cp.async.wait_group 1;" ::: "memory");
}

// ---------------- fp32 -> fp16 convert ----------------
__global__ void __launch_bounds__(256) convert_f2h(
    const float* __restrict__ src, __half* __restrict__ dst, int n8)
{
    int i = blockIdx.x * 256 + threadIdx.x;
    if (i >= n8) return;
    const float4* s = (const float4*)src + 2 * (size_t)i;
    float4 a = s[0], b = s[1];
    __half2 h0 = __floats2half2_rn(a.x, a.y);
    __half2 h1 = __floats2half2_rn(a.z, a.w);
    __half2 h2 = __floats2half2_rn(b.x, b.y);
    __half2 h3 = __floats2half2_rn(b.z, b.w);
    uint4 o;
    o.x = *(uint32_t*)&h0; o.y = *(uint32_t*)&h1;
    o.z = *(uint32_t*)&h2; o.w = *(uint32_t*)&h3;
    ((uint4*)dst)[i] = o;
}

// ---------------- routing ----------------
__global__ void zero_counts_kernel() {
    if (threadIdx.x < E_NUM) g_counts[threadIdx.x] = 0;
    if (threadIdx.x == 0) g_done = 0;
}

// 8 tokens per 256-thread block (1 per warp); gate weights cached in smem as
// float2 {wg,wn} at word stride 18 (2-way-max LDS.64). Emits x as fp16.
// The LAST block to finish also builds the compacted (expert, m-tile) map.
__global__ void __launch_bounds__(256) route_kernel(
    const float* __restrict__ x, const float* __restrict__ noise,
    const float* __restrict__ Wg, const float* __restrict__ bg,
    const float* __restrict__ Wn, const float* __restrict__ bn, int T)
{
    __shared__ float sW[D_DIM * 18];
    __shared__ int s_last;

    int tid = threadIdx.x, wid = tid >> 5, lane = tid & 31;

    for (int idx = tid; idx < D_DIM * E_NUM; idx += 256) {
        int d = idx >> 3, e = idx & 7;
        sW[d * 18 + 2 * e]     = Wg[idx];
        sW[d * 18 + 2 * e + 1] = Wn[idx];
    }
    __syncthreads();

    int t = blockIdx.x * RT_TOK + wid;
    if (t < T) {
        float pg[E_NUM], pn[E_NUM];
#pragma unroll
        for (int e = 0; e < E_NUM; e++) { pg[e] = 0.f; pn[e] = 0.f; }

        const float* xr = x + (size_t)t * D_DIM;
        __half* xhr = g_xh + (size_t)t * D_DIM;
#pragma unroll 6
        for (int i = 0; i < D_DIM / 32; i++) {
            int d = lane + 32 * i;
            float xv = xr[d];
            xhr[d] = __float2half_rn(xv);
            const float2* w = (const float2*)(sW + d * 18);
#pragma unroll
            for (int e = 0; e < E_NUM; e++) {
                float2 wv = w[e];
                pg[e] = fmaf(xv, wv.x, pg[e]);
                pn[e] = fmaf(xv, wv.y, pn[e]);
            }
        }
#pragma unroll
        for (int e = 0; e < E_NUM; e++)
#pragma unroll
            for (int o = 16; o > 0; o >>= 1) {
                pg[e] += __shfl_down_sync(0xffffffffu, pg[e], o);
                pn[e] += __shfl_down_sync(0xffffffffu, pn[e], o);
            }

        if (lane == 0) {
            float h[E_NUM];
#pragma unroll
            for (int e = 0; e < E_NUM; e++) {
                float a = pg[e] + bg[e];
                float b = pn[e] + bn[e];
                float sp = fmaxf(b, 0.f) + log1pf(expf(-fabsf(b)));
                h[e] = a + noise[(size_t)t * E_NUM + e] * sp;
            }
            int i0 = 0;
#pragma unroll
            for (int e = 1; e < E_NUM; e++) if (h[e] > h[i0]) i0 = e;
            int i1 = (i0 == 0) ? 1 : 0;
#pragma unroll
            for (int e = 0; e < E_NUM; e++) if (e != i0 && h[e] > h[i1]) i1 = e;

            float p0 = 1.f / (1.f + expf(h[i1] - h[i0]));
            float p1 = 1.f - p0;
            g_pslot[2 * t]     = p0;
            g_pslot[2 * t + 1] = p1;

            int s0 = atomicAdd(&g_counts[i0], 1);
            g_tok [i0 * MAX_T + s0] = t;
            g_slot[i0 * MAX_T + s0] = 2 * t;
            int s1 = atomicAdd(&g_counts[i1], 1);
            g_tok [i1 * MAX_T + s1] = t;
            g_slot[i1 * MAX_T + s1] = 2 * t + 1;
        }
    }

    // last-block-out builds the tile map
    __syncthreads();
    if (tid == 0) {
        __threadfence();
        int prev = atomicAdd(&g_done, 1);
        s_last = (prev == (int)gridDim.x - 1) ? 1 : 0;
    }
    __syncthreads();
    if (s_last && tid == 0) {
        __threadfence();
        int c = 0;
#pragma unroll
        for (int e = 0; e < E_NUM; e++) {
            int nt = (g_counts[e] + 127) >> 7;
            for (int m = 0; m < nt; m++) g_tmap[c++] = (e << 16) | m;
        }
        g_ntiles = c;
        __threadfence();
    }
}

// ---------------- grouped fp16 GEMM ----------------
// 128 threads (4 warps 2x2), BM=128, BN=128, BK=64, 3-stage cp.async ring.
// 2 CTAs/SM. Compacted tile map: blockIdx.y indexes g_tmap (no dead m-tiles).
// GEMM2 (!G1) is split-K=2: blockIdx.z = half.
#define STAGE_BYTES 32768
#define SM_BYTES (3 * STAGE_BYTES)   // 98304 per CTA

template <bool G1>
__global__ void __launch_bounds__(128) moe_gemm(
    const __half* __restrict__ Ah, const __half* __restrict__ Wh,
    const float* __restrict__ bias, void* __restrict__ OutV,
    float* __restrict__ Out2)
{
    constexpr int KTOT  = G1 ? D_DIM : H_DIM;
    constexpr int KSPAN = G1 ? D_DIM : (H_DIM / 2);
    constexpr int NG    = G1 ? H_DIM : D_DIM;
    constexpr int NC    = KSPAN / 64;

    int ty = blockIdx.y;
    if (ty >= g_ntiles) return;
    int tm   = g_tmap[ty];
    int e    = tm >> 16;
    int m0   = (tm & 0xFFFF) * 128;
    int half = G1 ? 0 : blockIdx.z;
    int cnt  = g_counts[e];
    int n0   = blockIdx.x * 128;
    size_t kbase = (size_t)half * KSPAN;

    extern __shared__ char smem[];
    uint32_t sbase = smem_u32(smem);

    int tid = threadIdx.x, wid = tid >> 5, lane = tid & 31;
    int wm = wid >> 1, wn = wid & 1;
    const int* idxarr = G1 ? g_tok : g_slot;

    // ---- cp.async plans ----
    int ar0 = tid >> 3, akq = tid & 7;
    uint32_t a_dst0 = (uint32_t)(ar0 * 8 + (akq ^ (ar0 & 7))) * 16;
    const __half* a_src[8]; uint32_t a_sz[8];
#pragma unroll
    for (int i = 0; i < 8; i++) {
        int gr = m0 + ar0 + 16 * i;
        if (gr < cnt) {
            a_src[i] = Ah + (size_t)idxarr[e * MAX_T + gr] * KTOT + kbase + akq * 8;
            a_sz[i] = 16;
        } else { a_src[i] = Ah; a_sz[i] = 0; }
    }
    int bk0 = tid >> 4, bnq = tid & 15;
    const __half* b_src = Wh + (size_t)e * KTOT * NG + (kbase + bk0) * NG
                        + n0 + bnq * 8;
    uint32_t b_dst0 = 16384u + (uint32_t)(bk0 * 16 + (bnq ^ (bk0 & 7))) * 16;

    auto issue = [&](int c) {
        if (c < NC) {
            uint32_t sa = sbase + (uint32_t)(c % 3) * STAGE_BYTES;
#pragma unroll
            for (int i = 0; i < 8; i++)
                cp16(sa + a_dst0 + (uint32_t)i * 2048,
                     a_src[i] + (size_t)c * 64, a_sz[i]);
            const __half* bs = b_src + (size_t)c * 64 * NG;
#pragma unroll
            for (int j = 0; j < 8; j++)
                cp16(sa + b_dst0 + (uint32_t)j * 2048,
                     bs + (size_t)(8 * j) * NG, 16);
        }
        cp_commit();
    };

    issue(0); issue(1);

    int lrow = (lane & 7) + 8 * ((lane >> 3) & 1);
    int lsel = lane >> 4;

    float acc[4][8][4];
#pragma unroll
    for (int a = 0; a < 4; a++)
#pragma unroll
        for (int b = 0; b < 8; b++)
#pragma unroll
            for (int k = 0; k < 4; k++) acc[a][b][k] = 0.f;

#pragma unroll 1
    for (int c = 0; c < NC; c++) {
        cp_wait1();
        __syncthreads();
        issue(c + 2);

        uint32_t sa = sbase + (uint32_t)(c % 3) * STAGE_BYTES;
        uint32_t sb = sa + 16384u;
#pragma unroll
        for (int ks = 0; ks < 4; ks++) {
            uint4 af[4]; uint2 bf[8];
            int kq = ks * 2 + lsel;
#pragma unroll
            for (int mf = 0; mf < 4; mf++) {
                int row = wm * 64 + mf * 16 + lrow;
                ldsm_x4(af[mf], sa + (uint32_t)(row * 8 + (kq ^ (row & 7))) * 16);
            }
            int kb = ks * 16 + lrow;
#pragma unroll
            for (int np = 0; np < 4; np++) {
                int nq = (wn * 4 + np) * 2 + lsel;
                uint4 bb;
                ldsm_x4t(bb, sb + (uint32_t)(kb * 16 + (nq ^ (kb & 7))) * 16);
                bf[2 * np].x     = bb.x; bf[2 * np].y     = bb.y;
                bf[2 * np + 1].x = bb.z; bf[2 * np + 1].y = bb.w;
            }
#pragma unroll
            for (int mf = 0; mf < 4; mf++)
#pragma unroll
                for (int nf = 0; nf < 8; nf++)
                    mma_f16(acc[mf][nf], af[mf], bf[nf]);
        }
        __syncthreads();
    }

    // ---- epilogue ----
#pragma unroll
    for (int mf = 0; mf < 4; mf++) {
        int r0 = m0 + wm * 64 + mf * 16 + (lane >> 2);
        int r1 = r0 + 8;
        bool v0 = r0 < cnt, v1 = r1 < cnt;
        int s0 = v0 ? g_slot[e * MAX_T + r0] : 0;
        int s1 = v1 ? g_slot[e * MAX_T + r1] : 0;
#pragma unroll
        for (int nf = 0; nf < 8; nf++) {
            int col = n0 + wn * 64 + nf * 8 + (lane & 3) * 2;
            float x0 = acc[mf][nf][0], x1 = acc[mf][nf][1];
            float x2 = acc[mf][nf][2], x3 = acc[mf][nf][3];
            if (G1 || half == 0) {
                float2 bb = *(const float2*)&bias[(size_t)e * NG + col];
                x0 += bb.x; x1 += bb.y; x2 += bb.x; x3 += bb.y;
            }
            if (G1) {
                x0 = fmaxf(x0, 0.f); x1 = fmaxf(x1, 0.f);
                x2 = fmaxf(x2, 0.f); x3 = fmaxf(x3, 0.f);
                __half* Out = (__half*)OutV;
                if (v0) {
                    __half2 hv = __floats2half2_rn(x0, x1);
                    *(__half2*)(Out + (size_t)s0 * NG + col) = hv;
                }
                if (v1) {
                    __half2 hv = __floats2half2_rn(x2, x3);
                    *(__half2*)(Out + (size_t)s1 * NG + col) = hv;
                }
            } else {
                float* Out = half ? Out2 : (float*)OutV;
                if (v0) { float2 o; o.x = x0; o.y = x1;
                          *(float2*)(Out + (size_t)s0 * NG + col) = o; }
                if (v1) { float2 o; o.x = x2; o.y = x3;
                          *(float2*)(Out + (size_t)s1 * NG + col) = o; }
            }
        }
    }
}

// out[t] = p0*(y[2t]+y2[2t]) + p1*(y[2t+1]+y2[2t+1])
__global__ void __launch_bounds__(256) combine_kernel(float* __restrict__ out, int T)
{
    int idx = blockIdx.x * 256 + threadIdx.x;
    int total = T * (D_DIM / 4);
    if (idx >= total) return;
    int t  = idx / (D_DIM / 4);
    int c4 = idx % (D_DIM / 4);
    float4 a0 = ((const float4*)(g_y  + (size_t)(2 * t) * D_DIM))[c4];
    float4 a1 = ((const float4*)(g_y2 + (size_t)(2 * t) * D_DIM))[c4];
    float4 b0 = ((const float4*)(g_y  + (size_t)(2 * t + 1) * D_DIM))[c4];
    float4 b1 = ((const float4*)(g_y2 + (size_t)(2 * t + 1) * D_DIM))[c4];
    float p0 = g_pslot[2 * t], p1 = g_pslot[2 * t + 1];
    float4 o;
    o.x = p0 * (a0.x + a1.x) + p1 * (b0.x + b1.x);
    o.y = p0 * (a0.y + a1.y) + p1 * (b0.y + b1.y);
    o.z = p0 * (a0.z + a1.z) + p1 * (b0.z + b1.z);
    o.w = p0 * (a0.w + a1.w) + p1 * (b0.w + b1.w);
    ((float4*)out)[idx] = o;
}

extern "C" void kernel_launch(void* const* d_in, const int* in_sizes, int n_in,
                              void* d_out, int out_size)
{
    const float* x     = (const float*)d_in[0];
    const float* noise = (const float*)d_in[1];
    const float* Wg    = (const float*)d_in[2];
    const float* bg    = (const float*)d_in[3];
    const float* Wn    = (const float*)d_in[4];
    const float* bn    = (const float*)d_in[5];
    const float* W1    = (const float*)d_in[6];
    const float* b1    = (const float*)d_in[7];
    const float* W2    = (const float*)d_in[8];
    const float* b2    = (const float*)d_in[9];
    float* out = (float*)d_out;

    int T = in_sizes[0] / D_DIM;
    if (T > MAX_T) T = MAX_T;

    // one-time setup (first call is the uncaptured correctness run)
    static bool s_init = false;
    static cudaStream_t s1, s2;
    static cudaEvent_t ev0, ev1, ev2;
    if (!s_init) {
        cudaStreamCreateWithFlags(&s1, cudaStreamNonBlocking);
        cudaStreamCreateWithFlags(&s2, cudaStreamNonBlocking);
        cudaEventCreateWithFlags(&ev0, cudaEventDisableTiming);
        cudaEventCreateWithFlags(&ev1, cudaEventDisableTiming);
        cudaEventCreateWithFlags(&ev2, cudaEventDisableTiming);
        cudaFuncSetAttribute(moe_gemm<true>,
                             cudaFuncAttributeMaxDynamicSharedMemorySize, SM_BYTES);
        cudaFuncSetAttribute(moe_gemm<false>,
                             cudaFuncAttributeMaxDynamicSharedMemorySize, SM_BYTES);
        s_init = true;
    }

    __half *xh = nullptr, *hid = nullptr, *w1h = nullptr, *w2h = nullptr;
    float *yv = nullptr, *yv2 = nullptr;
    cudaGetSymbolAddress((void**)&xh,  g_xh);
    cudaGetSymbolAddress((void**)&hid, g_hid);
    cudaGetSymbolAddress((void**)&w1h, g_w1h);
    cudaGetSymbolAddress((void**)&w2h, g_w2h);
    cudaGetSymbolAddress((void**)&yv,  g_y);
    cudaGetSymbolAddress((void**)&yv2, g_y2);

    int nw = E_NUM * D_DIM * H_DIM / 8;

    // fork: weight converts on side streams, route on main stream
    zero_counts_kernel<<<1, 32>>>();
    cudaEventRecord(ev0, 0);
    cudaStreamWaitEvent(s1, ev0, 0);
    cudaStreamWaitEvent(s2, ev0, 0);
    convert_f2h<<<(nw + 255) / 256, 256, 0, s1>>>(W1, w1h, nw);
    cudaEventRecord(ev1, s1);
    convert_f2h<<<(nw + 255) / 256, 256, 0, s2>>>(W2, w2h, nw);
    cudaEventRecord(ev2, s2);

    route_kernel<<<(T + RT_TOK - 1) / RT_TOK, 256>>>(x, noise, Wg, bg, Wn, bn, T);

    int maxt = (2 * T + 127) / 128 + E_NUM;   // upper bound on active m-tiles
    cudaStreamWaitEvent(0, ev1, 0);   // join W1 convert
    moe_gemm<true ><<<dim3(H_DIM / 128, maxt, 1), 128, SM_BYTES>>>(
        xh, w1h, b1, hid, nullptr);
    cudaStreamWaitEvent(0, ev2, 0);   // join W2 convert
    moe_gemm<false><<<dim3(D_DIM / 128, maxt, 2), 128, SM_BYTES>>>(
        hid, w2h, b2, yv, yv2);

    combine_kernel<<<(T * (D_DIM / 4) + 255) / 256, 256>>>(out, T);
}

// round 14
// speedup vs baseline: 8.9947x; 1.0007x over previous
#include <cuda_runtime.h>
#include <cuda_fp16.h>
#include <cstdint>

#define D_DIM 768
#define H_DIM 3072
#define E_NUM 8
#define MAX_T 4096
#define RT_TOK 8    // tokens per routing block (1 per warp)

// ---------------- device scratch ----------------
__device__ int    g_counts[E_NUM];
__device__ int    g_done;
__device__ int    g_ntiles;
__device__ int    g_tmap[256];              // (e<<16)|mtile
__device__ int    g_tok [E_NUM * MAX_T];
__device__ int    g_slot[E_NUM * MAX_T];
__device__ float  g_pslot[2 * MAX_T];
__device__ __half g_xh [(size_t)MAX_T * D_DIM];
__device__ __half g_hid[(size_t)2 * MAX_T * H_DIM];
__device__ float  g_y  [(size_t)2 * MAX_T * D_DIM];   // split-K half 0 (+bias)
__device__ float  g_y2 [(size_t)2 * MAX_T * D_DIM];   // split-K half 1
__device__ __half g_w1h[(size_t)E_NUM * D_DIM * H_DIM];
__device__ __half g_w2h[(size_t)E_NUM * H_DIM * D_DIM];

// ---------------- PTX helpers ----------------
__device__ __forceinline__ uint32_t smem_u32(const void* p) {
    uint32_t r;
    asm("{ .reg .u64 t; cvta.to.shared.u64 t, %1; cvt.u32.u64 %0, t; }"
        : "=r"(r) : "l"(p));
    return r;
}
__device__ __forceinline__ void mma_f16(float* d, const uint4& a, const uint2& b) {
    asm volatile(
        "mma.sync.aligned.m16n8k16.row.col.f32.f16.f16.f32 "
        "{%0,%1,%2,%3}, {%4,%5,%6,%7}, {%8,%9}, {%0,%1,%2,%3};"
        : "+f"(d[0]), "+f"(d[1]), "+f"(d[2]), "+f"(d[3])
        : "r"(a.x), "r"(a.y), "r"(a.z), "r"(a.w), "r"(b.x), "r"(b.y));
}
__device__ __forceinline__ void ldsm_x4(uint4& r, uint32_t addr) {
    asm volatile("ldmatrix.sync.aligned.m8n8.x4.shared.b16 {%0,%1,%2,%3}, [%4];"
                 : "=r"(r.x), "=r"(r.y), "=r"(r.z), "=r"(r.w) : "r"(addr));
}
__device__ __forceinline__ void ldsm_x4t(uint4& r, uint32_t addr) {
    asm volatile("ldmatrix.sync.aligned.m8n8.x4.trans.shared.b16 {%0,%1,%2,%3}, [%4];"
                 : "=r"(r.x), "=r"(r.y), "=r"(r.z), "=r"(r.w) : "r"(addr));
}
__device__ __forceinline__ void cp16(uint32_t dst, const void* src, uint32_t sz) {
    asm volatile("cp.async.cg.shared.global [%0], [%1], 16, %2;"
                 :: "r"(dst), "l"(src), "r"(sz) : "memory");
}
__device__ __forceinline__ void cp_commit() {
    asm volatile("cp.async.commit_group;" ::: "memory");
}
__device__ __forceinline__ void cp_wait1() {
    asm volatile("cp.async.wait_group 1;" ::: "memory");
}

// ---------------- fp32 -> fp16 convert ----------------
__global__ void __launch_bounds__(256) convert_f2h(
    const float* __restrict__ src, __half* __restrict__ dst, int n8)
{
    int i = blockIdx.x * 256 + threadIdx.x;
    if (i >= n8) return;
    const float4* s = (const float4*)src + 2 * (size_t)i;
    float4 a = s[0], b = s[1];
    __half2 h0 = __floats2half2_rn(a.x, a.y);
    __half2 h1 = __floats2half2_rn(a.z, a.w);
    __half2 h2 = __floats2half2_rn(b.x, b.y);
    __half2 h3 = __floats2half2_rn(b.z, b.w);
    uint4 o;
    o.x = *(uint32_t*)&h0; o.y = *(uint32_t*)&h1;
    o.z = *(uint32_t*)&h2; o.w = *(uint32_t*)&h3;
    ((uint4*)dst)[i] = o;
}

// ---------------- routing ----------------
__global__ void zero_counts_kernel() {
    if (threadIdx.x < E_NUM) g_counts[threadIdx.x] = 0;
    if (threadIdx.x == 0) g_done = 0;
}

// 8 tokens per 256-thread block (1 per warp). Gate weights in smem as float2
// {wg,wn} stride-18. CTA-aggregated slot reservation: <=8 global atomics per
// CTA (one per expert) instead of 16. Last block out builds the tile map.
__global__ void __launch_bounds__(256) route_kernel(
    const float* __restrict__ x, const float* __restrict__ noise,
    const float* __restrict__ Wg, const float* __restrict__ bg,
    const float* __restrict__ Wn, const float* __restrict__ bn, int T)
{
    __shared__ float sW[D_DIM * 18];
    __shared__ int sE[16], sT2[16];
    __shared__ int sBase[E_NUM];
    __shared__ int s_last;

    int tid = threadIdx.x, wid = tid >> 5, lane = tid & 31;

    if (tid < 16) sE[tid] = -1;
    for (int idx = tid; idx < D_DIM * E_NUM; idx += 256) {
        int d = idx >> 3, e = idx & 7;
        sW[d * 18 + 2 * e]     = Wg[idx];
        sW[d * 18 + 2 * e + 1] = Wn[idx];
    }
    __syncthreads();

    int t = blockIdx.x * RT_TOK + wid;
    if (t < T) {
        float pg[E_NUM], pn[E_NUM];
#pragma unroll
        for (int e = 0; e < E_NUM; e++) { pg[e] = 0.f; pn[e] = 0.f; }

        const float* xr = x + (size_t)t * D_DIM;
        __half* xhr = g_xh + (size_t)t * D_DIM;
#pragma unroll
        for (int i = 0; i < D_DIM / 32; i++) {
            int d = lane + 32 * i;
            float xv = xr[d];
            xhr[d] = __float2half_rn(xv);
            const float2* w = (const float2*)(sW + d * 18);
#pragma unroll
            for (int e = 0; e < E_NUM; e++) {
                float2 wv = w[e];
                pg[e] = fmaf(xv, wv.x, pg[e]);
                pn[e] = fmaf(xv, wv.y, pn[e]);
            }
        }
#pragma unroll
        for (int e = 0; e < E_NUM; e++)
#pragma unroll
            for (int o = 16; o > 0; o >>= 1) {
                pg[e] += __shfl_down_sync(0xffffffffu, pg[e], o);
                pn[e] += __shfl_down_sync(0xffffffffu, pn[e], o);
            }

        if (lane == 0) {
            float h[E_NUM];
#pragma unroll
            for (int e = 0; e < E_NUM; e++) {
                float a = pg[e] + bg[e];
                float b = pn[e] + bn[e];
                float sp = fmaxf(b, 0.f) + log1pf(expf(-fabsf(b)));
                h[e] = a + noise[(size_t)t * E_NUM + e] * sp;
            }
            int i0 = 0;
#pragma unroll
            for (int e = 1; e < E_NUM; e++) if (h[e] > h[i0]) i0 = e;
            int i1 = (i0 == 0) ? 1 : 0;
#pragma unroll
            for (int e = 0; e < E_NUM; e++) if (e != i0 && h[e] > h[i1]) i1 = e;

            float p0 = 1.f / (1.f + expf(h[i1] - h[i0]));
            g_pslot[2 * t]     = p0;
            g_pslot[2 * t + 1] = 1.f - p0;
            sE[2 * wid]     = i0;  sT2[2 * wid]     = t;
            sE[2 * wid + 1] = i1;  sT2[2 * wid + 1] = t;
        }
    }
    __syncthreads();

    // one atomic per expert per CTA
    if (tid < E_NUM) {
        int c = 0;
#pragma unroll
        for (int j = 0; j < 16; j++) c += (sE[j] == tid);
        sBase[tid] = c ? atomicAdd(&g_counts[tid], c) : 0;
    }
    __syncthreads();
    if (tid < 16 && sE[tid] >= 0) {
        int e = sE[tid], r = 0;
#pragma unroll
        for (int j = 0; j < 16; j++) r += (j < tid && sE[j] == e);
        int pos = sBase[e] + r;
        g_tok [e * MAX_T + pos] = sT2[tid];
        g_slot[e * MAX_T + pos] = 2 * sT2[tid] + (tid & 1);
    }

    // last-block-out builds the tile map
    __threadfence();
    __syncthreads();
    if (tid == 0) {
        int prev = atomicAdd(&g_done, 1);
        s_last = (prev == (int)gridDim.x - 1) ? 1 : 0;
    }
    __syncthreads();
    if (s_last && tid == 0) {
        __threadfence();
        int c = 0;
#pragma unroll
        for (int e = 0; e < E_NUM; e++) {
            int nt = (g_counts[e] + 127) >> 7;
            for (int m = 0; m < nt; m++) g_tmap[c++] = (e << 16) | m;
        }
        g_ntiles = c;
        __threadfence();
    }
}

// ---------------- grouped fp16 GEMM ----------------
// 128 threads (4 warps 2x2), BM=128, BN=128, BK=64, 3-stage cp.async ring.
// 2 CTAs/SM. One __syncthreads per chunk (top-of-loop barrier orders the
// stage overwrite). Compacted tile map via g_tmap. GEMM2 split-K=2.
#define STAGE_BYTES 32768
#define SM_BYTES (3 * STAGE_BYTES)   // 98304 per CTA

template <bool G1>
__global__ void __launch_bounds__(128) moe_gemm(
    const __half* __restrict__ Ah, const __half* __restrict__ Wh,
    const float* __restrict__ bias, void* __restrict__ OutV,
    float* __restrict__ Out2)
{
    constexpr int KTOT  = G1 ? D_DIM : H_DIM;
    constexpr int KSPAN = G1 ? D_DIM : (H_DIM / 2);
    constexpr int NG    = G1 ? H_DIM : D_DIM;
    constexpr int NC    = KSPAN / 64;

    int ty = blockIdx.y;
    if (ty >= g_ntiles) return;
    int tm   = g_tmap[ty];
    int e    = tm >> 16;
    int m0   = (tm & 0xFFFF) * 128;
    int half = G1 ? 0 : blockIdx.z;
    int cnt  = g_counts[e];
    int n0   = blockIdx.x * 128;
    size_t kbase = (size_t)half * KSPAN;

    extern __shared__ char smem[];
    uint32_t sbase = smem_u32(smem);

    int tid = threadIdx.x, wid = tid >> 5, lane = tid & 31;
    int wm = wid >> 1, wn = wid & 1;
    const int* idxarr = G1 ? g_tok : g_slot;

    // ---- cp.async plans ----
    int ar0 = tid >> 3, akq = tid & 7;
    uint32_t a_dst0 = (uint32_t)(ar0 * 8 + (akq ^ (ar0 & 7))) * 16;
    const __half* a_src[8]; uint32_t a_sz[8];
#pragma unroll
    for (int i = 0; i < 8; i++) {
        int gr = m0 + ar0 + 16 * i;
        if (gr < cnt) {
            a_src[i] = Ah + (size_t)idxarr[e * MAX_T + gr] * KTOT + kbase + akq * 8;
            a_sz[i] = 16;
        } else { a_src[i] = Ah; a_sz[i] = 0; }
    }
    int bk0 = tid >> 4, bnq = tid & 15;
    const __half* b_src = Wh + (size_t)e * KTOT * NG + (kbase + bk0) * NG
                        + n0 + bnq * 8;
    uint32_t b_dst0 = 16384u + (uint32_t)(bk0 * 16 + (bnq ^ (bk0 & 7))) * 16;

    auto issue = [&](int c) {
        if (c < NC) {
            uint32_t sa = sbase + (uint32_t)(c % 3) * STAGE_BYTES;
#pragma unroll
            for (int i = 0; i < 8; i++)
                cp16(sa + a_dst0 + (uint32_t)i * 2048,
                     a_src[i] + (size_t)c * 64, a_sz[i]);
            const __half* bs = b_src + (size_t)c * 64 * NG;
#pragma unroll
            for (int j = 0; j < 8; j++)
                cp16(sa + b_dst0 + (uint32_t)j * 2048,
                     bs + (size_t)(8 * j) * NG, 16);
        }
        cp_commit();
    };

    issue(0); issue(1);

    int lrow = (lane & 7) + 8 * ((lane >> 3) & 1);
    int lsel = lane >> 4;

    float acc[4][8][4];
#pragma unroll
    for (int a = 0; a < 4; a++)
#pragma unroll
        for (int b = 0; b < 8; b++)
#pragma unroll
            for (int k = 0; k < 4; k++) acc[a][b][k] = 0.f;

#pragma unroll 1
    for (int c = 0; c < NC; c++) {
        cp_wait1();
        __syncthreads();
        issue(c + 2);

        uint32_t sa = sbase + (uint32_t)(c % 3) * STAGE_BYTES;
        uint32_t sb = sa + 16384u;
#pragma unroll
        for (int ks = 0; ks < 4; ks++) {
            uint4 af[4]; uint2 bf[8];
            int kq = ks * 2 + lsel;
#pragma unroll
            for (int mf = 0; mf < 4; mf++) {
                int row = wm * 64 + mf * 16 + lrow;
                ldsm_x4(af[mf], sa + (uint32_t)(row * 8 + (kq ^ (row & 7))) * 16);
            }
            int kb = ks * 16 + lrow;
#pragma unroll
            for (int np = 0; np < 4; np++) {
                int nq = (wn * 4 + np) * 2 + lsel;
                uint4 bb;
                ldsm_x4t(bb, sb + (uint32_t)(kb * 16 + (nq ^ (kb & 7))) * 16);
                bf[2 * np].x     = bb.x; bf[2 * np].y     = bb.y;
                bf[2 * np + 1].x = bb.z; bf[2 * np + 1].y = bb.w;
            }
#pragma unroll
            for (int mf = 0; mf < 4; mf++)
#pragma unroll
                for (int nf = 0; nf < 8; nf++)
                    mma_f16(acc[mf][nf], af[mf], bf[nf]);
        }
    }

    // ---- epilogue ----
#pragma unroll
    for (int mf = 0; mf < 4; mf++) {
        int r0 = m0 + wm * 64 + mf * 16 + (lane >> 2);
        int r1 = r0 + 8;
        bool v0 = r0 < cnt, v1 = r1 < cnt;
        int s0 = v0 ? g_slot[e * MAX_T + r0] : 0;
        int s1 = v1 ? g_slot[e * MAX_T + r1] : 0;
#pragma unroll
        for (int nf = 0; nf < 8; nf++) {
            int col = n0 + wn * 64 + nf * 8 + (lane & 3) * 2;
            float x0 = acc[mf][nf][0], x1 = acc[mf][nf][1];
            float x2 = acc[mf][nf][2], x3 = acc[mf][nf][3];
            if (G1 || half == 0) {
                float2 bb = *(const float2*)&bias[(size_t)e * NG + col];
                x0 += bb.x; x1 += bb.y; x2 += bb.x; x3 += bb.y;
            }
            if (G1) {
                x0 = fmaxf(x0, 0.f); x1 = fmaxf(x1, 0.f);
                x2 = fmaxf(x2, 0.f); x3 = fmaxf(x3, 0.f);
                __half* Out = (__half*)OutV;
                if (v0) {
                    __half2 hv = __floats2half2_rn(x0, x1);
                    *(__half2*)(Out + (size_t)s0 * NG + col) = hv;
                }
                if (v1) {
                    __half2 hv = __floats2half2_rn(x2, x3);
                    *(__half2*)(Out + (size_t)s1 * NG + col) = hv;
                }
            } else {
                float* Out = half ? Out2 : (float*)OutV;
                if (v0) { float2 o; o.x = x0; o.y = x1;
                          *(float2*)(Out + (size_t)s0 * NG + col) = o; }
                if (v1) { float2 o; o.x = x2; o.y = x3;
                          *(float2*)(Out + (size_t)s1 * NG + col) = o; }
            }
        }
    }
}

// out[t] = p0*(y[2t]+y2[2t]) + p1*(y[2t+1]+y2[2t+1])
__global__ void __launch_bounds__(256) combine_kernel(float* __restrict__ out, int T)
{
    int idx = blockIdx.x * 256 + threadIdx.x;
    int total = T * (D_DIM / 4);
    if (idx >= total) return;
    int t  = idx / (D_DIM / 4);
    int c4 = idx % (D_DIM / 4);
    float4 a0 = ((const float4*)(g_y  + (size_t)(2 * t) * D_DIM))[c4];
    float4 a1 = ((const float4*)(g_y2 + (size_t)(2 * t) * D_DIM))[c4];
    float4 b0 = ((const float4*)(g_y  + (size_t)(2 * t + 1) * D_DIM))[c4];
    float4 b1 = ((const float4*)(g_y2 + (size_t)(2 * t + 1) * D_DIM))[c4];
    float p0 = g_pslot[2 * t], p1 = g_pslot[2 * t + 1];
    float4 o;
    o.x = p0 * (a0.x + a1.x) + p1 * (b0.x + b1.x);
    o.y = p0 * (a0.y + a1.y) + p1 * (b0.y + b1.y);
    o.z = p0 * (a0.z + a1.z) + p1 * (b0.z + b1.z);
    o.w = p0 * (a0.w + a1.w) + p1 * (b0.w + b1.w);
    ((float4*)out)[idx] = o;
}

extern "C" void kernel_launch(void* const* d_in, const int* in_sizes, int n_in,
                              void* d_out, int out_size)
{
    const float* x     = (const float*)d_in[0];
    const float* noise = (const float*)d_in[1];
    const float* Wg    = (const float*)d_in[2];
    const float* bg    = (const float*)d_in[3];
    const float* Wn    = (const float*)d_in[4];
    const float* bn    = (const float*)d_in[5];
    const float* W1    = (const float*)d_in[6];
    const float* b1    = (const float*)d_in[7];
    const float* W2    = (const float*)d_in[8];
    const float* b2    = (const float*)d_in[9];
    float* out = (float*)d_out;

    int T = in_sizes[0] / D_DIM;
    if (T > MAX_T) T = MAX_T;

    // one-time setup (first call is the uncaptured correctness run)
    static bool s_init = false;
    static cudaStream_t s1, s2;
    static cudaEvent_t ev0, ev1, ev2;
    if (!s_init) {
        cudaStreamCreateWithFlags(&s1, cudaStreamNonBlocking);
        cudaStreamCreateWithFlags(&s2, cudaStreamNonBlocking);
        cudaEventCreateWithFlags(&ev0, cudaEventDisableTiming);
        cudaEventCreateWithFlags(&ev1, cudaEventDisableTiming);
        cudaEventCreateWithFlags(&ev2, cudaEventDisableTiming);
        cudaFuncSetAttribute(moe_gemm<true>,
                             cudaFuncAttributeMaxDynamicSharedMemorySize, SM_BYTES);
        cudaFuncSetAttribute(moe_gemm<false>,
                             cudaFuncAttributeMaxDynamicSharedMemorySize, SM_BYTES);
        s_init = true;
    }

    __half *xh = nullptr, *hid = nullptr, *w1h = nullptr, *w2h = nullptr;
    float *yv = nullptr, *yv2 = nullptr;
    cudaGetSymbolAddress((void**)&xh,  g_xh);
    cudaGetSymbolAddress((void**)&hid, g_hid);
    cudaGetSymbolAddress((void**)&w1h, g_w1h);
    cudaGetSymbolAddress((void**)&w2h, g_w2h);
    cudaGetSymbolAddress((void**)&yv,  g_y);
    cudaGetSymbolAddress((void**)&yv2, g_y2);

    int nw = E_NUM * D_DIM * H_DIM / 8;

    // fork: weight converts on side streams, route on main stream
    zero_counts_kernel<<<1, 32>>>();
    cudaEventRecord(ev0, 0);
    cudaStreamWaitEvent(s1, ev0, 0);
    cudaStreamWaitEvent(s2, ev0, 0);
    convert_f2h<<<(nw + 255) / 256, 256, 0, s1>>>(W1, w1h, nw);
    cudaEventRecord(ev1, s1);
    convert_f2h<<<(nw + 255) / 256, 256, 0, s2>>>(W2, w2h, nw);
    cudaEventRecord(ev2, s2);

    route_kernel<<<(T + RT_TOK - 1) / RT_TOK, 256>>>(x, noise, Wg, bg, Wn, bn, T);

    int maxt = (2 * T + 127) / 128 + E_NUM;   // upper bound on active m-tiles
    cudaStreamWaitEvent(0, ev1, 0);   // join W1 convert
    moe_gemm<true ><<<dim3(H_DIM / 128, maxt, 1), 128, SM_BYTES>>>(
        xh, w1h, b1, hid, nullptr);
    cudaStreamWaitEvent(0, ev2, 0);   // join W2 convert
    moe_gemm<false><<<dim3(D_DIM / 128, maxt, 2), 128, SM_BYTES>>>(
        hid, w2h, b2, yv, yv2);

    combine_kernel<<<(T * (D_DIM / 4) + 255) / 256, 256>>>(out, T);
}

// round 15
// speedup vs baseline: 9.0461x; 1.0057x over previous
#include <cuda_runtime.h>
#include <cuda_fp16.h>
#include <cstdint>

#define D_DIM 768
#define H_DIM 3072
#define E_NUM 8
#define MAX_T 4096
#define RT_TOK 8    // tokens per routing block (1 per warp)

// ---------------- device scratch ----------------
__device__ int    g_counts[E_NUM];
__device__ int    g_done;
__device__ int    g_ntiles;
__device__ int    g_tmap[256];              // (e<<16)|mtile
__device__ int    g_tok [E_NUM * MAX_T];
__device__ int    g_slot[E_NUM * MAX_T];
__device__ float  g_pslot[2 * MAX_T];
__device__ __half g_xh [(size_t)MAX_T * D_DIM];
__device__ __half g_hid[(size_t)2 * MAX_T * H_DIM];
__device__ float  g_y  [(size_t)2 * MAX_T * D_DIM];
__device__ __half g_w1h[(size_t)E_NUM * D_DIM * H_DIM];
__device__ __half g_w2h[(size_t)E_NUM * H_DIM * D_DIM];

// ---------------- PTX helpers ----------------
__device__ __forceinline__ uint32_t smem_u32(const void* p) {
    uint32_t r;
    asm("{ .reg .u64 t; cvta.to.shared.u64 t, %1; cvt.u32.u64 %0, t; }"
        : "=r"(r) : "l"(p));
    return r;
}
__device__ __forceinline__ void mma_f16(float* d, const uint4& a, const uint2& b) {
    asm volatile(
        "mma.sync.aligned.m16n8k16.row.col.f32.f16.f16.f32 "
        "{%0,%1,%2,%3}, {%4,%5,%6,%7}, {%8,%9}, {%0,%1,%2,%3};"
        : "+f"(d[0]), "+f"(d[1]), "+f"(d[2]), "+f"(d[3])
        : "r"(a.x), "r"(a.y), "r"(a.z), "r"(a.w), "r"(b.x), "r"(b.y));
}
__device__ __forceinline__ void ldsm_x4(uint4& r, uint32_t addr) {
    asm volatile("ldmatrix.sync.aligned.m8n8.x4.shared.b16 {%0,%1,%2,%3}, [%4];"
                 : "=r"(r.x), "=r"(r.y), "=r"(r.z), "=r"(r.w) : "r"(addr));
}
__device__ __forceinline__ void ldsm_x4t(uint4& r, uint32_t addr) {
    asm volatile("ldmatrix.sync.aligned.m8n8.x4.trans.shared.b16 {%0,%1,%2,%3}, [%4];"
                 : "=r"(r.x), "=r"(r.y), "=r"(r.z), "=r"(r.w) : "r"(addr));
}
__device__ __forceinline__ void cp16(uint32_t dst, const void* src, uint32_t sz) {
    asm volatile("cp.async.cg.shared.global [%0], [%1], 16, %2;"
                 :: "r"(dst), "l"(src), "r"(sz) : "memory");
}
__device__ __forceinline__ void cp_commit() {
    asm volatile("cp.async.commit_group;" ::: "memory");
}
__device__ __forceinline__ void cp_wait1() {
    asm volatile("cp.async.wait_group 1;" ::: "memory");
}

// ---------------- fp32 -> fp16 convert ----------------
__global__ void __launch_bounds__(256) convert_f2h(
    const float* __restrict__ src, __half* __restrict__ dst, int n8)
{
    int i = blockIdx.x * 256 + threadIdx.x;
    if (i >= n8) return;
    const float4* s = (const float4*)src + 2 * (size_t)i;
    float4 a = s[0], b = s[1];
    __half2 h0 = __floats2half2_rn(a.x, a.y);
    __half2 h1 = __floats2half2_rn(a.z, a.w);
    __half2 h2 = __floats2half2_rn(b.x, b.y);
    __half2 h3 = __floats2half2_rn(b.z, b.w);
    uint4 o;
    o.x = *(uint32_t*)&h0; o.y = *(uint32_t*)&h1;
    o.z = *(uint32_t*)&h2; o.w = *(uint32_t*)&h3;
    ((uint4*)dst)[i] = o;
}

// ---------------- routing ----------------
__global__ void zero_counts_kernel() {
    if (threadIdx.x < E_NUM) g_counts[threadIdx.x] = 0;
    if (threadIdx.x == 0) g_done = 0;
}

__global__ void __launch_bounds__(256) route_kernel(
    const float* __restrict__ x, const float* __restrict__ noise,
    const float* __restrict__ Wg, const float* __restrict__ bg,
    const float* __restrict__ Wn, const float* __restrict__ bn, int T)
{
    __shared__ float sW[D_DIM * 18];
    __shared__ int sE[16], sT2[16];
    __shared__ int sBase[E_NUM];
    __shared__ int s_last;

    int tid = threadIdx.x, wid = tid >> 5, lane = tid & 31;

    if (tid < 16) sE[tid] = -1;
    for (int idx = tid; idx < D_DIM * E_NUM; idx += 256) {
        int d = idx >> 3, e = idx & 7;
        sW[d * 18 + 2 * e]     = Wg[idx];
        sW[d * 18 + 2 * e + 1] = Wn[idx];
    }
    __syncthreads();

    int t = blockIdx.x * RT_TOK + wid;
    if (t < T) {
        float pg[E_NUM], pn[E_NUM];
#pragma unroll
        for (int e = 0; e < E_NUM; e++) { pg[e] = 0.f; pn[e] = 0.f; }

        const float* xr = x + (size_t)t * D_DIM;
        __half* xhr = g_xh + (size_t)t * D_DIM;
#pragma unroll
        for (int i = 0; i < D_DIM / 32; i++) {
            int d = lane + 32 * i;
            float xv = xr[d];
            xhr[d] = __float2half_rn(xv);
            const float2* w = (const float2*)(sW + d * 18);
#pragma unroll
            for (int e = 0; e < E_NUM; e++) {
                float2 wv = w[e];
                pg[e] = fmaf(xv, wv.x, pg[e]);
                pn[e] = fmaf(xv, wv.y, pn[e]);
            }
        }
#pragma unroll
        for (int e = 0; e < E_NUM; e++)
#pragma unroll
            for (int o = 16; o > 0; o >>= 1) {
                pg[e] += __shfl_down_sync(0xffffffffu, pg[e], o);
                pn[e] += __shfl_down_sync(0xffffffffu, pn[e], o);
            }

        if (lane == 0) {
            float h[E_NUM];
#pragma unroll
            for (int e = 0; e < E_NUM; e++) {
                float a = pg[e] + bg[e];
                float b = pn[e] + bn[e];
                float sp = fmaxf(b, 0.f) + log1pf(expf(-fabsf(b)));
                h[e] = a + noise[(size_t)t * E_NUM + e] * sp;
            }
            int i0 = 0;
#pragma unroll
            for (int e = 1; e < E_NUM; e++) if (h[e] > h[i0]) i0 = e;
            int i1 = (i0 == 0) ? 1 : 0;
#pragma unroll
            for (int e = 0; e < E_NUM; e++) if (e != i0 && h[e] > h[i1]) i1 = e;

            float p0 = 1.f / (1.f + expf(h[i1] - h[i0]));
            g_pslot[2 * t]     = p0;
            g_pslot[2 * t + 1] = 1.f - p0;
            sE[2 * wid]     = i0;  sT2[2 * wid]     = t;
            sE[2 * wid + 1] = i1;  sT2[2 * wid + 1] = t;
        }
    }
    __syncthreads();

    if (tid < E_NUM) {
        int c = 0;
#pragma unroll
        for (int j = 0; j < 16; j++) c += (sE[j] == tid);
        sBase[tid] = c ? atomicAdd(&g_counts[tid], c) : 0;
    }
    __syncthreads();
    if (tid < 16 && sE[tid] >= 0) {
        int e = sE[tid], r = 0;
#pragma unroll
        for (int j = 0; j < 16; j++) r += (j < tid && sE[j] == e);
        int pos = sBase[e] + r;
        g_tok [e * MAX_T + pos] = sT2[tid];
        g_slot[e * MAX_T + pos] = 2 * sT2[tid] + (tid & 1);
    }

    __threadfence();
    __syncthreads();
    if (tid == 0) {
        int prev = atomicAdd(&g_done, 1);
        s_last = (prev == (int)gridDim.x - 1) ? 1 : 0;
    }
    __syncthreads();
    if (s_last && tid == 0) {
        __threadfence();
        int c = 0;
#pragma unroll
        for (int e = 0; e < E_NUM; e++) {
            int nt = (g_counts[e] + 127) >> 7;
            for (int m = 0; m < nt; m++) g_tmap[c++] = (e << 16) | m;
        }
        g_ntiles = c;
        __threadfence();
    }
}

// ---------------- grouped fp16 GEMM ----------------
// 256 threads (8 warps, 2x4), BM=128, BN=128, BK=64, 3-stage cp.async ring.
// Warp tile 64x32 (4 mf x 4 nf), acc=64 regs -> <=128 regs @ 2 CTAs/SM,
// 16 warps/SM. One __syncthreads per chunk. Compacted tile map. No split-K.
#define STAGE_BYTES 32768
#define SM_BYTES (3 * STAGE_BYTES)   // 98304 per CTA

template <bool G1>
__global__ void __launch_bounds__(256, 2) moe_gemm(
    const __half* __restrict__ Ah, const __half* __restrict__ Wh,
    const float* __restrict__ bias, void* __restrict__ OutV)
{
    constexpr int KTOT = G1 ? D_DIM : H_DIM;
    constexpr int NG   = G1 ? H_DIM : D_DIM;
    constexpr int NC   = KTOT / 64;

    int ty = blockIdx.y;
    if (ty >= g_ntiles) return;
    int tm  = g_tmap[ty];
    int e   = tm >> 16;
    int m0  = (tm & 0xFFFF) * 128;
    int cnt = g_counts[e];
    int n0  = blockIdx.x * 128;

    extern __shared__ char smem[];
    uint32_t sbase = smem_u32(smem);

    int tid = threadIdx.x, wid = tid >> 5, lane = tid & 31;
    int wm = wid >> 2, wn = wid & 3;
    const int* idxarr = G1 ? g_tok : g_slot;

    // ---- cp.async plans (256 threads) ----
    // A: unit u = tid + 256*i (i<4): row = u>>3 (0..127), kq = u&7
    int ar0 = tid >> 3, akq = tid & 7;
    uint32_t a_dst0 = (uint32_t)(ar0 * 8 + (akq ^ (ar0 & 7))) * 16;
    const __half* a_src[4]; uint32_t a_sz[4];
#pragma unroll
    for (int i = 0; i < 4; i++) {
        int gr = m0 + ar0 + 32 * i;
        if (gr < cnt) {
            a_src[i] = Ah + (size_t)idxarr[e * MAX_T + gr] * KTOT + akq * 8;
            a_sz[i] = 16;
        } else { a_src[i] = Ah; a_sz[i] = 0; }
    }
    // B: unit u = tid + 256*j (j<4): k = u>>4 (0..63), nq = u&15
    int bk0 = tid >> 4, bnq = tid & 15;
    const __half* b_src = Wh + (size_t)e * KTOT * NG + (size_t)bk0 * NG
                        + n0 + bnq * 8;
    uint32_t b_dst0 = 16384u + (uint32_t)(bk0 * 16 + (bnq ^ (bk0 & 7))) * 16;

    auto issue = [&](int c) {
        if (c < NC) {
            uint32_t sa = sbase + (uint32_t)(c % 3) * STAGE_BYTES;
#pragma unroll
            for (int i = 0; i < 4; i++)
                cp16(sa + a_dst0 + (uint32_t)i * 4096,
                     a_src[i] + (size_t)c * 64, a_sz[i]);
            const __half* bs = b_src + (size_t)c * 64 * NG;
#pragma unroll
            for (int j = 0; j < 4; j++)
                cp16(sa + b_dst0 + (uint32_t)j * 4096,
                     bs + (size_t)(16 * j) * NG, 16);
        }
        cp_commit();
    };

    issue(0); issue(1);

    int lrow = (lane & 7) + 8 * ((lane >> 3) & 1);
    int lsel = lane >> 4;

    float acc[4][4][4];
#pragma unroll
    for (int a = 0; a < 4; a++)
#pragma unroll
        for (int b = 0; b < 4; b++)
#pragma unroll
            for (int k = 0; k < 4; k++) acc[a][b][k] = 0.f;

#pragma unroll 1
    for (int c = 0; c < NC; c++) {
        cp_wait1();
        __syncthreads();
        issue(c + 2);

        uint32_t sa = sbase + (uint32_t)(c % 3) * STAGE_BYTES;
        uint32_t sb = sa + 16384u;
#pragma unroll
        for (int ks = 0; ks < 4; ks++) {
            uint4 af[4]; uint2 bf[4];
            int kq = ks * 2 + lsel;
#pragma unroll
            for (int mf = 0; mf < 4; mf++) {
                int row = wm * 64 + mf * 16 + lrow;
                ldsm_x4(af[mf], sa + (uint32_t)(row * 8 + (kq ^ (row & 7))) * 16);
            }
            int kb = ks * 16 + lrow;
#pragma unroll
            for (int np = 0; np < 2; np++) {
                int gnfp = wn * 2 + np;
                int nq = gnfp * 2 + lsel;
                uint4 bb;
                ldsm_x4t(bb, sb + (uint32_t)(kb * 16 + (nq ^ (kb & 7))) * 16);
                bf[2 * np].x     = bb.x; bf[2 * np].y     = bb.y;
                bf[2 * np + 1].x = bb.z; bf[2 * np + 1].y = bb.w;
            }
#pragma unroll
            for (int mf = 0; mf < 4; mf++)
#pragma unroll
                for (int nf = 0; nf < 4; nf++)
                    mma_f16(acc[mf][nf], af[mf], bf[nf]);
        }
    }

    // ---- epilogue ----
#pragma unroll
    for (int mf = 0; mf < 4; mf++) {
        int r0 = m0 + wm * 64 + mf * 16 + (lane >> 2);
        int r1 = r0 + 8;
        bool v0 = r0 < cnt, v1 = r1 < cnt;
        int s0 = v0 ? g_slot[e * MAX_T + r0] : 0;
        int s1 = v1 ? g_slot[e * MAX_T + r1] : 0;
#pragma unroll
        for (int nf = 0; nf < 4; nf++) {
            int col = n0 + wn * 32 + nf * 8 + (lane & 3) * 2;
            float2 bb = *(const float2*)&bias[(size_t)e * NG + col];
            float x0 = acc[mf][nf][0] + bb.x, x1 = acc[mf][nf][1] + bb.y;
            float x2 = acc[mf][nf][2] + bb.x, x3 = acc[mf][nf][3] + bb.y;
            if (G1) {
                x0 = fmaxf(x0, 0.f); x1 = fmaxf(x1, 0.f);
                x2 = fmaxf(x2, 0.f); x3 = fmaxf(x3, 0.f);
                __half* Out = (__half*)OutV;
                if (v0) {
                    __half2 hv = __floats2half2_rn(x0, x1);
                    *(__half2*)(Out + (size_t)s0 * NG + col) = hv;
                }
                if (v1) {
                    __half2 hv = __floats2half2_rn(x2, x3);
                    *(__half2*)(Out + (size_t)s1 * NG + col) = hv;
                }
            } else {
                float* Out = (float*)OutV;
                if (v0) { float2 o; o.x = x0; o.y = x1;
                          *(float2*)(Out + (size_t)s0 * NG + col) = o; }
                if (v1) { float2 o; o.x = x2; o.y = x3;
                          *(float2*)(Out + (size_t)s1 * NG + col) = o; }
            }
        }
    }
}

// out[t] = p0*y[2t] + p1*y[2t+1]
__global__ void __launch_bounds__(256) combine_kernel(float* __restrict__ out, int T)
{
    int idx = blockIdx.x * 256 + threadIdx.x;
    int total = T * (D_DIM / 4);
    if (idx >= total) return;
    int t  = idx / (D_DIM / 4);
    int c4 = idx % (D_DIM / 4);
    float4 a = ((const float4*)(g_y + (size_t)(2 * t) * D_DIM))[c4];
    float4 b = ((const float4*)(g_y + (size_t)(2 * t + 1) * D_DIM))[c4];
    float p0 = g_pslot[2 * t], p1 = g_pslot[2 * t + 1];
    float4 o;
    o.x = p0 * a.x + p1 * b.x;
    o.y = p0 * a.y + p1 * b.y;
    o.z = p0 * a.z + p1 * b.z;
    o.w = p0 * a.w + p1 * b.w;
    ((float4*)out)[idx] = o;
}

extern "C" void kernel_launch(void* const* d_in, const int* in_sizes, int n_in,
                              void* d_out, int out_size)
{
    const float* x     = (const float*)d_in[0];
    const float* noise = (const float*)d_in[1];
    const float* Wg    = (const float*)d_in[2];
    const float* bg    = (const float*)d_in[3];
    const float* Wn    = (const float*)d_in[4];
    const float* bn    = (const float*)d_in[5];
    const float* W1    = (const float*)d_in[6];
    const float* b1    = (const float*)d_in[7];
    const float* W2    = (const float*)d_in[8];
    const float* b2    = (const float*)d_in[9];
    float* out = (float*)d_out;

    int T = in_sizes[0] / D_DIM;
    if (T > MAX_T) T = MAX_T;

    static bool s_init = false;
    static cudaStream_t s1, s2;
    static cudaEvent_t ev0, ev1, ev2;
    if (!s_init) {
        cudaStreamCreateWithFlags(&s1, cudaStreamNonBlocking);
        cudaStreamCreateWithFlags(&s2, cudaStreamNonBlocking);
        cudaEventCreateWithFlags(&ev0, cudaEventDisableTiming);
        cudaEventCreateWithFlags(&ev1, cudaEventDisableTiming);
        cudaEventCreateWithFlags(&ev2, cudaEventDisableTiming);
        cudaFuncSetAttribute(moe_gemm<true>,
                             cudaFuncAttributeMaxDynamicSharedMemorySize, SM_BYTES);
        cudaFuncSetAttribute(moe_gemm<false>,
                             cudaFuncAttributeMaxDynamicSharedMemorySize, SM_BYTES);
        s_init = true;
    }

    __half *xh = nullptr, *hid = nullptr, *w1h = nullptr, *w2h = nullptr;
    float *yv = nullptr;
    cudaGetSymbolAddress((void**)&xh,  g_xh);
    cudaGetSymbolAddress((void**)&hid, g_hid);
    cudaGetSymbolAddress((void**)&w1h, g_w1h);
    cudaGetSymbolAddress((void**)&w2h, g_w2h);
    cudaGetSymbolAddress((void**)&yv,  g_y);

    int nw = E_NUM * D_DIM * H_DIM / 8;

    zero_counts_kernel<<<1, 32>>>();
    cudaEventRecord(ev0, 0);
    cudaStreamWaitEvent(s1, ev0, 0);
    cudaStreamWaitEvent(s2, ev0, 0);
    convert_f2h<<<(nw + 255) / 256, 256, 0, s1>>>(W1, w1h, nw);
    cudaEventRecord(ev1, s1);
    convert_f2h<<<(nw + 255) / 256, 256, 0, s2>>>(W2, w2h, nw);
    cudaEventRecord(ev2, s2);

    route_kernel<<<(T + RT_TOK - 1) / RT_TOK, 256>>>(x, noise, Wg, bg, Wn, bn, T);

    int maxt = (2 * T + 127) / 128 + E_NUM;
    cudaStreamWaitEvent(0, ev1, 0);
    moe_gemm<true ><<<dim3(H_DIM / 128, maxt, 1), 256, SM_BYTES>>>(
        xh, w1h, b1, hid);
    cudaStreamWaitEvent(0, ev2, 0);
    moe_gemm<false><<<dim3(D_DIM / 128, maxt, 1), 256, SM_BYTES>>>(
        hid, w2h, b2, yv);

    combine_kernel<<<(T * (D_DIM / 4) + 255) / 256, 256>>>(out, T);
}

// round 16
// speedup vs baseline: 9.2555x; 1.0231x over previous
#include <cuda_runtime.h>
#include <cuda_fp16.h>
#include <cstdint>

#define D_DIM 768
#define H_DIM 3072
#define E_NUM 8
#define MAX_T 4096
#define RT_TOK 8    // tokens per routing block (1 per warp)

// ---------------- device scratch ----------------
__device__ int    g_counts[E_NUM];
__device__ int    g_done;
__device__ int    g_ntiles;
__device__ int    g_tmap[256];              // (e<<16)|mtile
__device__ int    g_tok [E_NUM * MAX_T];
__device__ int    g_slot[E_NUM * MAX_T];
__device__ float  g_pslot[2 * MAX_T];
__device__ __half g_xh [(size_t)MAX_T * D_DIM];
__device__ __half g_hid[(size_t)2 * MAX_T * H_DIM];
__device__ float  g_y  [(size_t)2 * MAX_T * D_DIM];   // p-scaled expert outputs
__device__ __half g_w1h[(size_t)E_NUM * D_DIM * H_DIM];
__device__ __half g_w2h[(size_t)E_NUM * H_DIM * D_DIM];

// ---------------- PTX helpers ----------------
__device__ __forceinline__ uint32_t smem_u32(const void* p) {
    uint32_t r;
    asm("{ .reg .u64 t; cvta.to.shared.u64 t, %1; cvt.u32.u64 %0, t; }"
        : "=r"(r) : "l"(p));
    return r;
}
__device__ __forceinline__ void mma_f16(float* d, const uint4& a, const uint2& b) {
    asm volatile(
        "mma.sync.aligned.m16n8k16.row.col.f32.f16.f16.f32 "
        "{%0,%1,%2,%3}, {%4,%5,%6,%7}, {%8,%9}, {%0,%1,%2,%3};"
        : "+f"(d[0]), "+f"(d[1]), "+f"(d[2]), "+f"(d[3])
        : "r"(a.x), "r"(a.y), "r"(a.z), "r"(a.w), "r"(b.x), "r"(b.y));
}
__device__ __forceinline__ void ldsm_x4(uint4& r, uint32_t addr) {
    asm volatile("ldmatrix.sync.aligned.m8n8.x4.shared.b16 {%0,%1,%2,%3}, [%4];"
                 : "=r"(r.x), "=r"(r.y), "=r"(r.z), "=r"(r.w) : "r"(addr));
}
__device__ __forceinline__ void ldsm_x4t(uint4& r, uint32_t addr) {
    asm volatile("ldmatrix.sync.aligned.m8n8.x4.trans.shared.b16 {%0,%1,%2,%3}, [%4];"
                 : "=r"(r.x), "=r"(r.y), "=r"(r.z), "=r"(r.w) : "r"(addr));
}
__device__ __forceinline__ void cp16(uint32_t dst, const void* src, uint32_t sz) {
    asm volatile("cp.async.cg.shared.global [%0], [%1], 16, %2;"
                 :: "r"(dst), "l"(src), "r"(sz) : "memory");
}
__device__ __forceinline__ void cp_commit() {
    asm volatile("cp.async.commit_group;" ::: "memory");
}
__device__ __forceinline__ void cp_wait1() {
    asm volatile("cp.async.wait_group 1;" ::: "memory");
}

// ---------------- fp32 -> fp16 convert ----------------
__global__ void __launch_bounds__(256) convert_f2h(
    const float* __restrict__ src, __half* __restrict__ dst, int n8)
{
    int i = blockIdx.x * 256 + threadIdx.x;
    if (i >= n8) return;
    const float4* s = (const float4*)src + 2 * (size_t)i;
    float4 a = s[0], b = s[1];
    __half2 h0 = __floats2half2_rn(a.x, a.y);
    __half2 h1 = __floats2half2_rn(a.z, a.w);
    __half2 h2 = __floats2half2_rn(b.x, b.y);
    __half2 h3 = __floats2half2_rn(b.z, b.w);
    uint4 o;
    o.x = *(uint32_t*)&h0; o.y = *(uint32_t*)&h1;
    o.z = *(uint32_t*)&h2; o.w = *(uint32_t*)&h3;
    ((uint4*)dst)[i] = o;
}

// ---------------- routing ----------------
__global__ void zero_counts_kernel() {
    if (threadIdx.x < E_NUM) g_counts[threadIdx.x] = 0;
    if (threadIdx.x == 0) g_done = 0;
}

__global__ void __launch_bounds__(256) route_kernel(
    const float* __restrict__ x, const float* __restrict__ noise,
    const float* __restrict__ Wg, const float* __restrict__ bg,
    const float* __restrict__ Wn, const float* __restrict__ bn, int T)
{
    __shared__ float sW[D_DIM * 18];
    __shared__ int sE[16], sT2[16];
    __shared__ int sBase[E_NUM];
    __shared__ int s_last;

    int tid = threadIdx.x, wid = tid >> 5, lane = tid & 31;

    if (tid < 16) sE[tid] = -1;
    for (int idx = tid; idx < D_DIM * E_NUM; idx += 256) {
        int d = idx >> 3, e = idx & 7;
        sW[d * 18 + 2 * e]     = Wg[idx];
        sW[d * 18 + 2 * e + 1] = Wn[idx];
    }
    __syncthreads();

    int t = blockIdx.x * RT_TOK + wid;
    if (t < T) {
        float pg[E_NUM], pn[E_NUM];
#pragma unroll
        for (int e = 0; e < E_NUM; e++) { pg[e] = 0.f; pn[e] = 0.f; }

        const float* xr = x + (size_t)t * D_DIM;
        __half* xhr = g_xh + (size_t)t * D_DIM;
#pragma unroll
        for (int i = 0; i < D_DIM / 32; i++) {
            int d = lane + 32 * i;
            float xv = xr[d];
            xhr[d] = __float2half_rn(xv);
            const float2* w = (const float2*)(sW + d * 18);
#pragma unroll
            for (int e = 0; e < E_NUM; e++) {
                float2 wv = w[e];
                pg[e] = fmaf(xv, wv.x, pg[e]);
                pn[e] = fmaf(xv, wv.y, pn[e]);
            }
        }
#pragma unroll
        for (int e = 0; e < E_NUM; e++)
#pragma unroll
            for (int o = 16; o > 0; o >>= 1) {
                pg[e] += __shfl_down_sync(0xffffffffu, pg[e], o);
                pn[e] += __shfl_down_sync(0xffffffffu, pn[e], o);
            }

        if (lane == 0) {
            float h[E_NUM];
#pragma unroll
            for (int e = 0; e < E_NUM; e++) {
                float a = pg[e] + bg[e];
                float b = pn[e] + bn[e];
                float sp = fmaxf(b, 0.f) + log1pf(expf(-fabsf(b)));
                h[e] = a + noise[(size_t)t * E_NUM + e] * sp;
            }
            int i0 = 0;
#pragma unroll
            for (int e = 1; e < E_NUM; e++) if (h[e] > h[i0]) i0 = e;
            int i1 = (i0 == 0) ? 1 : 0;
#pragma unroll
            for (int e = 0; e < E_NUM; e++) if (e != i0 && h[e] > h[i1]) i1 = e;

            float p0 = 1.f / (1.f + expf(h[i1] - h[i0]));
            g_pslot[2 * t]     = p0;
            g_pslot[2 * t + 1] = 1.f - p0;
            sE[2 * wid]     = i0;  sT2[2 * wid]     = t;
            sE[2 * wid + 1] = i1;  sT2[2 * wid + 1] = t;
        }
    }
    __syncthreads();

    if (tid < E_NUM) {
        int c = 0;
#pragma unroll
        for (int j = 0; j < 16; j++) c += (sE[j] == tid);
        sBase[tid] = c ? atomicAdd(&g_counts[tid], c) : 0;
    }
    __syncthreads();
    if (tid < 16 && sE[tid] >= 0) {
        int e = sE[tid], r = 0;
#pragma unroll
        for (int j = 0; j < 16; j++) r += (j < tid && sE[j] == e);
        int pos = sBase[e] + r;
        g_tok [e * MAX_T + pos] = sT2[tid];
        g_slot[e * MAX_T + pos] = 2 * sT2[tid] + (tid & 1);
    }

    __threadfence();
    __syncthreads();
    if (tid == 0) {
        int prev = atomicAdd(&g_done, 1);
        s_last = (prev == (int)gridDim.x - 1) ? 1 : 0;
    }
    __syncthreads();
    if (s_last && tid == 0) {
        __threadfence();
        int c = 0;
#pragma unroll
        for (int e = 0; e < E_NUM; e++) {
            int nt = (g_counts[e] + 127) >> 7;
            for (int m = 0; m < nt; m++) g_tmap[c++] = (e << 16) | m;
        }
        g_ntiles = c;
        __threadfence();
    }
}

// ---------------- grouped fp16 GEMM ----------------
// 256 threads (8 warps, 2x4), BM=128, BN=128, BK=64, 3-stage cp.async ring.
// Warp tile 64x32, 2 CTAs/SM (16 warps/SM). One __syncthreads per chunk.
// Compacted tile map. GEMM2 epilogue pre-scales by the gate prob.
#define STAGE_BYTES 32768
#define SM_BYTES (3 * STAGE_BYTES)   // 98304 per CTA

template <bool G1>
__global__ void __launch_bounds__(256, 2) moe_gemm(
    const __half* __restrict__ Ah, const __half* __restrict__ Wh,
    const float* __restrict__ bias, void* __restrict__ OutV)
{
    constexpr int KTOT = G1 ? D_DIM : H_DIM;
    constexpr int NG   = G1 ? H_DIM : D_DIM;
    constexpr int NC   = KTOT / 64;

    int ty = blockIdx.y;
    if (ty >= g_ntiles) return;
    int tm  = g_tmap[ty];
    int e   = tm >> 16;
    int m0  = (tm & 0xFFFF) * 128;
    int cnt = g_counts[e];
    int n0  = blockIdx.x * 128;

    extern __shared__ char smem[];
    uint32_t sbase = smem_u32(smem);

    int tid = threadIdx.x, wid = tid >> 5, lane = tid & 31;
    int wm = wid >> 2, wn = wid & 3;
    const int* idxarr = G1 ? g_tok : g_slot;

    // ---- cp.async plans ----
    int ar0 = tid >> 3, akq = tid & 7;
    uint32_t a_dst0 = (uint32_t)(ar0 * 8 + (akq ^ (ar0 & 7))) * 16;
    const __half* a_src[4]; uint32_t a_sz[4];
#pragma unroll
    for (int i = 0; i < 4; i++) {
        int gr = m0 + ar0 + 32 * i;
        if (gr < cnt) {
            a_src[i] = Ah + (size_t)idxarr[e * MAX_T + gr] * KTOT + akq * 8;
            a_sz[i] = 16;
        } else { a_src[i] = Ah; a_sz[i] = 0; }
    }
    int bk0 = tid >> 4, bnq = tid & 15;
    const __half* b_src = Wh + (size_t)e * KTOT * NG + (size_t)bk0 * NG
                        + n0 + bnq * 8;
    uint32_t b_dst0 = 16384u + (uint32_t)(bk0 * 16 + (bnq ^ (bk0 & 7))) * 16;

    auto issue = [&](int c) {
        if (c < NC) {
            uint32_t sa = sbase + (uint32_t)(c % 3) * STAGE_BYTES;
#pragma unroll
            for (int i = 0; i < 4; i++)
                cp16(sa + a_dst0 + (uint32_t)i * 4096,
                     a_src[i] + (size_t)c * 64, a_sz[i]);
            const __half* bs = b_src + (size_t)c * 64 * NG;
#pragma unroll
            for (int j = 0; j < 4; j++)
                cp16(sa + b_dst0 + (uint32_t)j * 4096,
                     bs + (size_t)(16 * j) * NG, 16);
        }
        cp_commit();
    };

    issue(0); issue(1);

    int lrow = (lane & 7) + 8 * ((lane >> 3) & 1);
    int lsel = lane >> 4;

    float acc[4][4][4];
#pragma unroll
    for (int a = 0; a < 4; a++)
#pragma unroll
        for (int b = 0; b < 4; b++)
#pragma unroll
            for (int k = 0; k < 4; k++) acc[a][b][k] = 0.f;

#pragma unroll 1
    for (int c = 0; c < NC; c++) {
        cp_wait1();
        __syncthreads();
        issue(c + 2);

        uint32_t sa = sbase + (uint32_t)(c % 3) * STAGE_BYTES;
        uint32_t sb = sa + 16384u;
#pragma unroll
        for (int ks = 0; ks < 4; ks++) {
            uint4 af[4]; uint2 bf[4];
            int kq = ks * 2 + lsel;
#pragma unroll
            for (int mf = 0; mf < 4; mf++) {
                int row = wm * 64 + mf * 16 + lrow;
                ldsm_x4(af[mf], sa + (uint32_t)(row * 8 + (kq ^ (row & 7))) * 16);
            }
            int kb = ks * 16 + lrow;
#pragma unroll
            for (int np = 0; np < 2; np++) {
                int gnfp = wn * 2 + np;
                int nq = gnfp * 2 + lsel;
                uint4 bb;
                ldsm_x4t(bb, sb + (uint32_t)(kb * 16 + (nq ^ (kb & 7))) * 16);
                bf[2 * np].x     = bb.x; bf[2 * np].y     = bb.y;
                bf[2 * np + 1].x = bb.z; bf[2 * np + 1].y = bb.w;
            }
#pragma unroll
            for (int mf = 0; mf < 4; mf++)
#pragma unroll
                for (int nf = 0; nf < 4; nf++)
                    mma_f16(acc[mf][nf], af[mf], bf[nf]);
        }
    }

    // ---- epilogue ----
#pragma unroll
    for (int mf = 0; mf < 4; mf++) {
        int r0 = m0 + wm * 64 + mf * 16 + (lane >> 2);
        int r1 = r0 + 8;
        bool v0 = r0 < cnt, v1 = r1 < cnt;
        int s0 = v0 ? g_slot[e * MAX_T + r0] : 0;
        int s1 = v1 ? g_slot[e * MAX_T + r1] : 0;
        float p0 = 1.f, p1 = 1.f;
        if (!G1) {
            p0 = v0 ? g_pslot[s0] : 0.f;
            p1 = v1 ? g_pslot[s1] : 0.f;
        }
#pragma unroll
        for (int nf = 0; nf < 4; nf++) {
            int col = n0 + wn * 32 + nf * 8 + (lane & 3) * 2;
            float2 bb = *(const float2*)&bias[(size_t)e * NG + col];
            float x0 = acc[mf][nf][0] + bb.x, x1 = acc[mf][nf][1] + bb.y;
            float x2 = acc[mf][nf][2] + bb.x, x3 = acc[mf][nf][3] + bb.y;
            if (G1) {
                x0 = fmaxf(x0, 0.f); x1 = fmaxf(x1, 0.f);
                x2 = fmaxf(x2, 0.f); x3 = fmaxf(x3, 0.f);
                __half* Out = (__half*)OutV;
                if (v0) {
                    __half2 hv = __floats2half2_rn(x0, x1);
                    *(__half2*)(Out + (size_t)s0 * NG + col) = hv;
                }
                if (v1) {
                    __half2 hv = __floats2half2_rn(x2, x3);
                    *(__half2*)(Out + (size_t)s1 * NG + col) = hv;
                }
            } else {
                float* Out = (float*)OutV;
                if (v0) { float2 o; o.x = p0 * x0; o.y = p0 * x1;
                          *(float2*)(Out + (size_t)s0 * NG + col) = o; }
                if (v1) { float2 o; o.x = p1 * x2; o.y = p1 * x3;
                          *(float2*)(Out + (size_t)s1 * NG + col) = o; }
            }
        }
    }
}

// out[t] = y[2t] + y[2t+1]   (y already gate-scaled)
__global__ void __launch_bounds__(256) combine_kernel(float* __restrict__ out, int T)
{
    int idx = blockIdx.x * 256 + threadIdx.x;
    int total = T * (D_DIM / 4);
    if (idx >= total) return;
    int t  = idx / (D_DIM / 4);
    int c4 = idx % (D_DIM / 4);
    float4 a = ((const float4*)(g_y + (size_t)(2 * t) * D_DIM))[c4];
    float4 b = ((const float4*)(g_y + (size_t)(2 * t + 1) * D_DIM))[c4];
    float4 o;
    o.x = a.x + b.x;
    o.y = a.y + b.y;
    o.z = a.z + b.z;
    o.w = a.w + b.w;
    ((float4*)out)[idx] = o;
}

extern "C" void kernel_launch(void* const* d_in, const int* in_sizes, int n_in,
                              void* d_out, int out_size)
{
    const float* x     = (const float*)d_in[0];
    const float* noise = (const float*)d_in[1];
    const float* Wg    = (const float*)d_in[2];
    const float* bg    = (const float*)d_in[3];
    const float* Wn    = (const float*)d_in[4];
    const float* bn    = (const float*)d_in[5];
    const float* W1    = (const float*)d_in[6];
    const float* b1    = (const float*)d_in[7];
    const float* W2    = (const float*)d_in[8];
    const float* b2    = (const float*)d_in[9];
    float* out = (float*)d_out;

    int T = in_sizes[0] / D_DIM;
    if (T > MAX_T) T = MAX_T;

    static bool s_init = false;
    static cudaStream_t s1;
    static cudaEvent_t ev0, ev1, ev2;
    if (!s_init) {
        cudaStreamCreateWithFlags(&s1, cudaStreamNonBlocking);
        cudaEventCreateWithFlags(&ev0, cudaEventDisableTiming);
        cudaEventCreateWithFlags(&ev1, cudaEventDisableTiming);
        cudaEventCreateWithFlags(&ev2, cudaEventDisableTiming);
        cudaFuncSetAttribute(moe_gemm<true>,
                             cudaFuncAttributeMaxDynamicSharedMemorySize, SM_BYTES);
        cudaFuncSetAttribute(moe_gemm<false>,
                             cudaFuncAttributeMaxDynamicSharedMemorySize, SM_BYTES);
        s_init = true;
    }

    __half *xh = nullptr, *hid = nullptr, *w1h = nullptr, *w2h = nullptr;
    float *yv = nullptr;
    cudaGetSymbolAddress((void**)&xh,  g_xh);
    cudaGetSymbolAddress((void**)&hid, g_hid);
    cudaGetSymbolAddress((void**)&w1h, g_w1h);
    cudaGetSymbolAddress((void**)&w2h, g_w2h);
    cudaGetSymbolAddress((void**)&yv,  g_y);

    int nw = E_NUM * D_DIM * H_DIM / 8;

    // prologue: route || convert_w1 ; convert_w2 chained AFTER w1 so it
    // overlaps GEMM1 instead of contending during the prologue.
    zero_counts_kernel<<<1, 32>>>();
    cudaEventRecord(ev0, 0);
    cudaStreamWaitEvent(s1, ev0, 0);
    convert_f2h<<<(nw + 255) / 256, 256, 0, s1>>>(W1, w1h, nw);
    cudaEventRecord(ev1, s1);
    convert_f2h<<<(nw + 255) / 256, 256, 0, s1>>>(W2, w2h, nw);
    cudaEventRecord(ev2, s1);

    route_kernel<<<(T + RT_TOK - 1) / RT_TOK, 256>>>(x, noise, Wg, bg, Wn, bn, T);

    int maxt = (2 * T + 127) / 128 + E_NUM;
    cudaStreamWaitEvent(0, ev1, 0);   // join W1 convert
    moe_gemm<true ><<<dim3(H_DIM / 128, maxt, 1), 256, SM_BYTES>>>(
        xh, w1h, b1, hid);
    cudaStreamWaitEvent(0, ev2, 0);   // join W2 convert (done long before)
    moe_gemm<false><<<dim3(D_DIM / 128, maxt, 1), 256, SM_BYTES>>>(
        hid, w2h, b2, yv);

    combine_kernel<<<(T * (D_DIM / 4) + 255) / 256, 256>>>(out, T);
}